// round 4
// baseline (speedup 1.0000x reference)
#include <cuda_runtime.h>
#include <cmath>

// ---------------- problem constants ----------------
static constexpr int B_   = 512;
static constexpr int T_   = 12;
static constexpr int E_   = 1024;
static constexpr int NH_  = 8;
static constexpr int HS_  = 128;
static constexpr int H_   = 1024;
static constexpr int G4_  = 4096;
static constexpr int BT_  = B_ * T_;        // 6144
static constexpr int ROWS48_ = B_ * 48;     // 24576

// ---------------- scratch (device globals; no allocation) ----------------
__device__ float d_xn [BT_ * (size_t)E_];
__device__ float d_xc [BT_ * (size_t)E_];
__device__ float d_x1 [BT_ * (size_t)E_];
__device__ float d_xn2[BT_ * (size_t)E_];
__device__ float d_gx [BT_ * (size_t)G4_];
__device__ float d_h  [BT_ * (size_t)H_];
__device__ float d_hn [BT_ * (size_t)H_];
__device__ float d_left [BT_ * (size_t)H_];
__device__ float d_right[BT_ * (size_t)H_];
__device__ float d_x1o[BT_ * (size_t)E_];
__device__ float d_y  [BT_ * (size_t)E_];
__device__ float d_z48[(size_t)B_ * 48 * E_];
__device__ float d_RgT[(size_t)NH_ * HS_ * 512];

// ---------------- helpers ----------------
__device__ __forceinline__ float gelu_exact(float x) {
    return 0.5f * x * (1.0f + erff(x * 0.70710678118654752440f));
}
__device__ __forceinline__ float sigmoidf_(float x) {
    return 1.0f / (1.0f + expf(-x));
}

// block-wide (256 threads) sum reduce of two values
__device__ __forceinline__ void block_reduce_2(float& s, float& ss) {
    __shared__ float sh[16];
    int lane = threadIdx.x & 31, w = threadIdx.x >> 5;
    #pragma unroll
    for (int o = 16; o; o >>= 1) {
        s  += __shfl_down_sync(0xffffffffu, s,  o);
        ss += __shfl_down_sync(0xffffffffu, ss, o);
    }
    if (!lane) { sh[w] = s; sh[8 + w] = ss; }
    __syncthreads();
    if (threadIdx.x == 0) {
        float a = 0.f, b = 0.f;
        #pragma unroll
        for (int i = 0; i < 8; i++) { a += sh[i]; b += sh[8 + i]; }
        sh[0] = a; sh[8] = b;
    }
    __syncthreads();
    s = sh[0]; ss = sh[8];
}

// ---------------- LayerNorm over rows of 1024 (EXONERATED by tail) ----------------
__global__ __launch_bounds__(256) void ln_rows(const float* __restrict__ in,
                                               float* __restrict__ out,
                                               const float* __restrict__ gw,
                                               const float* __restrict__ bw) {
    size_t row = blockIdx.x;
    const float* x = in + row * 1024;
    int t4 = threadIdx.x * 4;
    float4 v = *reinterpret_cast<const float4*>(x + t4);
    float s  = v.x + v.y + v.z + v.w;
    float ss = v.x*v.x + v.y*v.y + v.z*v.z + v.w*v.w;
    block_reduce_2(s, ss);
    float mu  = s * (1.0f / 1024.0f);
    float var = ss * (1.0f / 1024.0f) - mu * mu;
    float rstd = rsqrtf(var + 1e-5f);
    float4 g = *reinterpret_cast<const float4*>(gw + t4);
    float4 b = *reinterpret_cast<const float4*>(bw + t4);
    float4 o;
    o.x = (v.x - mu) * rstd * g.x + b.x;
    o.y = (v.y - mu) * rstd * g.y + b.y;
    o.z = (v.z - mu) * rstd * g.z + b.z;
    o.w = (v.w - mu) * rstd * g.w + b.w;
    *reinterpret_cast<float4*>(out + row * 1024 + t4) = o;
}

// ---------------- gelu then LayerNorm, in-place (EXONERATED by tail) ----------------
__global__ __launch_bounds__(256) void gelu_ln_rows(float* __restrict__ data,
                                                    const float* __restrict__ gw,
                                                    const float* __restrict__ bw) {
    size_t row = blockIdx.x;
    float* x = data + row * 1024;
    int t4 = threadIdx.x * 4;
    float4 v = *reinterpret_cast<const float4*>(x + t4);
    v.x = gelu_exact(v.x); v.y = gelu_exact(v.y);
    v.z = gelu_exact(v.z); v.w = gelu_exact(v.w);
    float s  = v.x + v.y + v.z + v.w;
    float ss = v.x*v.x + v.y*v.y + v.z*v.z + v.w*v.w;
    block_reduce_2(s, ss);
    float mu  = s * (1.0f / 1024.0f);
    float var = ss * (1.0f / 1024.0f) - mu * mu;
    float rstd = rsqrtf(var + 1e-5f);
    float4 g = *reinterpret_cast<const float4*>(gw + t4);
    float4 b = *reinterpret_cast<const float4*>(bw + t4);
    float4 o;
    o.x = (v.x - mu) * rstd * g.x + b.x;
    o.y = (v.y - mu) * rstd * g.y + b.y;
    o.z = (v.z - mu) * rstd * g.z + b.z;
    o.w = (v.w - mu) * rstd * g.w + b.w;
    *reinterpret_cast<float4*>(x + t4) = o;
}

// ---------------- GroupNorm v2: scalar, one warp per head ----------------
__global__ __launch_bounds__(256) void groupnorm2(const float* __restrict__ gng,
                                                  const float* __restrict__ gnb) {
    size_t row = blockIdx.x;                 // 0..6143
    int head = threadIdx.x >> 5, lane = threadIdx.x & 31;
    const float* x = d_h + row * 1024 + head * 128;
    float s = 0.f, ss = 0.f;
    for (int j = lane; j < 128; j += 32) {
        float v = x[j];
        s += v; ss += v * v;
    }
    #pragma unroll
    for (int o = 16; o; o >>= 1) {
        s  += __shfl_xor_sync(0xffffffffu, s,  o);
        ss += __shfl_xor_sync(0xffffffffu, ss, o);
    }
    float mu  = s * (1.0f / 128.0f);
    float var = ss * (1.0f / 128.0f) - mu * mu;
    float rstd = rsqrtf(var + 1e-5f);
    for (int j = lane; j < 128; j += 32) {
        int ch = head * 128 + j;
        d_hn[row * 1024 + ch] = (x[j] - mu) * rstd * gng[ch] + gnb[ch];
    }
}

// ---------------- fc1 conv only (12->12, k=3, same): xn -> xc ----------------
__global__ __launch_bounds__(128) void fc1_conv(const float* __restrict__ w1,
                                                const float* __restrict__ b1) {
    __shared__ float sx[12][130];
    __shared__ float sw1[12 * 12 * 3];
    __shared__ float sb1[12];
    int b = blockIdx.y, l0 = blockIdx.x * 128, tid = threadIdx.x;
    for (int i = tid; i < 12 * 130; i += 128) {
        int c = i / 130, j = i % 130, l = l0 + j - 1;
        sx[c][j] = (l >= 0 && l < 1024) ? d_xn[(size_t)(b * 12 + c) * 1024 + l] : 0.f;
    }
    for (int i = tid; i < 432; i += 128) sw1[i] = w1[i];
    if (tid < 12) sb1[tid] = b1[tid];
    __syncthreads();
    int l = l0 + tid;
    #pragma unroll
    for (int o = 0; o < 12; o++) {
        float a = sb1[o];
        #pragma unroll
        for (int c = 0; c < 12; c++) {
            const float* wp = &sw1[(o * 12 + c) * 3];
            a += wp[0] * sx[c][tid] + wp[1] * sx[c][tid + 1] + wp[2] * sx[c][tid + 2];
        }
        d_xc[(size_t)(b * 12 + o) * 1024 + l] = a;
    }
}

// ---------------- fc2 (1x1): x1[b,o,l] = b2[o] + sum_c w2[o,c]*xc[b,c,l] ----------------
__global__ __launch_bounds__(256) void fc2_1x1(const float* __restrict__ w2,
                                               const float* __restrict__ b2) {
    __shared__ float sw2[144], sb2[12];
    int b = blockIdx.y, l = blockIdx.x * 256 + threadIdx.x;
    if (threadIdx.x < 144) sw2[threadIdx.x] = w2[threadIdx.x];
    if (threadIdx.x < 12) sb2[threadIdx.x] = b2[threadIdx.x];
    __syncthreads();
    float xv[12];
    #pragma unroll
    for (int c = 0; c < 12; c++) xv[c] = d_xc[(size_t)(b * 12 + c) * 1024 + l];
    #pragma unroll
    for (int o = 0; o < 12; o++) {
        float a = sb2[o];
        #pragma unroll
        for (int c = 0; c < 12; c++) a += sw2[o * 12 + c] * xv[c];
        d_x1[(size_t)(b * 12 + o) * 1024 + l] = a;
    }
}

// ---------------- conv1: 12 -> 48 (EXONERATED pattern) ----------------
__global__ __launch_bounds__(128) void conv12_48(const float* __restrict__ w,
                                                 const float* __restrict__ bb) {
    __shared__ float sx[12][130];
    __shared__ float sw[48 * 12 * 3];
    __shared__ float sb[48];
    int b = blockIdx.y, l0 = blockIdx.x * 128, tid = threadIdx.x;
    for (int i = tid; i < 12 * 130; i += 128) {
        int c = i / 130, j = i % 130, l = l0 + j - 1;
        sx[c][j] = (l >= 0 && l < 1024) ? d_y[(size_t)(b * 12 + c) * 1024 + l] : 0.f;
    }
    for (int i = tid; i < 1728; i += 128) sw[i] = w[i];
    if (tid < 48) sb[tid] = bb[tid];
    __syncthreads();
    float acc[48];
    #pragma unroll
    for (int o = 0; o < 48; o++) acc[o] = sb[o];
    #pragma unroll
    for (int c = 0; c < 12; c++) {
        float x0 = sx[c][tid], x1 = sx[c][tid + 1], x2 = sx[c][tid + 2];
        #pragma unroll
        for (int o = 0; o < 48; o++) {
            const float* wp = &sw[(o * 12 + c) * 3];
            acc[o] += wp[0] * x0 + wp[1] * x1 + wp[2] * x2;
        }
    }
    int l = l0 + tid;
    #pragma unroll
    for (int o = 0; o < 48; o++) d_z48[(size_t)(b * 48 + o) * 1024 + l] = acc[o];
}

// ---------------- conv2: 48 -> 12; + skip -> out (EXONERATED pattern) ----------------
__global__ __launch_bounds__(128) void conv48_12(const float* __restrict__ w,
                                                 const float* __restrict__ bb,
                                                 float* __restrict__ out) {
    __shared__ float sx[48][130];
    __shared__ float sw[12 * 48 * 3];
    __shared__ float sb[12];
    int b = blockIdx.y, l0 = blockIdx.x * 128, tid = threadIdx.x;
    for (int i = tid; i < 48 * 130; i += 128) {
        int c = i / 130, j = i % 130, l = l0 + j - 1;
        sx[c][j] = (l >= 0 && l < 1024) ? d_z48[(size_t)(b * 48 + c) * 1024 + l] : 0.f;
    }
    for (int i = tid; i < 1728; i += 128) sw[i] = w[i];
    if (tid < 12) sb[tid] = bb[tid];
    __syncthreads();
    float acc[12];
    #pragma unroll
    for (int o = 0; o < 12; o++) acc[o] = sb[o];
    #pragma unroll
    for (int c = 0; c < 48; c++) {
        float x0 = sx[c][tid], x1 = sx[c][tid + 1], x2 = sx[c][tid + 2];
        #pragma unroll
        for (int o = 0; o < 12; o++) {
            const float* wp = &sw[(o * 48 + c) * 3];
            acc[o] += wp[0] * x0 + wp[1] * x1 + wp[2] * x2;
        }
    }
    int l = l0 + tid;
    #pragma unroll
    for (int o = 0; o < 12; o++) {
        size_t idx = (size_t)(b * 12 + o) * 1024 + l;
        out[idx] = acc[o] + d_xn[idx];
    }
}

// ---------------- elementwise v2 (scalar): d_left = gelu(d_left) * d_right ----------------
__global__ __launch_bounds__(256) void ew_gelu_mul2() {
    size_t i = (size_t)blockIdx.x * 256 + threadIdx.x;
    d_left[i] = gelu_exact(d_left[i]) * d_right[i];
}

// ---------------- elementwise v2 (scalar): d_y = silu(d_xc)*d_x1o + d_xn ----------------
__global__ __launch_bounds__(256) void ew_y2() {
    size_t i = (size_t)blockIdx.x * 256 + threadIdx.x;
    float c = d_xc[i];
    d_y[i] = c * sigmoidf_(c) * d_x1o[i] + d_xn[i];
}

// ---------------- GEMM v2 (independent rewrite): 64x64 tiles, 4x4 micro ----------------
// C[M,N] = A[M,K] @ B[K,N] + bias (+resid). M=gridDim.y*64, N=gridDim.x*64, K%16==0.
__global__ __launch_bounds__(256) void gemm64(int N, int K,
                                              const float* __restrict__ A,
                                              const float* __restrict__ Bm,
                                              const float* __restrict__ bias,
                                              const float* __restrict__ resid,
                                              float* __restrict__ C) {
    __shared__ float As[64 * 17];
    __shared__ float Bs[16 * 68];
    int tid = threadIdx.x;
    int ty = tid >> 4, tx = tid & 15;            // 16x16 thread grid
    int row0 = blockIdx.y * 64, col0 = blockIdx.x * 64;
    float acc[4][4] = {};
    for (int k0 = 0; k0 < K; k0 += 16) {
        {   // A tile: 64 rows x 16 k
            int idx = tid * 4;                   // 0..1020
            int r = idx >> 4, k = idx & 15;      // k in {0,4,8,12}
            float4 v = *reinterpret_cast<const float4*>(A + (size_t)(row0 + r) * K + k0 + k);
            As[r * 17 + k + 0] = v.x;
            As[r * 17 + k + 1] = v.y;
            As[r * 17 + k + 2] = v.z;
            As[r * 17 + k + 3] = v.w;
        }
        {   // B tile: 16 k x 64 cols
            int idx = tid * 4;
            int k = idx >> 6, c = idx & 63;      // c in {0,4,...,60}
            float4 v = *reinterpret_cast<const float4*>(Bm + (size_t)(k0 + k) * N + col0 + c);
            Bs[k * 68 + c + 0] = v.x;
            Bs[k * 68 + c + 1] = v.y;
            Bs[k * 68 + c + 2] = v.z;
            Bs[k * 68 + c + 3] = v.w;
        }
        __syncthreads();
        #pragma unroll
        for (int kk = 0; kk < 16; kk++) {
            float ar[4], br[4];
            #pragma unroll
            for (int i = 0; i < 4; i++) ar[i] = As[(ty * 4 + i) * 17 + kk];
            #pragma unroll
            for (int j = 0; j < 4; j++) br[j] = Bs[kk * 68 + tx * 4 + j];
            #pragma unroll
            for (int i = 0; i < 4; i++)
                #pragma unroll
                for (int j = 0; j < 4; j++)
                    acc[i][j] = fmaf(ar[i], br[j], acc[i][j]);
        }
        __syncthreads();
    }
    #pragma unroll
    for (int i = 0; i < 4; i++) {
        int r = row0 + ty * 4 + i;
        #pragma unroll
        for (int j = 0; j < 4; j++) {
            int c = col0 + tx * 4 + j;
            float v = acc[i][j] + bias[c];
            if (resid) v += resid[(size_t)r * N + c];
            C[(size_t)r * N + c] = v;
        }
    }
}

// ---------------- Rg transpose: RgT[n][hs][g] = Rg[n][g][hs] ----------------
__global__ void rg_transpose(const float* __restrict__ Rg) {
    __shared__ float tile[32][33];
    int n = blockIdx.x, g0 = blockIdx.y << 5, h0 = blockIdx.z << 5;
    int x = threadIdx.x, y = threadIdx.y;
    #pragma unroll
    for (int j = y; j < 32; j += 8)
        tile[j][x] = Rg[(size_t)(n * 512 + g0 + j) * 128 + h0 + x];
    __syncthreads();
    #pragma unroll
    for (int j = y; j < 32; j += 8)
        d_RgT[(size_t)(n * 128 + h0 + j) * 512 + g0 + x] = tile[x][j];
}

// ---------------- sLSTM recurrence (R3 version, kept) ----------------
__global__ __launch_bounds__(256) void slstm_rec2() {
    __shared__ float sh_hT[128 * 17];     // h transposed: sh_hT[hs*17 + bb]
    __shared__ float sh_rec[16 * 512];    // rec[bb*512 + g]
    int head = blockIdx.x >> 5;
    int b0 = (blockIdx.x & 31) << 4;
    int tid = threadIdx.x;
    for (int i = tid; i < 128 * 17; i += 256) sh_hT[i] = 0.f;
    float cS[8], nS[8], mS[8];
    #pragma unroll
    for (int j = 0; j < 8; j++) { cS[j] = 0.f; nS[j] = 0.f; mS[j] = 0.f; }
    __syncthreads();
    const float* RgTh = d_RgT + (size_t)head * (128 * 512);
    for (int t = 0; t < 12; t++) {
        float acc0[16], acc1[16];
        #pragma unroll
        for (int b = 0; b < 16; b++) { acc0[b] = 0.f; acc1[b] = 0.f; }
        #pragma unroll 4
        for (int h = 0; h < 128; h++) {
            float w0 = __ldg(RgTh + (size_t)h * 512 + tid);
            float w1 = __ldg(RgTh + (size_t)h * 512 + 256 + tid);
            #pragma unroll
            for (int b = 0; b < 16; b++) {
                float hv = sh_hT[h * 17 + b];
                acc0[b] = fmaf(hv, w0, acc0[b]);
                acc1[b] = fmaf(hv, w1, acc1[b]);
            }
        }
        #pragma unroll
        for (int b = 0; b < 16; b++) {
            sh_rec[b * 512 + tid]       = acc0[b];
            sh_rec[b * 512 + 256 + tid] = acc1[b];
        }
        __syncthreads();
        #pragma unroll
        for (int it = 0; it < 8; it++) {
            int idx = it * 256 + tid;
            int bb = idx >> 7, hs = idx & 127;
            int b = b0 + bb;
            const float* gxp = d_gx + (size_t)(b * 12 + t) * 4096 + head * 512;
            const float* rp = sh_rec + bb * 512;
            float z_ = gxp[hs]       + rp[hs];
            float i_ = gxp[128 + hs] + rp[128 + hs];
            float f_ = gxp[256 + hs] + rp[256 + hs];
            float o_ = gxp[384 + hs] + rp[384 + hs];
            float z  = tanhf(z_);
            float o  = sigmoidf_(o_);
            float mo = mS[it];
            float mn = fmaxf(f_ + mo, i_);
            float iv = expf(i_ - mn);
            float fv = expf(f_ + mo - mn);
            float cv = fv * cS[it] + iv * z;
            float nv = fv * nS[it] + iv;
            float hv = o * (cv / nv);
            cS[it] = cv; nS[it] = nv; mS[it] = mn;
            sh_hT[hs * 17 + bb] = hv;
            d_h[(size_t)((b * 12 + t) * 8 + head) * 128 + hs] = hv;
        }
        __syncthreads();
    }
}

// ---------------- launch ----------------
extern "C" void kernel_launch(void* const* d_in, const int* in_sizes, int n_in,
                              void* d_out, int out_size) {
    const float* x       = (const float*)d_in[0];
    const float* ln_g    = (const float*)d_in[1];
    const float* ln_b    = (const float*)d_in[2];
    const float* fc1_w   = (const float*)d_in[3];
    const float* fc1_b   = (const float*)d_in[4];
    const float* fc2_w   = (const float*)d_in[5];
    const float* fc2_b   = (const float*)d_in[6];
    const float* conv1_w = (const float*)d_in[7];
    const float* conv1_b = (const float*)d_in[8];
    const float* conv2_w = (const float*)d_in[9];
    const float* conv2_b = (const float*)d_in[10];
    const float* xlg     = (const float*)d_in[11];
    const float* xlb     = (const float*)d_in[12];
    const float* Wg      = (const float*)d_in[13];
    const float* bg      = (const float*)d_in[14];
    const float* Rg      = (const float*)d_in[15];
    const float* gng     = (const float*)d_in[16];
    const float* gnb     = (const float*)d_in[17];
    const float* uplw    = (const float*)d_in[18];
    const float* uplb    = (const float*)d_in[19];
    const float* uprw    = (const float*)d_in[20];
    const float* uprb    = (const float*)d_in[21];
    const float* downw   = (const float*)d_in[22];
    const float* downb   = (const float*)d_in[23];
    float* out = (float*)d_out;

    float *p_xn, *p_x1, *p_xn2, *p_gx, *p_hn, *p_left, *p_right, *p_x1o, *p_z48;
    cudaGetSymbolAddress((void**)&p_xn,   d_xn);
    cudaGetSymbolAddress((void**)&p_x1,   d_x1);
    cudaGetSymbolAddress((void**)&p_xn2,  d_xn2);
    cudaGetSymbolAddress((void**)&p_gx,   d_gx);
    cudaGetSymbolAddress((void**)&p_hn,   d_hn);
    cudaGetSymbolAddress((void**)&p_left, d_left);
    cudaGetSymbolAddress((void**)&p_right,d_right);
    cudaGetSymbolAddress((void**)&p_x1o,  d_x1o);
    cudaGetSymbolAddress((void**)&p_z48,  d_z48);

    rg_transpose<<<dim3(8, 16, 4), dim3(32, 8)>>>(Rg);

    // xn = LN(x); skip = xn
    ln_rows<<<BT_, 256>>>(x, p_xn, ln_g, ln_b);
    // xc = conv1d(xn, fc1)
    fc1_conv<<<dim3(8, B_), 128>>>(fc1_w, fc1_b);
    // x1 = fc2(xc)  (independent 1x1 kernel)
    fc2_1x1<<<dim3(4, B_), 256>>>(fc2_w, fc2_b);
    // xn2 = LN(x1)
    ln_rows<<<BT_, 256>>>(p_x1, p_xn2, xlg, xlb);
    // gx = xn2 @ Wg + bg   (6144 x 1024 x 4096)
    gemm64<<<dim3(64, 96), 256>>>(4096, 1024, p_xn2, Wg, bg, nullptr, p_gx);
    // sLSTM recurrence -> d_h
    slstm_rec2<<<256, 256>>>();
    // per-head GroupNorm -> d_hn
    groupnorm2<<<BT_, 256>>>(gng, gnb);
    // left/right projections
    gemm64<<<dim3(16, 96), 256>>>(1024, 1024, p_hn, uplw, uplb, nullptr, p_left);
    gemm64<<<dim3(16, 96), 256>>>(1024, 1024, p_hn, uprw, uprb, nullptr, p_right);
    // u = gelu(left) * right
    ew_gelu_mul2<<<24576, 256>>>();
    // x1_out = u @ down_w + down_b + x1
    gemm64<<<dim3(16, 96), 256>>>(1024, 1024, p_left, downw, downb, p_x1, p_x1o);
    // y = silu(xc) * x1_out + xn
    ew_y2<<<24576, 256>>>();
    // z48 = conv1d(y, 12->48)
    conv12_48<<<dim3(8, B_), 128>>>(conv1_w, conv1_b);
    // z48 = LN(gelu(z48))
    gelu_ln_rows<<<ROWS48_, 256>>>(p_z48, ln_g, ln_b);
    // out = conv1d(z48, 48->12) + skip
    conv48_12<<<dim3(8, B_), 128>>>(conv2_w, conv2_b, out);
}

// round 5
// speedup vs baseline: 2.2655x; 2.2655x over previous
#include <cuda_runtime.h>
#include <cmath>
#include <cstdint>

// ---------------- problem constants ----------------
static constexpr int B_   = 512;
static constexpr int T_   = 12;
static constexpr int E_   = 1024;
static constexpr int NH_  = 8;
static constexpr int HS_  = 128;
static constexpr int H_   = 1024;
static constexpr int G4_  = 4096;
static constexpr int BT_  = B_ * T_;        // 6144
static constexpr int ROWS48_ = B_ * 48;     // 24576

// ---------------- scratch (device globals; no allocation) ----------------
__device__ float d_xn [BT_ * (size_t)E_];
__device__ float d_xc [BT_ * (size_t)E_];
__device__ float d_x1 [BT_ * (size_t)E_];
__device__ float d_xn2[BT_ * (size_t)E_];
__device__ float d_gx [BT_ * (size_t)G4_];
__device__ float d_h  [BT_ * (size_t)H_];
__device__ float d_hn [BT_ * (size_t)H_];
__device__ float d_left [BT_ * (size_t)H_];
__device__ float d_right[BT_ * (size_t)H_];
__device__ float d_x1o[BT_ * (size_t)E_];
__device__ float d_y  [BT_ * (size_t)E_];
__device__ float d_z48[(size_t)B_ * 48 * E_];
__device__ float d_RgT[(size_t)NH_ * HS_ * 512];

// ---------------- helpers ----------------
__device__ __forceinline__ float gelu_exact(float x) {
    return 0.5f * x * (1.0f + erff(x * 0.70710678118654752440f));
}
__device__ __forceinline__ float sigmoidf_(float x) {
    return 1.0f / (1.0f + expf(-x));
}
__device__ __forceinline__ float to_tf32(float x) {
    float r;
    asm("cvt.rna.tf32.f32 %0, %1;" : "=f"(r) : "f"(x));
    return r;
}

// block-wide (256 threads) sum reduce of two values
__device__ __forceinline__ void block_reduce_2(float& s, float& ss) {
    __shared__ float sh[16];
    int lane = threadIdx.x & 31, w = threadIdx.x >> 5;
    #pragma unroll
    for (int o = 16; o; o >>= 1) {
        s  += __shfl_down_sync(0xffffffffu, s,  o);
        ss += __shfl_down_sync(0xffffffffu, ss, o);
    }
    if (!lane) { sh[w] = s; sh[8 + w] = ss; }
    __syncthreads();
    if (threadIdx.x == 0) {
        float a = 0.f, b = 0.f;
        #pragma unroll
        for (int i = 0; i < 8; i++) { a += sh[i]; b += sh[8 + i]; }
        sh[0] = a; sh[8] = b;
    }
    __syncthreads();
    s = sh[0]; ss = sh[8];
}

// ---------------- LayerNorm over rows of 1024 ----------------
__global__ __launch_bounds__(256) void ln_rows(const float* __restrict__ in,
                                               float* __restrict__ out,
                                               const float* __restrict__ gw,
                                               const float* __restrict__ bw) {
    size_t row = blockIdx.x;
    const float* x = in + row * 1024;
    int t4 = threadIdx.x * 4;
    float4 v = *reinterpret_cast<const float4*>(x + t4);
    float s  = v.x + v.y + v.z + v.w;
    float ss = v.x*v.x + v.y*v.y + v.z*v.z + v.w*v.w;
    block_reduce_2(s, ss);
    float mu  = s * (1.0f / 1024.0f);
    float var = ss * (1.0f / 1024.0f) - mu * mu;
    float rstd = rsqrtf(var + 1e-5f);
    float4 g = *reinterpret_cast<const float4*>(gw + t4);
    float4 b = *reinterpret_cast<const float4*>(bw + t4);
    float4 o;
    o.x = (v.x - mu) * rstd * g.x + b.x;
    o.y = (v.y - mu) * rstd * g.y + b.y;
    o.z = (v.z - mu) * rstd * g.z + b.z;
    o.w = (v.w - mu) * rstd * g.w + b.w;
    *reinterpret_cast<float4*>(out + row * 1024 + t4) = o;
}

// ---------------- gelu then LayerNorm, in-place rows of 1024 ----------------
__global__ __launch_bounds__(256) void gelu_ln_rows(float* __restrict__ data,
                                                    const float* __restrict__ gw,
                                                    const float* __restrict__ bw) {
    size_t row = blockIdx.x;
    float* x = data + row * 1024;
    int t4 = threadIdx.x * 4;
    float4 v = *reinterpret_cast<const float4*>(x + t4);
    v.x = gelu_exact(v.x); v.y = gelu_exact(v.y);
    v.z = gelu_exact(v.z); v.w = gelu_exact(v.w);
    float s  = v.x + v.y + v.z + v.w;
    float ss = v.x*v.x + v.y*v.y + v.z*v.z + v.w*v.w;
    block_reduce_2(s, ss);
    float mu  = s * (1.0f / 1024.0f);
    float var = ss * (1.0f / 1024.0f) - mu * mu;
    float rstd = rsqrtf(var + 1e-5f);
    float4 g = *reinterpret_cast<const float4*>(gw + t4);
    float4 b = *reinterpret_cast<const float4*>(bw + t4);
    float4 o;
    o.x = (v.x - mu) * rstd * g.x + b.x;
    o.y = (v.y - mu) * rstd * g.y + b.y;
    o.z = (v.z - mu) * rstd * g.z + b.z;
    o.w = (v.w - mu) * rstd * g.w + b.w;
    *reinterpret_cast<float4*>(x + t4) = o;
}

// ---------------- GroupNorm: scalar, one warp per head ----------------
__global__ __launch_bounds__(256) void groupnorm2(const float* __restrict__ gng,
                                                  const float* __restrict__ gnb) {
    size_t row = blockIdx.x;
    int head = threadIdx.x >> 5, lane = threadIdx.x & 31;
    const float* x = d_h + row * 1024 + head * 128;
    float s = 0.f, ss = 0.f;
    for (int j = lane; j < 128; j += 32) {
        float v = x[j];
        s += v; ss += v * v;
    }
    #pragma unroll
    for (int o = 16; o; o >>= 1) {
        s  += __shfl_xor_sync(0xffffffffu, s,  o);
        ss += __shfl_xor_sync(0xffffffffu, ss, o);
    }
    float mu  = s * (1.0f / 128.0f);
    float var = ss * (1.0f / 128.0f) - mu * mu;
    float rstd = rsqrtf(var + 1e-5f);
    for (int j = lane; j < 128; j += 32) {
        int ch = head * 128 + j;
        d_hn[row * 1024 + ch] = (x[j] - mu) * rstd * gng[ch] + gnb[ch];
    }
}

// ---------------- fc1 conv only (12->12, k=3, same): xn -> xc ----------------
__global__ __launch_bounds__(128) void fc1_conv(const float* __restrict__ w1,
                                                const float* __restrict__ b1) {
    __shared__ float sx[12][130];
    __shared__ float sw1[12 * 12 * 3];
    __shared__ float sb1[12];
    int b = blockIdx.y, l0 = blockIdx.x * 128, tid = threadIdx.x;
    for (int i = tid; i < 12 * 130; i += 128) {
        int c = i / 130, j = i % 130, l = l0 + j - 1;
        sx[c][j] = (l >= 0 && l < 1024) ? d_xn[(size_t)(b * 12 + c) * 1024 + l] : 0.f;
    }
    for (int i = tid; i < 432; i += 128) sw1[i] = w1[i];
    if (tid < 12) sb1[tid] = b1[tid];
    __syncthreads();
    int l = l0 + tid;
    #pragma unroll
    for (int o = 0; o < 12; o++) {
        float a = sb1[o];
        #pragma unroll
        for (int c = 0; c < 12; c++) {
            const float* wp = &sw1[(o * 12 + c) * 3];
            a += wp[0] * sx[c][tid] + wp[1] * sx[c][tid + 1] + wp[2] * sx[c][tid + 2];
        }
        d_xc[(size_t)(b * 12 + o) * 1024 + l] = a;
    }
}

// ---------------- fc2 (1x1) ----------------
__global__ __launch_bounds__(256) void fc2_1x1(const float* __restrict__ w2,
                                               const float* __restrict__ b2) {
    __shared__ float sw2[144], sb2[12];
    int b = blockIdx.y, l = blockIdx.x * 256 + threadIdx.x;
    if (threadIdx.x < 144) sw2[threadIdx.x] = w2[threadIdx.x];
    if (threadIdx.x < 12) sb2[threadIdx.x] = b2[threadIdx.x];
    __syncthreads();
    float xv[12];
    #pragma unroll
    for (int c = 0; c < 12; c++) xv[c] = d_xc[(size_t)(b * 12 + c) * 1024 + l];
    #pragma unroll
    for (int o = 0; o < 12; o++) {
        float a = sb2[o];
        #pragma unroll
        for (int c = 0; c < 12; c++) a += sw2[o * 12 + c] * xv[c];
        d_x1[(size_t)(b * 12 + o) * 1024 + l] = a;
    }
}

// ---------------- conv1: 12 -> 48 ----------------
__global__ __launch_bounds__(128) void conv12_48(const float* __restrict__ w,
                                                 const float* __restrict__ bb) {
    __shared__ float sx[12][130];
    __shared__ float sw[48 * 12 * 3];
    __shared__ float sb[48];
    int b = blockIdx.y, l0 = blockIdx.x * 128, tid = threadIdx.x;
    for (int i = tid; i < 12 * 130; i += 128) {
        int c = i / 130, j = i % 130, l = l0 + j - 1;
        sx[c][j] = (l >= 0 && l < 1024) ? d_y[(size_t)(b * 12 + c) * 1024 + l] : 0.f;
    }
    for (int i = tid; i < 1728; i += 128) sw[i] = w[i];
    if (tid < 48) sb[tid] = bb[tid];
    __syncthreads();
    float acc[48];
    #pragma unroll
    for (int o = 0; o < 48; o++) acc[o] = sb[o];
    #pragma unroll
    for (int c = 0; c < 12; c++) {
        float x0 = sx[c][tid], x1 = sx[c][tid + 1], x2 = sx[c][tid + 2];
        #pragma unroll
        for (int o = 0; o < 48; o++) {
            const float* wp = &sw[(o * 12 + c) * 3];
            acc[o] += wp[0] * x0 + wp[1] * x1 + wp[2] * x2;
        }
    }
    int l = l0 + tid;
    #pragma unroll
    for (int o = 0; o < 48; o++) d_z48[(size_t)(b * 48 + o) * 1024 + l] = acc[o];
}

// ---------------- conv2: 48 -> 12; + skip -> out ----------------
__global__ __launch_bounds__(128) void conv48_12(const float* __restrict__ w,
                                                 const float* __restrict__ bb,
                                                 float* __restrict__ out) {
    __shared__ float sx[48][130];
    __shared__ float sw[12 * 48 * 3];
    __shared__ float sb[12];
    int b = blockIdx.y, l0 = blockIdx.x * 128, tid = threadIdx.x;
    for (int i = tid; i < 48 * 130; i += 128) {
        int c = i / 130, j = i % 130, l = l0 + j - 1;
        sx[c][j] = (l >= 0 && l < 1024) ? d_z48[(size_t)(b * 48 + c) * 1024 + l] : 0.f;
    }
    for (int i = tid; i < 1728; i += 128) sw[i] = w[i];
    if (tid < 12) sb[tid] = bb[tid];
    __syncthreads();
    float acc[12];
    #pragma unroll
    for (int o = 0; o < 12; o++) acc[o] = sb[o];
    #pragma unroll
    for (int c = 0; c < 48; c++) {
        float x0 = sx[c][tid], x1 = sx[c][tid + 1], x2 = sx[c][tid + 2];
        #pragma unroll
        for (int o = 0; o < 12; o++) {
            const float* wp = &sw[(o * 48 + c) * 3];
            acc[o] += wp[0] * x0 + wp[1] * x1 + wp[2] * x2;
        }
    }
    int l = l0 + tid;
    #pragma unroll
    for (int o = 0; o < 12; o++) {
        size_t idx = (size_t)(b * 12 + o) * 1024 + l;
        out[idx] = acc[o] + d_xn[idx];
    }
}

// ---------------- elementwise ----------------
__global__ __launch_bounds__(256) void ew_gelu_mul2() {
    size_t i = (size_t)blockIdx.x * 256 + threadIdx.x;
    d_left[i] = gelu_exact(d_left[i]) * d_right[i];
}
__global__ __launch_bounds__(256) void ew_y2() {
    size_t i = (size_t)blockIdx.x * 256 + threadIdx.x;
    float c = d_xc[i];
    d_y[i] = c * sigmoidf_(c) * d_x1o[i] + d_xn[i];
}

// ---------------- TF32 tensor-core GEMM ----------------
// C[M,N] = A[M,K] @ B[K,N] + bias (+resid). Block tile 128x128, BK=32.
// 8 warps: warpM = warp>>2 (2 tiles of 64 rows), warpN = warp&3 (4 tiles of 32 cols).
// Warp tile 64x32 via mma.sync.m16n8k8 (4 m-tiles x 4 n-tiles).
__global__ __launch_bounds__(256) void gemm_tf32(int N, int K,
                                                 const float* __restrict__ A,
                                                 const float* __restrict__ Bm,
                                                 const float* __restrict__ bias,
                                                 const float* __restrict__ resid,
                                                 float* __restrict__ C) {
    __shared__ float As[128 * 36];   // [r][k], pad 36 -> A-frag loads conflict-free
    __shared__ float Bs[32 * 136];   // [k][c], pad 136 -> B-frag loads conflict-free
    int tid = threadIdx.x;
    int warp = tid >> 5, lane = tid & 31;
    int g = lane >> 2, tg = lane & 3;           // group-of-4 id, thread-in-group
    int warpM = warp >> 2, warpN = warp & 3;
    int row0 = blockIdx.y * 128, col0 = blockIdx.x * 128;
    float acc[4][4][4];
    #pragma unroll
    for (int m = 0; m < 4; m++)
        #pragma unroll
        for (int n = 0; n < 4; n++)
            #pragma unroll
            for (int q = 0; q < 4; q++) acc[m][n][q] = 0.f;

    for (int k0 = 0; k0 < K; k0 += 32) {
        // stage A tile (128x32) as tf32
        #pragma unroll
        for (int i = 0; i < 4; i++) {
            int e = i * 1024 + tid * 4;
            int r = e >> 5, c = e & 31;
            float4 v = *reinterpret_cast<const float4*>(A + (size_t)(row0 + r) * K + k0 + c);
            As[r * 36 + c + 0] = to_tf32(v.x);
            As[r * 36 + c + 1] = to_tf32(v.y);
            As[r * 36 + c + 2] = to_tf32(v.z);
            As[r * 36 + c + 3] = to_tf32(v.w);
        }
        // stage B tile (32x128) as tf32
        #pragma unroll
        for (int i = 0; i < 4; i++) {
            int e = i * 1024 + tid * 4;
            int k = e >> 7, c = e & 127;
            float4 v = *reinterpret_cast<const float4*>(Bm + (size_t)(k0 + k) * N + col0 + c);
            Bs[k * 136 + c + 0] = to_tf32(v.x);
            Bs[k * 136 + c + 1] = to_tf32(v.y);
            Bs[k * 136 + c + 2] = to_tf32(v.z);
            Bs[k * 136 + c + 3] = to_tf32(v.w);
        }
        __syncthreads();
        #pragma unroll
        for (int kc = 0; kc < 4; kc++) {
            int kb = kc * 8;
            uint32_t af[4][4];
            #pragma unroll
            for (int m = 0; m < 4; m++) {
                int r = warpM * 64 + m * 16;
                af[m][0] = __float_as_uint(As[(r + g)     * 36 + kb + tg]);
                af[m][1] = __float_as_uint(As[(r + 8 + g) * 36 + kb + tg]);
                af[m][2] = __float_as_uint(As[(r + g)     * 36 + kb + tg + 4]);
                af[m][3] = __float_as_uint(As[(r + 8 + g) * 36 + kb + tg + 4]);
            }
            uint32_t bf[4][2];
            #pragma unroll
            for (int n = 0; n < 4; n++) {
                int c = warpN * 32 + n * 8 + g;
                bf[n][0] = __float_as_uint(Bs[(kb + tg)     * 136 + c]);
                bf[n][1] = __float_as_uint(Bs[(kb + tg + 4) * 136 + c]);
            }
            #pragma unroll
            for (int m = 0; m < 4; m++)
                #pragma unroll
                for (int n = 0; n < 4; n++) {
                    asm volatile(
                        "mma.sync.aligned.m16n8k8.row.col.f32.tf32.tf32.f32 "
                        "{%0,%1,%2,%3}, {%4,%5,%6,%7}, {%8,%9}, {%0,%1,%2,%3};"
                        : "+f"(acc[m][n][0]), "+f"(acc[m][n][1]),
                          "+f"(acc[m][n][2]), "+f"(acc[m][n][3])
                        : "r"(af[m][0]), "r"(af[m][1]), "r"(af[m][2]), "r"(af[m][3]),
                          "r"(bf[n][0]), "r"(bf[n][1]));
                }
        }
        __syncthreads();
    }
    // epilogue: c0:(g,2tg) c1:(g,2tg+1) c2:(g+8,2tg) c3:(g+8,2tg+1)
    #pragma unroll
    for (int m = 0; m < 4; m++) {
        int r = row0 + warpM * 64 + m * 16 + g;
        #pragma unroll
        for (int n = 0; n < 4; n++) {
            int c = col0 + warpN * 32 + n * 8 + 2 * tg;
            float v0 = acc[m][n][0] + bias[c];
            float v1 = acc[m][n][1] + bias[c + 1];
            float v2 = acc[m][n][2] + bias[c];
            float v3 = acc[m][n][3] + bias[c + 1];
            if (resid) {
                v0 += resid[(size_t)r * N + c];
                v1 += resid[(size_t)r * N + c + 1];
                v2 += resid[(size_t)(r + 8) * N + c];
                v3 += resid[(size_t)(r + 8) * N + c + 1];
            }
            *reinterpret_cast<float2*>(C + (size_t)r * N + c)       = make_float2(v0, v1);
            *reinterpret_cast<float2*>(C + (size_t)(r + 8) * N + c) = make_float2(v2, v3);
        }
    }
}

// ---------------- Rg transpose: RgT[n][hs][g] = Rg[n][g][hs] ----------------
__global__ void rg_transpose(const float* __restrict__ Rg) {
    __shared__ float tile[32][33];
    int n = blockIdx.x, g0 = blockIdx.y << 5, h0 = blockIdx.z << 5;
    int x = threadIdx.x, y = threadIdx.y;
    #pragma unroll
    for (int j = y; j < 32; j += 8)
        tile[j][x] = Rg[(size_t)(n * 512 + g0 + j) * 128 + h0 + x];
    __syncthreads();
    #pragma unroll
    for (int j = y; j < 32; j += 8)
        d_RgT[(size_t)(n * 128 + h0 + j) * 512 + g0 + x] = tile[x][j];
}

// ---------------- sLSTM recurrence (verified R4 version) ----------------
__global__ __launch_bounds__(256) void slstm_rec2() {
    __shared__ float sh_hT[128 * 17];
    __shared__ float sh_rec[16 * 512];
    int head = blockIdx.x >> 5;
    int b0 = (blockIdx.x & 31) << 4;
    int tid = threadIdx.x;
    for (int i = tid; i < 128 * 17; i += 256) sh_hT[i] = 0.f;
    float cS[8], nS[8], mS[8];
    #pragma unroll
    for (int j = 0; j < 8; j++) { cS[j] = 0.f; nS[j] = 0.f; mS[j] = 0.f; }
    __syncthreads();
    const float* RgTh = d_RgT + (size_t)head * (128 * 512);
    for (int t = 0; t < 12; t++) {
        float acc0[16], acc1[16];
        #pragma unroll
        for (int b = 0; b < 16; b++) { acc0[b] = 0.f; acc1[b] = 0.f; }
        #pragma unroll 4
        for (int h = 0; h < 128; h++) {
            float w0 = __ldg(RgTh + (size_t)h * 512 + tid);
            float w1 = __ldg(RgTh + (size_t)h * 512 + 256 + tid);
            #pragma unroll
            for (int b = 0; b < 16; b++) {
                float hv = sh_hT[h * 17 + b];
                acc0[b] = fmaf(hv, w0, acc0[b]);
                acc1[b] = fmaf(hv, w1, acc1[b]);
            }
        }
        #pragma unroll
        for (int b = 0; b < 16; b++) {
            sh_rec[b * 512 + tid]       = acc0[b];
            sh_rec[b * 512 + 256 + tid] = acc1[b];
        }
        __syncthreads();
        #pragma unroll
        for (int it = 0; it < 8; it++) {
            int idx = it * 256 + tid;
            int bb = idx >> 7, hs = idx & 127;
            int b = b0 + bb;
            const float* gxp = d_gx + (size_t)(b * 12 + t) * 4096 + head * 512;
            const float* rp = sh_rec + bb * 512;
            float z_ = gxp[hs]       + rp[hs];
            float i_ = gxp[128 + hs] + rp[128 + hs];
            float f_ = gxp[256 + hs] + rp[256 + hs];
            float o_ = gxp[384 + hs] + rp[384 + hs];
            float z  = tanhf(z_);
            float o  = sigmoidf_(o_);
            float mo = mS[it];
            float mn = fmaxf(f_ + mo, i_);
            float iv = expf(i_ - mn);
            float fv = expf(f_ + mo - mn);
            float cv = fv * cS[it] + iv * z;
            float nv = fv * nS[it] + iv;
            float hv = o * (cv / nv);
            cS[it] = cv; nS[it] = nv; mS[it] = mn;
            sh_hT[hs * 17 + bb] = hv;
            d_h[(size_t)((b * 12 + t) * 8 + head) * 128 + hs] = hv;
        }
        __syncthreads();
    }
}

// ---------------- launch ----------------
extern "C" void kernel_launch(void* const* d_in, const int* in_sizes, int n_in,
                              void* d_out, int out_size) {
    const float* x       = (const float*)d_in[0];
    const float* ln_g    = (const float*)d_in[1];
    const float* ln_b    = (const float*)d_in[2];
    const float* fc1_w   = (const float*)d_in[3];
    const float* fc1_b   = (const float*)d_in[4];
    const float* fc2_w   = (const float*)d_in[5];
    const float* fc2_b   = (const float*)d_in[6];
    const float* conv1_w = (const float*)d_in[7];
    const float* conv1_b = (const float*)d_in[8];
    const float* conv2_w = (const float*)d_in[9];
    const float* conv2_b = (const float*)d_in[10];
    const float* xlg     = (const float*)d_in[11];
    const float* xlb     = (const float*)d_in[12];
    const float* Wg      = (const float*)d_in[13];
    const float* bg      = (const float*)d_in[14];
    const float* Rg      = (const float*)d_in[15];
    const float* gng     = (const float*)d_in[16];
    const float* gnb     = (const float*)d_in[17];
    const float* uplw    = (const float*)d_in[18];
    const float* uplb    = (const float*)d_in[19];
    const float* uprw    = (const float*)d_in[20];
    const float* uprb    = (const float*)d_in[21];
    const float* downw   = (const float*)d_in[22];
    const float* downb   = (const float*)d_in[23];
    float* out = (float*)d_out;

    float *p_xn, *p_x1, *p_xn2, *p_gx, *p_hn, *p_left, *p_right, *p_x1o, *p_z48;
    cudaGetSymbolAddress((void**)&p_xn,   d_xn);
    cudaGetSymbolAddress((void**)&p_x1,   d_x1);
    cudaGetSymbolAddress((void**)&p_xn2,  d_xn2);
    cudaGetSymbolAddress((void**)&p_gx,   d_gx);
    cudaGetSymbolAddress((void**)&p_hn,   d_hn);
    cudaGetSymbolAddress((void**)&p_left, d_left);
    cudaGetSymbolAddress((void**)&p_right,d_right);
    cudaGetSymbolAddress((void**)&p_x1o,  d_x1o);
    cudaGetSymbolAddress((void**)&p_z48,  d_z48);

    rg_transpose<<<dim3(8, 16, 4), dim3(32, 8)>>>(Rg);

    // xn = LN(x); skip = xn
    ln_rows<<<BT_, 256>>>(x, p_xn, ln_g, ln_b);
    // xc = conv1d(xn, fc1)
    fc1_conv<<<dim3(8, B_), 128>>>(fc1_w, fc1_b);
    // x1 = fc2(xc)
    fc2_1x1<<<dim3(4, B_), 256>>>(fc2_w, fc2_b);
    // xn2 = LN(x1)
    ln_rows<<<BT_, 256>>>(p_x1, p_xn2, xlg, xlb);
    // gx = xn2 @ Wg + bg   (6144 x 1024 x 4096)  [TF32 tensor cores]
    gemm_tf32<<<dim3(32, 48), 256>>>(4096, 1024, p_xn2, Wg, bg, nullptr, p_gx);
    // sLSTM recurrence -> d_h
    slstm_rec2<<<256, 256>>>();
    // per-head GroupNorm -> d_hn
    groupnorm2<<<BT_, 256>>>(gng, gnb);
    // left/right projections [TF32]
    gemm_tf32<<<dim3(8, 48), 256>>>(1024, 1024, p_hn, uplw, uplb, nullptr, p_left);
    gemm_tf32<<<dim3(8, 48), 256>>>(1024, 1024, p_hn, uprw, uprb, nullptr, p_right);
    // u = gelu(left) * right
    ew_gelu_mul2<<<24576, 256>>>();
    // x1_out = u @ down_w + down_b + x1 [TF32]
    gemm_tf32<<<dim3(8, 48), 256>>>(1024, 1024, p_left, downw, downb, p_x1, p_x1o);
    // y = silu(xc) * x1_out + xn
    ew_y2<<<24576, 256>>>();
    // z48 = conv1d(y, 12->48)
    conv12_48<<<dim3(8, B_), 128>>>(conv1_w, conv1_b);
    // z48 = LN(gelu(z48))
    gelu_ln_rows<<<ROWS48_, 256>>>(p_z48, ln_g, ln_b);
    // out = conv1d(z48, 48->12) + skip
    conv48_12<<<dim3(8, B_), 128>>>(conv2_w, conv2_b, out);
}

// round 7
// speedup vs baseline: 2.3614x; 1.0423x over previous
#include <cuda_runtime.h>
#include <cmath>
#include <cstdint>

// ---------------- problem constants ----------------
static constexpr int B_   = 512;
static constexpr int T_   = 12;
static constexpr int E_   = 1024;
static constexpr int NH_  = 8;
static constexpr int HS_  = 128;
static constexpr int H_   = 1024;
static constexpr int G4_  = 4096;
static constexpr int BT_  = B_ * T_;        // 6144
static constexpr int ROWS48_ = B_ * 48;     // 24576

// ---------------- scratch (device globals; no allocation) ----------------
__device__ float d_xn [BT_ * (size_t)E_];
__device__ float d_xc [BT_ * (size_t)E_];
__device__ float d_x1 [BT_ * (size_t)E_];
__device__ float d_xn2[BT_ * (size_t)E_];
__device__ float d_gx [BT_ * (size_t)G4_];
__device__ float d_h  [BT_ * (size_t)H_];
__device__ float d_hn [BT_ * (size_t)H_];
__device__ float d_left [BT_ * (size_t)H_];
__device__ float d_y  [BT_ * (size_t)E_];
__device__ float d_z48[(size_t)B_ * 48 * E_];
__device__ float d_RgT[(size_t)NH_ * HS_ * 512];

// ---------------- helpers ----------------
__device__ __forceinline__ float gelu_exact(float x) {
    return 0.5f * x * (1.0f + erff(x * 0.70710678118654752440f));
}
__device__ __forceinline__ float sigmoidf_(float x) {
    return 1.0f / (1.0f + expf(-x));
}
__device__ __forceinline__ void cp_async16(uint32_t saddr, const float* g) {
    asm volatile("cp.async.cg.shared.global [%0], [%1], 16;" :: "r"(saddr), "l"(g));
}

// block-wide (256 threads) sum reduce of two values
__device__ __forceinline__ void block_reduce_2(float& s, float& ss) {
    __shared__ float sh[16];
    int lane = threadIdx.x & 31, w = threadIdx.x >> 5;
    #pragma unroll
    for (int o = 16; o; o >>= 1) {
        s  += __shfl_down_sync(0xffffffffu, s,  o);
        ss += __shfl_down_sync(0xffffffffu, ss, o);
    }
    if (!lane) { sh[w] = s; sh[8 + w] = ss; }
    __syncthreads();
    if (threadIdx.x == 0) {
        float a = 0.f, b = 0.f;
        #pragma unroll
        for (int i = 0; i < 8; i++) { a += sh[i]; b += sh[8 + i]; }
        sh[0] = a; sh[8] = b;
    }
    __syncthreads();
    s = sh[0]; ss = sh[8];
}

// ---------------- LayerNorm over rows of 1024 ----------------
__global__ __launch_bounds__(256) void ln_rows(const float* __restrict__ in,
                                               float* __restrict__ out,
                                               const float* __restrict__ gw,
                                               const float* __restrict__ bw) {
    size_t row = blockIdx.x;
    const float* x = in + row * 1024;
    int t4 = threadIdx.x * 4;
    float4 v = *reinterpret_cast<const float4*>(x + t4);
    float s  = v.x + v.y + v.z + v.w;
    float ss = v.x*v.x + v.y*v.y + v.z*v.z + v.w*v.w;
    block_reduce_2(s, ss);
    float mu  = s * (1.0f / 1024.0f);
    float var = ss * (1.0f / 1024.0f) - mu * mu;
    float rstd = rsqrtf(var + 1e-5f);
    float4 g = *reinterpret_cast<const float4*>(gw + t4);
    float4 b = *reinterpret_cast<const float4*>(bw + t4);
    float4 o;
    o.x = (v.x - mu) * rstd * g.x + b.x;
    o.y = (v.y - mu) * rstd * g.y + b.y;
    o.z = (v.z - mu) * rstd * g.z + b.z;
    o.w = (v.w - mu) * rstd * g.w + b.w;
    *reinterpret_cast<float4*>(out + row * 1024 + t4) = o;
}

// ---------------- gelu then LayerNorm, in-place rows of 1024 ----------------
__global__ __launch_bounds__(256) void gelu_ln_rows(float* __restrict__ data,
                                                    const float* __restrict__ gw,
                                                    const float* __restrict__ bw) {
    size_t row = blockIdx.x;
    float* x = data + row * 1024;
    int t4 = threadIdx.x * 4;
    float4 v = *reinterpret_cast<const float4*>(x + t4);
    v.x = gelu_exact(v.x); v.y = gelu_exact(v.y);
    v.z = gelu_exact(v.z); v.w = gelu_exact(v.w);
    float s  = v.x + v.y + v.z + v.w;
    float ss = v.x*v.x + v.y*v.y + v.z*v.z + v.w*v.w;
    block_reduce_2(s, ss);
    float mu  = s * (1.0f / 1024.0f);
    float var = ss * (1.0f / 1024.0f) - mu * mu;
    float rstd = rsqrtf(var + 1e-5f);
    float4 g = *reinterpret_cast<const float4*>(gw + t4);
    float4 b = *reinterpret_cast<const float4*>(bw + t4);
    float4 o;
    o.x = (v.x - mu) * rstd * g.x + b.x;
    o.y = (v.y - mu) * rstd * g.y + b.y;
    o.z = (v.z - mu) * rstd * g.z + b.z;
    o.w = (v.w - mu) * rstd * g.w + b.w;
    *reinterpret_cast<float4*>(x + t4) = o;
}

// ---------------- GroupNorm: scalar, one warp per head ----------------
__global__ __launch_bounds__(256) void groupnorm2(const float* __restrict__ gng,
                                                  const float* __restrict__ gnb) {
    size_t row = blockIdx.x;
    int head = threadIdx.x >> 5, lane = threadIdx.x & 31;
    const float* x = d_h + row * 1024 + head * 128;
    float s = 0.f, ss = 0.f;
    for (int j = lane; j < 128; j += 32) {
        float v = x[j];
        s += v; ss += v * v;
    }
    #pragma unroll
    for (int o = 16; o; o >>= 1) {
        s  += __shfl_xor_sync(0xffffffffu, s,  o);
        ss += __shfl_xor_sync(0xffffffffu, ss, o);
    }
    float mu  = s * (1.0f / 128.0f);
    float var = ss * (1.0f / 128.0f) - mu * mu;
    float rstd = rsqrtf(var + 1e-5f);
    for (int j = lane; j < 128; j += 32) {
        int ch = head * 128 + j;
        d_hn[row * 1024 + ch] = (x[j] - mu) * rstd * gng[ch] + gnb[ch];
    }
}

// ---------------- fc1 conv only (12->12, k=3, same): xn -> xc ----------------
__global__ __launch_bounds__(128) void fc1_conv(const float* __restrict__ w1,
                                                const float* __restrict__ b1) {
    __shared__ float sx[12][130];
    __shared__ float sw1[12 * 12 * 3];
    __shared__ float sb1[12];
    int b = blockIdx.y, l0 = blockIdx.x * 128, tid = threadIdx.x;
    for (int i = tid; i < 12 * 130; i += 128) {
        int c = i / 130, j = i % 130, l = l0 + j - 1;
        sx[c][j] = (l >= 0 && l < 1024) ? d_xn[(size_t)(b * 12 + c) * 1024 + l] : 0.f;
    }
    for (int i = tid; i < 432; i += 128) sw1[i] = w1[i];
    if (tid < 12) sb1[tid] = b1[tid];
    __syncthreads();
    int l = l0 + tid;
    #pragma unroll
    for (int o = 0; o < 12; o++) {
        float a = sb1[o];
        #pragma unroll
        for (int c = 0; c < 12; c++) {
            const float* wp = &sw1[(o * 12 + c) * 3];
            a += wp[0] * sx[c][tid] + wp[1] * sx[c][tid + 1] + wp[2] * sx[c][tid + 2];
        }
        d_xc[(size_t)(b * 12 + o) * 1024 + l] = a;
    }
}

// ---------------- fc2 (1x1) ----------------
__global__ __launch_bounds__(256) void fc2_1x1(const float* __restrict__ w2,
                                               const float* __restrict__ b2) {
    __shared__ float sw2[144], sb2[12];
    int b = blockIdx.y, l = blockIdx.x * 256 + threadIdx.x;
    if (threadIdx.x < 144) sw2[threadIdx.x] = w2[threadIdx.x];
    if (threadIdx.x < 12) sb2[threadIdx.x] = b2[threadIdx.x];
    __syncthreads();
    float xv[12];
    #pragma unroll
    for (int c = 0; c < 12; c++) xv[c] = d_xc[(size_t)(b * 12 + c) * 1024 + l];
    #pragma unroll
    for (int o = 0; o < 12; o++) {
        float a = sb2[o];
        #pragma unroll
        for (int c = 0; c < 12; c++) a += sw2[o * 12 + c] * xv[c];
        d_x1[(size_t)(b * 12 + o) * 1024 + l] = a;
    }
}

// ---------------- conv1: 12 -> 48 ----------------
__global__ __launch_bounds__(128) void conv12_48(const float* __restrict__ w,
                                                 const float* __restrict__ bb) {
    __shared__ float sx[12][130];
    __shared__ float sw[48 * 12 * 3];
    __shared__ float sb[48];
    int b = blockIdx.y, l0 = blockIdx.x * 128, tid = threadIdx.x;
    for (int i = tid; i < 12 * 130; i += 128) {
        int c = i / 130, j = i % 130, l = l0 + j - 1;
        sx[c][j] = (l >= 0 && l < 1024) ? d_y[(size_t)(b * 12 + c) * 1024 + l] : 0.f;
    }
    for (int i = tid; i < 1728; i += 128) sw[i] = w[i];
    if (tid < 48) sb[tid] = bb[tid];
    __syncthreads();
    float acc[48];
    #pragma unroll
    for (int o = 0; o < 48; o++) acc[o] = sb[o];
    #pragma unroll
    for (int c = 0; c < 12; c++) {
        float x0 = sx[c][tid], x1 = sx[c][tid + 1], x2 = sx[c][tid + 2];
        #pragma unroll
        for (int o = 0; o < 48; o++) {
            const float* wp = &sw[(o * 12 + c) * 3];
            acc[o] += wp[0] * x0 + wp[1] * x1 + wp[2] * x2;
        }
    }
    int l = l0 + tid;
    #pragma unroll
    for (int o = 0; o < 48; o++) d_z48[(size_t)(b * 48 + o) * 1024 + l] = acc[o];
}

// ---------------- conv2: 48 -> 12; + skip -> out ----------------
__global__ __launch_bounds__(128) void conv48_12(const float* __restrict__ w,
                                                 const float* __restrict__ bb,
                                                 float* __restrict__ out) {
    __shared__ float sx[48][130];
    __shared__ float sw[12 * 48 * 3];
    __shared__ float sb[12];
    int b = blockIdx.y, l0 = blockIdx.x * 128, tid = threadIdx.x;
    for (int i = tid; i < 48 * 130; i += 128) {
        int c = i / 130, j = i % 130, l = l0 + j - 1;
        sx[c][j] = (l >= 0 && l < 1024) ? d_z48[(size_t)(b * 48 + c) * 1024 + l] : 0.f;
    }
    for (int i = tid; i < 1728; i += 128) sw[i] = w[i];
    if (tid < 12) sb[tid] = bb[tid];
    __syncthreads();
    float acc[12];
    #pragma unroll
    for (int o = 0; o < 12; o++) acc[o] = sb[o];
    #pragma unroll
    for (int c = 0; c < 48; c++) {
        float x0 = sx[c][tid], x1 = sx[c][tid + 1], x2 = sx[c][tid + 2];
        #pragma unroll
        for (int o = 0; o < 12; o++) {
            const float* wp = &sw[(o * 48 + c) * 3];
            acc[o] += wp[0] * x0 + wp[1] * x1 + wp[2] * x2;
        }
    }
    int l = l0 + tid;
    #pragma unroll
    for (int o = 0; o < 12; o++) {
        size_t idx = (size_t)(b * 12 + o) * 1024 + l;
        out[idx] = acc[o] + d_xn[idx];
    }
}

// ---------------- TF32 tensor-core GEMM v2: cp.async double-buffered ----------------
// C[M,N] = A[M,K] @ B[K,N], block tile 128x128, BK=16, 2-stage LDGSTS pipeline.
// Raw fp32 bits fed to mma.tf32 (hw truncation; error irrelevant vs 1e-3 budget).
// MODE 0: C = acc + bias
// MODE 1: C = gelu(aux0) * (acc + bias)                       [u = gelu(left)*right]
// MODE 2: C = silu(aux0) * (acc + bias + aux1) + aux2         [y = silu(xc)*x1o + xn]
template<int MODE>
__global__ __launch_bounds__(256) void gemm_tf32_v2(int N, int K,
                                                    const float* __restrict__ A,
                                                    const float* __restrict__ Bm,
                                                    const float* __restrict__ bias,
                                                    const float* __restrict__ aux0,
                                                    const float* __restrict__ aux1,
                                                    const float* __restrict__ aux2,
                                                    float* __restrict__ C) {
    __shared__ float As[2][128 * 20];   // [r][k] pad 20: banks 20g+tg distinct, 16B-aligned
    __shared__ float Bs[2][16 * 136];   // [k][c] pad 136: banks 8tg+g distinct, 16B-aligned
    int tid = threadIdx.x;
    int warp = tid >> 5, lane = tid & 31;
    int g = lane >> 2, tg = lane & 3;
    int warpM = warp >> 2, warpN = warp & 3;
    int row0 = blockIdx.y * 128, col0 = blockIdx.x * 128;

    uint32_t asb = (uint32_t)__cvta_generic_to_shared(&As[0][0]);
    uint32_t bsb = (uint32_t)__cvta_generic_to_shared(&Bs[0][0]);

    float acc[4][4][4];
    #pragma unroll
    for (int m = 0; m < 4; m++)
        #pragma unroll
        for (int n = 0; n < 4; n++)
            #pragma unroll
            for (int q = 0; q < 4; q++) acc[m][n][q] = 0.f;

    const int nt = K >> 4;    // K/16 tiles

    auto load_tile = [&](int it, int buf) {
        int k0 = it << 4;
        #pragma unroll
        for (int i = 0; i < 2; i++) {
            int e = i * 256 + tid;
            int r = e >> 2, kq = (e & 3) * 4;
            cp_async16(asb + (uint32_t)(buf * 128 * 20 + r * 20 + kq) * 4,
                       A + (size_t)(row0 + r) * K + k0 + kq);
        }
        #pragma unroll
        for (int i = 0; i < 2; i++) {
            int e = i * 256 + tid;
            int k = e >> 5, c = (e & 31) * 4;
            cp_async16(bsb + (uint32_t)(buf * 16 * 136 + k * 136 + c) * 4,
                       Bm + (size_t)(k0 + k) * N + col0 + c);
        }
        asm volatile("cp.async.commit_group;");
    };

    load_tile(0, 0);
    for (int it = 0; it < nt; it++) {
        int buf = it & 1;
        if (it + 1 < nt) {
            load_tile(it + 1, buf ^ 1);
            asm volatile("cp.async.wait_group 1;");
        } else {
            asm volatile("cp.async.wait_group 0;");
        }
        __syncthreads();
        const float* Ab = &As[buf][0];
        const float* Bb = &Bs[buf][0];
        #pragma unroll
        for (int kc = 0; kc < 2; kc++) {
            int kb = kc * 8;
            uint32_t af[4][4];
            #pragma unroll
            for (int m = 0; m < 4; m++) {
                int r = warpM * 64 + m * 16;
                af[m][0] = __float_as_uint(Ab[(r + g)     * 20 + kb + tg]);
                af[m][1] = __float_as_uint(Ab[(r + 8 + g) * 20 + kb + tg]);
                af[m][2] = __float_as_uint(Ab[(r + g)     * 20 + kb + tg + 4]);
                af[m][3] = __float_as_uint(Ab[(r + 8 + g) * 20 + kb + tg + 4]);
            }
            uint32_t bf[4][2];
            #pragma unroll
            for (int n = 0; n < 4; n++) {
                int c = warpN * 32 + n * 8 + g;
                bf[n][0] = __float_as_uint(Bb[(kb + tg)     * 136 + c]);
                bf[n][1] = __float_as_uint(Bb[(kb + tg + 4) * 136 + c]);
            }
            #pragma unroll
            for (int m = 0; m < 4; m++)
                #pragma unroll
                for (int n = 0; n < 4; n++) {
                    asm volatile(
                        "mma.sync.aligned.m16n8k8.row.col.f32.tf32.tf32.f32 "
                        "{%0,%1,%2,%3}, {%4,%5,%6,%7}, {%8,%9}, {%0,%1,%2,%3};"
                        : "+f"(acc[m][n][0]), "+f"(acc[m][n][1]),
                          "+f"(acc[m][n][2]), "+f"(acc[m][n][3])
                        : "r"(af[m][0]), "r"(af[m][1]), "r"(af[m][2]), "r"(af[m][3]),
                          "r"(bf[n][0]), "r"(bf[n][1]));
                }
        }
        __syncthreads();
    }

    // epilogue: c0:(g,2tg) c1:(g,2tg+1) c2:(g+8,2tg) c3:(g+8,2tg+1)
    #pragma unroll
    for (int m = 0; m < 4; m++) {
        int r = row0 + warpM * 64 + m * 16 + g;
        #pragma unroll
        for (int n = 0; n < 4; n++) {
            int c = col0 + warpN * 32 + n * 8 + 2 * tg;
            #pragma unroll
            for (int half = 0; half < 2; half++) {
                int rr = r + half * 8;
                size_t i0 = (size_t)rr * N + c;
                float v0 = acc[m][n][half * 2 + 0] + bias[c];
                float v1 = acc[m][n][half * 2 + 1] + bias[c + 1];
                if (MODE == 1) {
                    v0 = gelu_exact(aux0[i0])     * v0;
                    v1 = gelu_exact(aux0[i0 + 1]) * v1;
                } else if (MODE == 2) {
                    float x0 = aux0[i0], x1v = aux0[i0 + 1];
                    v0 = x0  * sigmoidf_(x0)  * (v0 + aux1[i0])     + aux2[i0];
                    v1 = x1v * sigmoidf_(x1v) * (v1 + aux1[i0 + 1]) + aux2[i0 + 1];
                }
                *reinterpret_cast<float2*>(C + i0) = make_float2(v0, v1);
            }
        }
    }
}

// ---------------- Rg transpose: RgT[n][hs][g] = Rg[n][g][hs] ----------------
__global__ void rg_transpose(const float* __restrict__ Rg) {
    __shared__ float tile[32][33];
    int n = blockIdx.x, g0 = blockIdx.y << 5, h0 = blockIdx.z << 5;
    int x = threadIdx.x, y = threadIdx.y;
    #pragma unroll
    for (int j = y; j < 32; j += 8)
        tile[j][x] = Rg[(size_t)(n * 512 + g0 + j) * 128 + h0 + x];
    __syncthreads();
    #pragma unroll
    for (int j = y; j < 32; j += 8)
        d_RgT[(size_t)(n * 128 + h0 + j) * 512 + g0 + x] = tile[x][j];
}

// ---------------- sLSTM recurrence (verified) ----------------
__global__ __launch_bounds__(256) void slstm_rec2() {
    __shared__ float sh_hT[128 * 17];
    __shared__ float sh_rec[16 * 512];
    int head = blockIdx.x >> 5;
    int b0 = (blockIdx.x & 31) << 4;
    int tid = threadIdx.x;
    for (int i = tid; i < 128 * 17; i += 256) sh_hT[i] = 0.f;
    float cS[8], nS[8], mS[8];
    #pragma unroll
    for (int j = 0; j < 8; j++) { cS[j] = 0.f; nS[j] = 0.f; mS[j] = 0.f; }
    __syncthreads();
    const float* RgTh = d_RgT + (size_t)head * (128 * 512);
    for (int t = 0; t < 12; t++) {
        float acc0[16], acc1[16];
        #pragma unroll
        for (int b = 0; b < 16; b++) { acc0[b] = 0.f; acc1[b] = 0.f; }
        #pragma unroll 4
        for (int h = 0; h < 128; h++) {
            float w0 = __ldg(RgTh + (size_t)h * 512 + tid);
            float w1 = __ldg(RgTh + (size_t)h * 512 + 256 + tid);
            #pragma unroll
            for (int b = 0; b < 16; b++) {
                float hv = sh_hT[h * 17 + b];
                acc0[b] = fmaf(hv, w0, acc0[b]);
                acc1[b] = fmaf(hv, w1, acc1[b]);
            }
        }
        #pragma unroll
        for (int b = 0; b < 16; b++) {
            sh_rec[b * 512 + tid]       = acc0[b];
            sh_rec[b * 512 + 256 + tid] = acc1[b];
        }
        __syncthreads();
        #pragma unroll
        for (int it = 0; it < 8; it++) {
            int idx = it * 256 + tid;
            int bb = idx >> 7, hs = idx & 127;
            int b = b0 + bb;
            const float* gxp = d_gx + (size_t)(b * 12 + t) * 4096 + head * 512;
            const float* rp = sh_rec + bb * 512;
            float z_ = gxp[hs]       + rp[hs];
            float i_ = gxp[128 + hs] + rp[128 + hs];
            float f_ = gxp[256 + hs] + rp[256 + hs];
            float o_ = gxp[384 + hs] + rp[384 + hs];
            float z  = tanhf(z_);
            float o  = sigmoidf_(o_);
            float mo = mS[it];
            float mn = fmaxf(f_ + mo, i_);
            float iv = expf(i_ - mn);
            float fv = expf(f_ + mo - mn);
            float cv = fv * cS[it] + iv * z;
            float nv = fv * nS[it] + iv;
            float hv = o * (cv / nv);
            cS[it] = cv; nS[it] = nv; mS[it] = mn;
            sh_hT[hs * 17 + bb] = hv;
            d_h[(size_t)((b * 12 + t) * 8 + head) * 128 + hs] = hv;
        }
        __syncthreads();
    }
}

// ---------------- launch ----------------
extern "C" void kernel_launch(void* const* d_in, const int* in_sizes, int n_in,
                              void* d_out, int out_size) {
    const float* x       = (const float*)d_in[0];
    const float* ln_g    = (const float*)d_in[1];
    const float* ln_b    = (const float*)d_in[2];
    const float* fc1_w   = (const float*)d_in[3];
    const float* fc1_b   = (const float*)d_in[4];
    const float* fc2_w   = (const float*)d_in[5];
    const float* fc2_b   = (const float*)d_in[6];
    const float* conv1_w = (const float*)d_in[7];
    const float* conv1_b = (const float*)d_in[8];
    const float* conv2_w = (const float*)d_in[9];
    const float* conv2_b = (const float*)d_in[10];
    const float* xlg     = (const float*)d_in[11];
    const float* xlb     = (const float*)d_in[12];
    const float* Wg      = (const float*)d_in[13];
    const float* bg      = (const float*)d_in[14];
    const float* Rg      = (const float*)d_in[15];
    const float* gng     = (const float*)d_in[16];
    const float* gnb     = (const float*)d_in[17];
    const float* uplw    = (const float*)d_in[18];
    const float* uplb    = (const float*)d_in[19];
    const float* uprw    = (const float*)d_in[20];
    const float* uprb    = (const float*)d_in[21];
    const float* downw   = (const float*)d_in[22];
    const float* downb   = (const float*)d_in[23];
    float* out = (float*)d_out;

    float *p_xn, *p_xc, *p_x1, *p_xn2, *p_gx, *p_hn, *p_left, *p_y, *p_z48;
    cudaGetSymbolAddress((void**)&p_xn,   d_xn);
    cudaGetSymbolAddress((void**)&p_xc,   d_xc);
    cudaGetSymbolAddress((void**)&p_x1,   d_x1);
    cudaGetSymbolAddress((void**)&p_xn2,  d_xn2);
    cudaGetSymbolAddress((void**)&p_gx,   d_gx);
    cudaGetSymbolAddress((void**)&p_hn,   d_hn);
    cudaGetSymbolAddress((void**)&p_left, d_left);
    cudaGetSymbolAddress((void**)&p_y,    d_y);
    cudaGetSymbolAddress((void**)&p_z48,  d_z48);

    rg_transpose<<<dim3(8, 16, 4), dim3(32, 8)>>>(Rg);

    // xn = LN(x); skip = xn
    ln_rows<<<BT_, 256>>>(x, p_xn, ln_g, ln_b);
    // xc = conv1d(xn, fc1)
    fc1_conv<<<dim3(8, B_), 128>>>(fc1_w, fc1_b);
    // x1 = fc2(xc)
    fc2_1x1<<<dim3(4, B_), 256>>>(fc2_w, fc2_b);
    // xn2 = LN(x1)
    ln_rows<<<BT_, 256>>>(p_x1, p_xn2, xlg, xlb);
    // gx = xn2 @ Wg + bg   [TF32, cp.async pipeline]
    gemm_tf32_v2<0><<<dim3(32, 48), 256>>>(4096, 1024, p_xn2, Wg, bg,
                                           nullptr, nullptr, nullptr, p_gx);
    // sLSTM recurrence -> d_h
    slstm_rec2<<<256, 256>>>();
    // per-head GroupNorm -> d_hn
    groupnorm2<<<BT_, 256>>>(gng, gnb);
    // left = hn @ upl + uplb
    gemm_tf32_v2<0><<<dim3(8, 48), 256>>>(1024, 1024, p_hn, uplw, uplb,
                                          nullptr, nullptr, nullptr, p_left);
    // u = gelu(left) * (hn @ upr + uprb)   [fused epilogue, in-place into d_left]
    gemm_tf32_v2<1><<<dim3(8, 48), 256>>>(1024, 1024, p_hn, uprw, uprb,
                                          p_left, nullptr, nullptr, p_left);
    // y = silu(xc) * (u @ down + downb + x1) + xn   [fused epilogue]
    gemm_tf32_v2<2><<<dim3(8, 48), 256>>>(1024, 1024, p_left, downw, downb,
                                          p_xc, p_x1, p_xn, p_y);
    // z48 = conv1d(y, 12->48)
    conv12_48<<<dim3(8, B_), 128>>>(conv1_w, conv1_b);
    // z48 = LN(gelu(z48))
    gelu_ln_rows<<<ROWS48_, 256>>>(p_z48, ln_g, ln_b);
    // out = conv1d(z48, 48->12) + skip
    conv48_12<<<dim3(8, B_), 128>>>(conv2_w, conv2_b, out);
}

// round 8
// speedup vs baseline: 3.0040x; 1.2722x over previous
#include <cuda_runtime.h>
#include <cuda_bf16.h>
#include <cmath>
#include <cstdint>

// ---------------- problem constants ----------------
static constexpr int B_   = 512;
static constexpr int T_   = 12;
static constexpr int E_   = 1024;
static constexpr int NH_  = 8;
static constexpr int HS_  = 128;
static constexpr int H_   = 1024;
static constexpr int G4_  = 4096;
static constexpr int BT_  = B_ * T_;        // 6144
static constexpr int ROWS48_ = B_ * 48;     // 24576

// ---------------- scratch (device globals; no allocation) ----------------
__device__ float d_xn [BT_ * (size_t)E_];
__device__ float d_xc [BT_ * (size_t)E_];
__device__ float d_x1 [BT_ * (size_t)E_];
__device__ float d_gx [BT_ * (size_t)G4_];
__device__ float d_h  [BT_ * (size_t)H_];
__device__ float d_left [BT_ * (size_t)H_];
__device__ float d_y  [BT_ * (size_t)E_];
__device__ float d_z48[(size_t)B_ * 48 * E_];
__device__ float d_RgT[(size_t)NH_ * HS_ * 512];
// bf16 GEMM operands
__device__ __nv_bfloat16 d_xn2h[BT_ * (size_t)E_];
__device__ __nv_bfloat16 d_hnh [BT_ * (size_t)H_];
__device__ __nv_bfloat16 d_uh  [BT_ * (size_t)H_];
// pair-packed bf16 weights: [K/2][N] words, word = (w[2k][n] lo, w[2k+1][n] hi)
__device__ uint32_t d_Wgp  [(size_t)512 * G4_];
__device__ uint32_t d_uplp [(size_t)512 * H_];
__device__ uint32_t d_uprp [(size_t)512 * H_];
__device__ uint32_t d_downp[(size_t)512 * E_];

// ---------------- helpers ----------------
__device__ __forceinline__ float gelu_exact(float x) {
    return 0.5f * x * (1.0f + erff(x * 0.70710678118654752440f));
}
__device__ __forceinline__ float sigmoidf_(float x) {
    return 1.0f / (1.0f + expf(-x));
}
__device__ __forceinline__ void cp_async16(uint32_t saddr, const void* g) {
    asm volatile("cp.async.cg.shared.global [%0], [%1], 16;" :: "r"(saddr), "l"(g));
}

// block-wide (256 threads) sum reduce of two values
__device__ __forceinline__ void block_reduce_2(float& s, float& ss) {
    __shared__ float sh[16];
    int lane = threadIdx.x & 31, w = threadIdx.x >> 5;
    #pragma unroll
    for (int o = 16; o; o >>= 1) {
        s  += __shfl_down_sync(0xffffffffu, s,  o);
        ss += __shfl_down_sync(0xffffffffu, ss, o);
    }
    if (!lane) { sh[w] = s; sh[8 + w] = ss; }
    __syncthreads();
    if (threadIdx.x == 0) {
        float a = 0.f, b = 0.f;
        #pragma unroll
        for (int i = 0; i < 8; i++) { a += sh[i]; b += sh[8 + i]; }
        sh[0] = a; sh[8] = b;
    }
    __syncthreads();
    s = sh[0]; ss = sh[8];
}

// ---------------- LayerNorm over rows of 1024 -> fp32 ----------------
__global__ __launch_bounds__(256) void ln_rows(const float* __restrict__ in,
                                               float* __restrict__ out,
                                               const float* __restrict__ gw,
                                               const float* __restrict__ bw) {
    size_t row = blockIdx.x;
    const float* x = in + row * 1024;
    int t4 = threadIdx.x * 4;
    float4 v = *reinterpret_cast<const float4*>(x + t4);
    float s  = v.x + v.y + v.z + v.w;
    float ss = v.x*v.x + v.y*v.y + v.z*v.z + v.w*v.w;
    block_reduce_2(s, ss);
    float mu  = s * (1.0f / 1024.0f);
    float var = ss * (1.0f / 1024.0f) - mu * mu;
    float rstd = rsqrtf(var + 1e-5f);
    float4 g = *reinterpret_cast<const float4*>(gw + t4);
    float4 b = *reinterpret_cast<const float4*>(bw + t4);
    float4 o;
    o.x = (v.x - mu) * rstd * g.x + b.x;
    o.y = (v.y - mu) * rstd * g.y + b.y;
    o.z = (v.z - mu) * rstd * g.z + b.z;
    o.w = (v.w - mu) * rstd * g.w + b.w;
    *reinterpret_cast<float4*>(out + row * 1024 + t4) = o;
}

// ---------------- LayerNorm over rows of 1024 -> bf16 (GEMM operand) ----------------
__global__ __launch_bounds__(256) void ln_rows_bf16(const float* __restrict__ in,
                                                    __nv_bfloat16* __restrict__ out,
                                                    const float* __restrict__ gw,
                                                    const float* __restrict__ bw) {
    size_t row = blockIdx.x;
    const float* x = in + row * 1024;
    int t4 = threadIdx.x * 4;
    float4 v = *reinterpret_cast<const float4*>(x + t4);
    float s  = v.x + v.y + v.z + v.w;
    float ss = v.x*v.x + v.y*v.y + v.z*v.z + v.w*v.w;
    block_reduce_2(s, ss);
    float mu  = s * (1.0f / 1024.0f);
    float var = ss * (1.0f / 1024.0f) - mu * mu;
    float rstd = rsqrtf(var + 1e-5f);
    float4 g = *reinterpret_cast<const float4*>(gw + t4);
    float4 b = *reinterpret_cast<const float4*>(bw + t4);
    __nv_bfloat162 h0 = __floats2bfloat162_rn((v.x - mu) * rstd * g.x + b.x,
                                              (v.y - mu) * rstd * g.y + b.y);
    __nv_bfloat162 h1 = __floats2bfloat162_rn((v.z - mu) * rstd * g.z + b.z,
                                              (v.w - mu) * rstd * g.w + b.w);
    uint2 pk = make_uint2(*reinterpret_cast<uint32_t*>(&h0),
                          *reinterpret_cast<uint32_t*>(&h1));
    *reinterpret_cast<uint2*>(out + row * 1024 + t4) = pk;
}

// ---------------- gelu then LayerNorm, in-place rows of 1024 ----------------
__global__ __launch_bounds__(256) void gelu_ln_rows(float* __restrict__ data,
                                                    const float* __restrict__ gw,
                                                    const float* __restrict__ bw) {
    size_t row = blockIdx.x;
    float* x = data + row * 1024;
    int t4 = threadIdx.x * 4;
    float4 v = *reinterpret_cast<const float4*>(x + t4);
    v.x = gelu_exact(v.x); v.y = gelu_exact(v.y);
    v.z = gelu_exact(v.z); v.w = gelu_exact(v.w);
    float s  = v.x + v.y + v.z + v.w;
    float ss = v.x*v.x + v.y*v.y + v.z*v.z + v.w*v.w;
    block_reduce_2(s, ss);
    float mu  = s * (1.0f / 1024.0f);
    float var = ss * (1.0f / 1024.0f) - mu * mu;
    float rstd = rsqrtf(var + 1e-5f);
    float4 g = *reinterpret_cast<const float4*>(gw + t4);
    float4 b = *reinterpret_cast<const float4*>(bw + t4);
    float4 o;
    o.x = (v.x - mu) * rstd * g.x + b.x;
    o.y = (v.y - mu) * rstd * g.y + b.y;
    o.z = (v.z - mu) * rstd * g.z + b.z;
    o.w = (v.w - mu) * rstd * g.w + b.w;
    *reinterpret_cast<float4*>(x + t4) = o;
}

// ---------------- GroupNorm -> bf16 (GEMM operand) ----------------
__global__ __launch_bounds__(256) void groupnorm2(const float* __restrict__ gng,
                                                  const float* __restrict__ gnb) {
    size_t row = blockIdx.x;
    int head = threadIdx.x >> 5, lane = threadIdx.x & 31;
    const float* x = d_h + row * 1024 + head * 128;
    float s = 0.f, ss = 0.f;
    for (int j = lane; j < 128; j += 32) {
        float v = x[j];
        s += v; ss += v * v;
    }
    #pragma unroll
    for (int o = 16; o; o >>= 1) {
        s  += __shfl_xor_sync(0xffffffffu, s,  o);
        ss += __shfl_xor_sync(0xffffffffu, ss, o);
    }
    float mu  = s * (1.0f / 128.0f);
    float var = ss * (1.0f / 128.0f) - mu * mu;
    float rstd = rsqrtf(var + 1e-5f);
    for (int j = lane; j < 128; j += 32) {
        int ch = head * 128 + j;
        d_hnh[row * 1024 + ch] =
            __float2bfloat16_rn((x[j] - mu) * rstd * gng[ch] + gnb[ch]);
    }
}

// ---------------- weight pair-pack: out[kp][n] = half2(w[2kp][n], w[2kp+1][n]) ----------------
__global__ void pack_w(const float* __restrict__ w, uint32_t* __restrict__ out, int N) {
    int n = blockIdx.x * 256 + threadIdx.x;
    int kp = blockIdx.y;
    __nv_bfloat162 h = __floats2bfloat162_rn(w[(size_t)(2 * kp) * N + n],
                                             w[(size_t)(2 * kp + 1) * N + n]);
    out[(size_t)kp * N + n] = *reinterpret_cast<uint32_t*>(&h);
}

// ---------------- fc1 conv only (12->12, k=3, same): xn -> xc ----------------
__global__ __launch_bounds__(128) void fc1_conv(const float* __restrict__ w1,
                                                const float* __restrict__ b1) {
    __shared__ float sx[12][130];
    __shared__ float sw1[12 * 12 * 3];
    __shared__ float sb1[12];
    int b = blockIdx.y, l0 = blockIdx.x * 128, tid = threadIdx.x;
    for (int i = tid; i < 12 * 130; i += 128) {
        int c = i / 130, j = i % 130, l = l0 + j - 1;
        sx[c][j] = (l >= 0 && l < 1024) ? d_xn[(size_t)(b * 12 + c) * 1024 + l] : 0.f;
    }
    for (int i = tid; i < 432; i += 128) sw1[i] = w1[i];
    if (tid < 12) sb1[tid] = b1[tid];
    __syncthreads();
    int l = l0 + tid;
    #pragma unroll
    for (int o = 0; o < 12; o++) {
        float a = sb1[o];
        #pragma unroll
        for (int c = 0; c < 12; c++) {
            const float* wp = &sw1[(o * 12 + c) * 3];
            a += wp[0] * sx[c][tid] + wp[1] * sx[c][tid + 1] + wp[2] * sx[c][tid + 2];
        }
        d_xc[(size_t)(b * 12 + o) * 1024 + l] = a;
    }
}

// ---------------- fc2 (1x1) ----------------
__global__ __launch_bounds__(256) void fc2_1x1(const float* __restrict__ w2,
                                               const float* __restrict__ b2) {
    __shared__ float sw2[144], sb2[12];
    int b = blockIdx.y, l = blockIdx.x * 256 + threadIdx.x;
    if (threadIdx.x < 144) sw2[threadIdx.x] = w2[threadIdx.x];
    if (threadIdx.x < 12) sb2[threadIdx.x] = b2[threadIdx.x];
    __syncthreads();
    float xv[12];
    #pragma unroll
    for (int c = 0; c < 12; c++) xv[c] = d_xc[(size_t)(b * 12 + c) * 1024 + l];
    #pragma unroll
    for (int o = 0; o < 12; o++) {
        float a = sb2[o];
        #pragma unroll
        for (int c = 0; c < 12; c++) a += sw2[o * 12 + c] * xv[c];
        d_x1[(size_t)(b * 12 + o) * 1024 + l] = a;
    }
}

// ---------------- conv1: 12 -> 48 ----------------
__global__ __launch_bounds__(128) void conv12_48(const float* __restrict__ w,
                                                 const float* __restrict__ bb) {
    __shared__ float sx[12][130];
    __shared__ float sw[48 * 12 * 3];
    __shared__ float sb[48];
    int b = blockIdx.y, l0 = blockIdx.x * 128, tid = threadIdx.x;
    for (int i = tid; i < 12 * 130; i += 128) {
        int c = i / 130, j = i % 130, l = l0 + j - 1;
        sx[c][j] = (l >= 0 && l < 1024) ? d_y[(size_t)(b * 12 + c) * 1024 + l] : 0.f;
    }
    for (int i = tid; i < 1728; i += 128) sw[i] = w[i];
    if (tid < 48) sb[tid] = bb[tid];
    __syncthreads();
    float acc[48];
    #pragma unroll
    for (int o = 0; o < 48; o++) acc[o] = sb[o];
    #pragma unroll
    for (int c = 0; c < 12; c++) {
        float x0 = sx[c][tid], x1 = sx[c][tid + 1], x2 = sx[c][tid + 2];
        #pragma unroll
        for (int o = 0; o < 48; o++) {
            const float* wp = &sw[(o * 12 + c) * 3];
            acc[o] += wp[0] * x0 + wp[1] * x1 + wp[2] * x2;
        }
    }
    int l = l0 + tid;
    #pragma unroll
    for (int o = 0; o < 48; o++) d_z48[(size_t)(b * 48 + o) * 1024 + l] = acc[o];
}

// ---------------- conv2: 48 -> 12; + skip -> out ----------------
__global__ __launch_bounds__(128) void conv48_12(const float* __restrict__ w,
                                                 const float* __restrict__ bb,
                                                 float* __restrict__ out) {
    __shared__ float sx[48][130];
    __shared__ float sw[12 * 48 * 3];
    __shared__ float sb[12];
    int b = blockIdx.y, l0 = blockIdx.x * 128, tid = threadIdx.x;
    for (int i = tid; i < 48 * 130; i += 128) {
        int c = i / 130, j = i % 130, l = l0 + j - 1;
        sx[c][j] = (l >= 0 && l < 1024) ? d_z48[(size_t)(b * 48 + c) * 1024 + l] : 0.f;
    }
    for (int i = tid; i < 1728; i += 128) sw[i] = w[i];
    if (tid < 12) sb[tid] = bb[tid];
    __syncthreads();
    float acc[12];
    #pragma unroll
    for (int o = 0; o < 12; o++) acc[o] = sb[o];
    #pragma unroll
    for (int c = 0; c < 48; c++) {
        float x0 = sx[c][tid], x1 = sx[c][tid + 1], x2 = sx[c][tid + 2];
        #pragma unroll
        for (int o = 0; o < 12; o++) {
            const float* wp = &sw[(o * 48 + c) * 3];
            acc[o] += wp[0] * x0 + wp[1] * x1 + wp[2] * x2;
        }
    }
    int l = l0 + tid;
    #pragma unroll
    for (int o = 0; o < 12; o++) {
        size_t idx = (size_t)(b * 12 + o) * 1024 + l;
        out[idx] = acc[o] + d_xn[idx];
    }
}

// ---------------- bf16 tensor-core GEMM: mma.m16n8k16, cp.async 2-stage ----------------
// C[M,N] = A[M,K] @ B[K,N] + bias; A bf16 [M][K], B pair-packed words [K/2][N].
// Block 128x128, BK=32. 8 warps (2x4), warp tile 64x32.
// MODE 0: C(fp32) = acc + bias
// MODE 1: C(bf16) = gelu(aux0) * (acc + bias)
// MODE 2: C(fp32) = silu(aux0) * (acc + bias + aux1) + aux2
template<int MODE>
__global__ __launch_bounds__(256) void gemm_bf16(int N, int K,
                                                 const __nv_bfloat16* __restrict__ A,
                                                 const uint32_t* __restrict__ Bp,
                                                 const float* __restrict__ bias,
                                                 const float* __restrict__ aux0,
                                                 const float* __restrict__ aux1,
                                                 const float* __restrict__ aux2,
                                                 void* __restrict__ Cout) {
    __shared__ uint32_t As[2][128 * 20];   // [r][20 words = 40 halves]; banks 20g+tg distinct
    __shared__ uint32_t Bs[2][16 * 136];   // [kp][136 words]; banks 8tg+g distinct
    int tid = threadIdx.x;
    int warp = tid >> 5, lane = tid & 31;
    int g = lane >> 2, tg = lane & 3;
    int warpM = warp >> 2, warpN = warp & 3;
    int row0 = blockIdx.y * 128, col0 = blockIdx.x * 128;

    uint32_t asb = (uint32_t)__cvta_generic_to_shared(&As[0][0]);
    uint32_t bsb = (uint32_t)__cvta_generic_to_shared(&Bs[0][0]);

    float acc[4][4][4];
    #pragma unroll
    for (int m = 0; m < 4; m++)
        #pragma unroll
        for (int n = 0; n < 4; n++)
            #pragma unroll
            for (int q = 0; q < 4; q++) acc[m][n][q] = 0.f;

    const int nt = K >> 5;      // K/32 tiles

    auto load_tile = [&](int it, int buf) {
        int k0 = it << 5;       // halves
        int kp0 = it << 4;      // pair rows
        #pragma unroll
        for (int i = 0; i < 2; i++) {
            int e = i * 256 + tid;
            int r = e >> 2, ch = e & 3;   // 4 x 8-half chunks per row
            cp_async16(asb + (uint32_t)(buf * 128 * 20 + r * 20 + ch * 4) * 4,
                       A + (size_t)(row0 + r) * K + k0 + ch * 8);
        }
        #pragma unroll
        for (int i = 0; i < 2; i++) {
            int e = i * 256 + tid;
            int kp = e >> 5, c = (e & 31) * 4;
            cp_async16(bsb + (uint32_t)(buf * 16 * 136 + kp * 136 + c) * 4,
                       Bp + (size_t)(kp0 + kp) * N + col0 + c);
        }
        asm volatile("cp.async.commit_group;");
    };

    load_tile(0, 0);
    for (int it = 0; it < nt; it++) {
        int buf = it & 1;
        if (it + 1 < nt) {
            load_tile(it + 1, buf ^ 1);
            asm volatile("cp.async.wait_group 1;");
        } else {
            asm volatile("cp.async.wait_group 0;");
        }
        __syncthreads();
        const uint32_t* Ab = &As[buf][0];
        const uint32_t* Bb = &Bs[buf][0];
        #pragma unroll
        for (int s = 0; s < 2; s++) {           // two k16 steps per BK=32
            uint32_t af[4][4];
            #pragma unroll
            for (int m = 0; m < 4; m++) {
                int r = warpM * 64 + m * 16;
                af[m][0] = Ab[(r + g)     * 20 + s * 8 + tg];
                af[m][1] = Ab[(r + 8 + g) * 20 + s * 8 + tg];
                af[m][2] = Ab[(r + g)     * 20 + s * 8 + tg + 4];
                af[m][3] = Ab[(r + 8 + g) * 20 + s * 8 + tg + 4];
            }
            uint32_t bf[4][2];
            #pragma unroll
            for (int n = 0; n < 4; n++) {
                int c = warpN * 32 + n * 8 + g;
                bf[n][0] = Bb[(s * 8 + tg)     * 136 + c];
                bf[n][1] = Bb[(s * 8 + tg + 4) * 136 + c];
            }
            #pragma unroll
            for (int m = 0; m < 4; m++)
                #pragma unroll
                for (int n = 0; n < 4; n++) {
                    asm volatile(
                        "mma.sync.aligned.m16n8k16.row.col.f32.bf16.bf16.f32 "
                        "{%0,%1,%2,%3}, {%4,%5,%6,%7}, {%8,%9}, {%0,%1,%2,%3};"
                        : "+f"(acc[m][n][0]), "+f"(acc[m][n][1]),
                          "+f"(acc[m][n][2]), "+f"(acc[m][n][3])
                        : "r"(af[m][0]), "r"(af[m][1]), "r"(af[m][2]), "r"(af[m][3]),
                          "r"(bf[n][0]), "r"(bf[n][1]));
                }
        }
        __syncthreads();
    }

    // epilogue: c0:(g,2tg) c1:(g,2tg+1) c2:(g+8,2tg) c3:(g+8,2tg+1)
    #pragma unroll
    for (int m = 0; m < 4; m++) {
        int r = row0 + warpM * 64 + m * 16 + g;
        #pragma unroll
        for (int n = 0; n < 4; n++) {
            int c = col0 + warpN * 32 + n * 8 + 2 * tg;
            #pragma unroll
            for (int half = 0; half < 2; half++) {
                int rr = r + half * 8;
                size_t i0 = (size_t)rr * N + c;
                float v0 = acc[m][n][half * 2 + 0] + bias[c];
                float v1 = acc[m][n][half * 2 + 1] + bias[c + 1];
                if (MODE == 1) {
                    v0 = gelu_exact(aux0[i0])     * v0;
                    v1 = gelu_exact(aux0[i0 + 1]) * v1;
                    __nv_bfloat162 h = __floats2bfloat162_rn(v0, v1);
                    *reinterpret_cast<uint32_t*>((__nv_bfloat16*)Cout + i0) =
                        *reinterpret_cast<uint32_t*>(&h);
                } else {
                    if (MODE == 2) {
                        float x0 = aux0[i0], x1v = aux0[i0 + 1];
                        v0 = x0  * sigmoidf_(x0)  * (v0 + aux1[i0])     + aux2[i0];
                        v1 = x1v * sigmoidf_(x1v) * (v1 + aux1[i0 + 1]) + aux2[i0 + 1];
                    }
                    *reinterpret_cast<float2*>((float*)Cout + i0) = make_float2(v0, v1);
                }
            }
        }
    }
}

// ---------------- Rg transpose: RgT[n][hs][g] = Rg[n][g][hs] ----------------
__global__ void rg_transpose(const float* __restrict__ Rg) {
    __shared__ float tile[32][33];
    int n = blockIdx.x, g0 = blockIdx.y << 5, h0 = blockIdx.z << 5;
    int x = threadIdx.x, y = threadIdx.y;
    #pragma unroll
    for (int j = y; j < 32; j += 8)
        tile[j][x] = Rg[(size_t)(n * 512 + g0 + j) * 128 + h0 + x];
    __syncthreads();
    #pragma unroll
    for (int j = y; j < 32; j += 8)
        d_RgT[(size_t)(n * 128 + h0 + j) * 512 + g0 + x] = tile[x][j];
}

// ---------------- sLSTM recurrence (verified) ----------------
__global__ __launch_bounds__(256) void slstm_rec2() {
    __shared__ float sh_hT[128 * 17];
    __shared__ float sh_rec[16 * 512];
    int head = blockIdx.x >> 5;
    int b0 = (blockIdx.x & 31) << 4;
    int tid = threadIdx.x;
    for (int i = tid; i < 128 * 17; i += 256) sh_hT[i] = 0.f;
    float cS[8], nS[8], mS[8];
    #pragma unroll
    for (int j = 0; j < 8; j++) { cS[j] = 0.f; nS[j] = 0.f; mS[j] = 0.f; }
    __syncthreads();
    const float* RgTh = d_RgT + (size_t)head * (128 * 512);
    for (int t = 0; t < 12; t++) {
        float acc0[16], acc1[16];
        #pragma unroll
        for (int b = 0; b < 16; b++) { acc0[b] = 0.f; acc1[b] = 0.f; }
        #pragma unroll 4
        for (int h = 0; h < 128; h++) {
            float w0 = __ldg(RgTh + (size_t)h * 512 + tid);
            float w1 = __ldg(RgTh + (size_t)h * 512 + 256 + tid);
            #pragma unroll
            for (int b = 0; b < 16; b++) {
                float hv = sh_hT[h * 17 + b];
                acc0[b] = fmaf(hv, w0, acc0[b]);
                acc1[b] = fmaf(hv, w1, acc1[b]);
            }
        }
        #pragma unroll
        for (int b = 0; b < 16; b++) {
            sh_rec[b * 512 + tid]       = acc0[b];
            sh_rec[b * 512 + 256 + tid] = acc1[b];
        }
        __syncthreads();
        #pragma unroll
        for (int it = 0; it < 8; it++) {
            int idx = it * 256 + tid;
            int bb = idx >> 7, hs = idx & 127;
            int b = b0 + bb;
            const float* gxp = d_gx + (size_t)(b * 12 + t) * 4096 + head * 512;
            const float* rp = sh_rec + bb * 512;
            float z_ = gxp[hs]       + rp[hs];
            float i_ = gxp[128 + hs] + rp[128 + hs];
            float f_ = gxp[256 + hs] + rp[256 + hs];
            float o_ = gxp[384 + hs] + rp[384 + hs];
            float z  = tanhf(z_);
            float o  = sigmoidf_(o_);
            float mo = mS[it];
            float mn = fmaxf(f_ + mo, i_);
            float iv = expf(i_ - mn);
            float fv = expf(f_ + mo - mn);
            float cv = fv * cS[it] + iv * z;
            float nv = fv * nS[it] + iv;
            float hv = o * (cv / nv);
            cS[it] = cv; nS[it] = nv; mS[it] = mn;
            sh_hT[hs * 17 + bb] = hv;
            d_h[(size_t)((b * 12 + t) * 8 + head) * 128 + hs] = hv;
        }
        __syncthreads();
    }
}

// ---------------- launch ----------------
extern "C" void kernel_launch(void* const* d_in, const int* in_sizes, int n_in,
                              void* d_out, int out_size) {
    const float* x       = (const float*)d_in[0];
    const float* ln_g    = (const float*)d_in[1];
    const float* ln_b    = (const float*)d_in[2];
    const float* fc1_w   = (const float*)d_in[3];
    const float* fc1_b   = (const float*)d_in[4];
    const float* fc2_w   = (const float*)d_in[5];
    const float* fc2_b   = (const float*)d_in[6];
    const float* conv1_w = (const float*)d_in[7];
    const float* conv1_b = (const float*)d_in[8];
    const float* conv2_w = (const float*)d_in[9];
    const float* conv2_b = (const float*)d_in[10];
    const float* xlg     = (const float*)d_in[11];
    const float* xlb     = (const float*)d_in[12];
    const float* Wg      = (const float*)d_in[13];
    const float* bg      = (const float*)d_in[14];
    const float* Rg      = (const float*)d_in[15];
    const float* gng     = (const float*)d_in[16];
    const float* gnb     = (const float*)d_in[17];
    const float* uplw    = (const float*)d_in[18];
    const float* uplb    = (const float*)d_in[19];
    const float* uprw    = (const float*)d_in[20];
    const float* uprb    = (const float*)d_in[21];
    const float* downw   = (const float*)d_in[22];
    const float* downb   = (const float*)d_in[23];
    float* out = (float*)d_out;

    float *p_xn, *p_xc, *p_x1, *p_gx, *p_left, *p_y, *p_z48;
    __nv_bfloat16 *p_xn2h, *p_hnh, *p_uh;
    uint32_t *p_Wgp, *p_uplp, *p_uprp, *p_downp;
    cudaGetSymbolAddress((void**)&p_xn,   d_xn);
    cudaGetSymbolAddress((void**)&p_xc,   d_xc);
    cudaGetSymbolAddress((void**)&p_x1,   d_x1);
    cudaGetSymbolAddress((void**)&p_gx,   d_gx);
    cudaGetSymbolAddress((void**)&p_left, d_left);
    cudaGetSymbolAddress((void**)&p_y,    d_y);
    cudaGetSymbolAddress((void**)&p_z48,  d_z48);
    cudaGetSymbolAddress((void**)&p_xn2h, d_xn2h);
    cudaGetSymbolAddress((void**)&p_hnh,  d_hnh);
    cudaGetSymbolAddress((void**)&p_uh,   d_uh);
    cudaGetSymbolAddress((void**)&p_Wgp,  d_Wgp);
    cudaGetSymbolAddress((void**)&p_uplp, d_uplp);
    cudaGetSymbolAddress((void**)&p_uprp, d_uprp);
    cudaGetSymbolAddress((void**)&p_downp, d_downp);

    // one-time per launch: weight packs + Rg transpose
    pack_w<<<dim3(16, 512), 256>>>(Wg,    p_Wgp,   4096);
    pack_w<<<dim3(4, 512),  256>>>(uplw,  p_uplp,  1024);
    pack_w<<<dim3(4, 512),  256>>>(uprw,  p_uprp,  1024);
    pack_w<<<dim3(4, 512),  256>>>(downw, p_downp, 1024);
    rg_transpose<<<dim3(8, 16, 4), dim3(32, 8)>>>(Rg);

    // xn = LN(x); skip = xn
    ln_rows<<<BT_, 256>>>(x, p_xn, ln_g, ln_b);
    // xc = conv1d(xn, fc1)
    fc1_conv<<<dim3(8, B_), 128>>>(fc1_w, fc1_b);
    // x1 = fc2(xc)
    fc2_1x1<<<dim3(4, B_), 256>>>(fc2_w, fc2_b);
    // xn2 = LN(x1) -> bf16 (GEMM operand only)
    ln_rows_bf16<<<BT_, 256>>>(p_x1, p_xn2h, xlg, xlb);
    // gx = xn2 @ Wg + bg  [bf16 mma]
    gemm_bf16<0><<<dim3(32, 48), 256>>>(4096, 1024, p_xn2h, p_Wgp, bg,
                                        nullptr, nullptr, nullptr, p_gx);
    // sLSTM recurrence -> d_h
    slstm_rec2<<<256, 256>>>();
    // per-head GroupNorm -> bf16 hn
    groupnorm2<<<BT_, 256>>>(gng, gnb);
    // left = hn @ upl + uplb  (fp32; consumed by MODE1 epilogue)
    gemm_bf16<0><<<dim3(8, 48), 256>>>(1024, 1024, p_hnh, p_uplp, uplb,
                                       nullptr, nullptr, nullptr, p_left);
    // u = gelu(left) * (hn @ upr + uprb)  -> bf16
    gemm_bf16<1><<<dim3(8, 48), 256>>>(1024, 1024, p_hnh, p_uprp, uprb,
                                       p_left, nullptr, nullptr, p_uh);
    // y = silu(xc) * (u @ down + downb + x1) + xn
    gemm_bf16<2><<<dim3(8, 48), 256>>>(1024, 1024, p_uh, p_downp, downb,
                                       p_xc, p_x1, p_xn, p_y);
    // z48 = conv1d(y, 12->48)
    conv12_48<<<dim3(8, B_), 128>>>(conv1_w, conv1_b);
    // z48 = LN(gelu(z48))
    gelu_ln_rows<<<ROWS48_, 256>>>(p_z48, ln_g, ln_b);
    // out = conv1d(z48, 48->12) + skip
    conv48_12<<<dim3(8, B_), 128>>>(conv2_w, conv2_b, out);
}

// round 9
// speedup vs baseline: 3.3000x; 1.0985x over previous
#include <cuda_runtime.h>
#include <cuda_bf16.h>
#include <cmath>
#include <cstdint>

// ---------------- problem constants ----------------
static constexpr int B_   = 512;
static constexpr int T_   = 12;
static constexpr int E_   = 1024;
static constexpr int NH_  = 8;
static constexpr int HS_  = 128;
static constexpr int H_   = 1024;
static constexpr int G4_  = 4096;
static constexpr int BT_  = B_ * T_;        // 6144
static constexpr int ROWS48_ = B_ * 48;     // 24576

// ---------------- scratch (device globals; no allocation) ----------------
__device__ float d_xn [BT_ * (size_t)E_];
__device__ float d_xc [BT_ * (size_t)E_];
__device__ float d_x1 [BT_ * (size_t)E_];
__device__ float d_gx [BT_ * (size_t)G4_];
__device__ float d_h  [BT_ * (size_t)H_];
__device__ float d_y  [BT_ * (size_t)E_];
__device__ float d_z48[(size_t)B_ * 48 * E_];
// bf16 GEMM operands
__device__ __nv_bfloat16 d_xn2h[BT_ * (size_t)E_];
__device__ __nv_bfloat16 d_hnh [BT_ * (size_t)H_];
__device__ __nv_bfloat16 d_uh  [BT_ * (size_t)H_];
// pair-packed bf16 weights: word = (w[2k][n] lo, w[2k+1][n] hi)
__device__ uint32_t d_Wgp  [(size_t)512 * G4_];
__device__ uint32_t d_downp[(size_t)512 * E_];
__device__ uint32_t d_Wpair[(size_t)512 * 2048];   // interleaved upl/upr
__device__ uint32_t d_Rgp  [(size_t)NH_ * 64 * 512]; // [head][kp][g]

// ---------------- helpers ----------------
__device__ __forceinline__ float gelu_exact(float x) {
    return 0.5f * x * (1.0f + erff(x * 0.70710678118654752440f));
}
__device__ __forceinline__ float sigmoidf_(float x) {
    return 1.0f / (1.0f + expf(-x));
}
__device__ __forceinline__ void cp_async16(uint32_t saddr, const void* g) {
    asm volatile("cp.async.cg.shared.global [%0], [%1], 16;" :: "r"(saddr), "l"(g));
}
__device__ __forceinline__ void mma_bf16(float* acc, uint32_t a0, uint32_t a1,
                                         uint32_t a2, uint32_t a3,
                                         uint32_t b0, uint32_t b1) {
    asm volatile(
        "mma.sync.aligned.m16n8k16.row.col.f32.bf16.bf16.f32 "
        "{%0,%1,%2,%3}, {%4,%5,%6,%7}, {%8,%9}, {%0,%1,%2,%3};"
        : "+f"(acc[0]), "+f"(acc[1]), "+f"(acc[2]), "+f"(acc[3])
        : "r"(a0), "r"(a1), "r"(a2), "r"(a3), "r"(b0), "r"(b1));
}

// block-wide (256 threads) sum reduce of two values
__device__ __forceinline__ void block_reduce_2(float& s, float& ss) {
    __shared__ float sh[16];
    int lane = threadIdx.x & 31, w = threadIdx.x >> 5;
    #pragma unroll
    for (int o = 16; o; o >>= 1) {
        s  += __shfl_down_sync(0xffffffffu, s,  o);
        ss += __shfl_down_sync(0xffffffffu, ss, o);
    }
    if (!lane) { sh[w] = s; sh[8 + w] = ss; }
    __syncthreads();
    if (threadIdx.x == 0) {
        float a = 0.f, b = 0.f;
        #pragma unroll
        for (int i = 0; i < 8; i++) { a += sh[i]; b += sh[8 + i]; }
        sh[0] = a; sh[8] = b;
    }
    __syncthreads();
    s = sh[0]; ss = sh[8];
}

// ---------------- LayerNorm over rows of 1024 -> fp32 ----------------
__global__ __launch_bounds__(256) void ln_rows(const float* __restrict__ in,
                                               float* __restrict__ out,
                                               const float* __restrict__ gw,
                                               const float* __restrict__ bw) {
    size_t row = blockIdx.x;
    const float* x = in + row * 1024;
    int t4 = threadIdx.x * 4;
    float4 v = *reinterpret_cast<const float4*>(x + t4);
    float s  = v.x + v.y + v.z + v.w;
    float ss = v.x*v.x + v.y*v.y + v.z*v.z + v.w*v.w;
    block_reduce_2(s, ss);
    float mu  = s * (1.0f / 1024.0f);
    float var = ss * (1.0f / 1024.0f) - mu * mu;
    float rstd = rsqrtf(var + 1e-5f);
    float4 g = *reinterpret_cast<const float4*>(gw + t4);
    float4 b = *reinterpret_cast<const float4*>(bw + t4);
    float4 o;
    o.x = (v.x - mu) * rstd * g.x + b.x;
    o.y = (v.y - mu) * rstd * g.y + b.y;
    o.z = (v.z - mu) * rstd * g.z + b.z;
    o.w = (v.w - mu) * rstd * g.w + b.w;
    *reinterpret_cast<float4*>(out + row * 1024 + t4) = o;
}

// ---------------- LayerNorm over rows of 1024 -> bf16 ----------------
__global__ __launch_bounds__(256) void ln_rows_bf16(const float* __restrict__ in,
                                                    __nv_bfloat16* __restrict__ out,
                                                    const float* __restrict__ gw,
                                                    const float* __restrict__ bw) {
    size_t row = blockIdx.x;
    const float* x = in + row * 1024;
    int t4 = threadIdx.x * 4;
    float4 v = *reinterpret_cast<const float4*>(x + t4);
    float s  = v.x + v.y + v.z + v.w;
    float ss = v.x*v.x + v.y*v.y + v.z*v.z + v.w*v.w;
    block_reduce_2(s, ss);
    float mu  = s * (1.0f / 1024.0f);
    float var = ss * (1.0f / 1024.0f) - mu * mu;
    float rstd = rsqrtf(var + 1e-5f);
    float4 g = *reinterpret_cast<const float4*>(gw + t4);
    float4 b = *reinterpret_cast<const float4*>(bw + t4);
    __nv_bfloat162 h0 = __floats2bfloat162_rn((v.x - mu) * rstd * g.x + b.x,
                                              (v.y - mu) * rstd * g.y + b.y);
    __nv_bfloat162 h1 = __floats2bfloat162_rn((v.z - mu) * rstd * g.z + b.z,
                                              (v.w - mu) * rstd * g.w + b.w);
    uint2 pk = make_uint2(*reinterpret_cast<uint32_t*>(&h0),
                          *reinterpret_cast<uint32_t*>(&h1));
    *reinterpret_cast<uint2*>(out + row * 1024 + t4) = pk;
}

// ---------------- gelu then LayerNorm, in-place rows of 1024 ----------------
__global__ __launch_bounds__(256) void gelu_ln_rows(float* __restrict__ data,
                                                    const float* __restrict__ gw,
                                                    const float* __restrict__ bw) {
    size_t row = blockIdx.x;
    float* x = data + row * 1024;
    int t4 = threadIdx.x * 4;
    float4 v = *reinterpret_cast<const float4*>(x + t4);
    v.x = gelu_exact(v.x); v.y = gelu_exact(v.y);
    v.z = gelu_exact(v.z); v.w = gelu_exact(v.w);
    float s  = v.x + v.y + v.z + v.w;
    float ss = v.x*v.x + v.y*v.y + v.z*v.z + v.w*v.w;
    block_reduce_2(s, ss);
    float mu  = s * (1.0f / 1024.0f);
    float var = ss * (1.0f / 1024.0f) - mu * mu;
    float rstd = rsqrtf(var + 1e-5f);
    float4 g = *reinterpret_cast<const float4*>(gw + t4);
    float4 b = *reinterpret_cast<const float4*>(bw + t4);
    float4 o;
    o.x = (v.x - mu) * rstd * g.x + b.x;
    o.y = (v.y - mu) * rstd * g.y + b.y;
    o.z = (v.z - mu) * rstd * g.z + b.z;
    o.w = (v.w - mu) * rstd * g.w + b.w;
    *reinterpret_cast<float4*>(x + t4) = o;
}

// ---------------- GroupNorm -> bf16 ----------------
__global__ __launch_bounds__(256) void groupnorm2(const float* __restrict__ gng,
                                                  const float* __restrict__ gnb) {
    size_t row = blockIdx.x;
    int head = threadIdx.x >> 5, lane = threadIdx.x & 31;
    const float* x = d_h + row * 1024 + head * 128;
    float s = 0.f, ss = 0.f;
    for (int j = lane; j < 128; j += 32) {
        float v = x[j];
        s += v; ss += v * v;
    }
    #pragma unroll
    for (int o = 16; o; o >>= 1) {
        s  += __shfl_xor_sync(0xffffffffu, s,  o);
        ss += __shfl_xor_sync(0xffffffffu, ss, o);
    }
    float mu  = s * (1.0f / 128.0f);
    float var = ss * (1.0f / 128.0f) - mu * mu;
    float rstd = rsqrtf(var + 1e-5f);
    for (int j = lane; j < 128; j += 32) {
        int ch = head * 128 + j;
        d_hnh[row * 1024 + ch] =
            __float2bfloat16_rn((x[j] - mu) * rstd * gng[ch] + gnb[ch]);
    }
}

// ---------------- weight pair-pack ----------------
__global__ void pack_w(const float* __restrict__ w, uint32_t* __restrict__ out, int N) {
    int n = blockIdx.x * 256 + threadIdx.x;
    int kp = blockIdx.y;
    __nv_bfloat162 h = __floats2bfloat162_rn(w[(size_t)(2 * kp) * N + n],
                                             w[(size_t)(2 * kp + 1) * N + n]);
    out[(size_t)kp * N + n] = *reinterpret_cast<uint32_t*>(&h);
}

// ---------------- interleaved pack: col 2j = upl_j, col 2j+1 = upr_j ----------------
__global__ void pack_w_pair(const float* __restrict__ wl, const float* __restrict__ wr,
                            uint32_t* __restrict__ out) {
    int n = blockIdx.x * 256 + threadIdx.x;   // 0..1023
    int kp = blockIdx.y;                      // 0..511
    __nv_bfloat162 hl = __floats2bfloat162_rn(wl[(size_t)(2 * kp) * 1024 + n],
                                              wl[(size_t)(2 * kp + 1) * 1024 + n]);
    __nv_bfloat162 hr = __floats2bfloat162_rn(wr[(size_t)(2 * kp) * 1024 + n],
                                              wr[(size_t)(2 * kp + 1) * 1024 + n]);
    out[(size_t)kp * 2048 + 2 * n]     = *reinterpret_cast<uint32_t*>(&hl);
    out[(size_t)kp * 2048 + 2 * n + 1] = *reinterpret_cast<uint32_t*>(&hr);
}

// ---------------- pack Rg: d_Rgp[head][kp][g] = bf16x2(Rg[head][g][2kp], [2kp+1]) ----------------
__global__ __launch_bounds__(256) void pack_rg(const float* __restrict__ Rg) {
    __shared__ float tile[32][129];
    int head = blockIdx.x;
    int g0 = blockIdx.y * 32;
    int tid = threadIdx.x;
    #pragma unroll
    for (int i = 0; i < 16; i++) {
        int e = i * 256 + tid;
        int r = e >> 7, c = e & 127;
        tile[r][c] = Rg[((size_t)(head * 512 + g0 + r)) * 128 + c];
    }
    __syncthreads();
    #pragma unroll
    for (int i = 0; i < 8; i++) {
        int e = i * 256 + tid;       // 0..2047
        int kp = e >> 5, gl = e & 31;
        __nv_bfloat162 h = __floats2bfloat162_rn(tile[gl][2 * kp], tile[gl][2 * kp + 1]);
        d_Rgp[((size_t)(head * 64 + kp)) * 512 + g0 + gl] =
            *reinterpret_cast<uint32_t*>(&h);
    }
}

// ---------------- fc1 conv only (12->12, k=3, same): xn -> xc ----------------
__global__ __launch_bounds__(128) void fc1_conv(const float* __restrict__ w1,
                                                const float* __restrict__ b1) {
    __shared__ float sx[12][130];
    __shared__ float sw1[12 * 12 * 3];
    __shared__ float sb1[12];
    int b = blockIdx.y, l0 = blockIdx.x * 128, tid = threadIdx.x;
    for (int i = tid; i < 12 * 130; i += 128) {
        int c = i / 130, j = i % 130, l = l0 + j - 1;
        sx[c][j] = (l >= 0 && l < 1024) ? d_xn[(size_t)(b * 12 + c) * 1024 + l] : 0.f;
    }
    for (int i = tid; i < 432; i += 128) sw1[i] = w1[i];
    if (tid < 12) sb1[tid] = b1[tid];
    __syncthreads();
    int l = l0 + tid;
    #pragma unroll
    for (int o = 0; o < 12; o++) {
        float a = sb1[o];
        #pragma unroll
        for (int c = 0; c < 12; c++) {
            const float* wp = &sw1[(o * 12 + c) * 3];
            a += wp[0] * sx[c][tid] + wp[1] * sx[c][tid + 1] + wp[2] * sx[c][tid + 2];
        }
        d_xc[(size_t)(b * 12 + o) * 1024 + l] = a;
    }
}

// ---------------- fc2 (1x1) ----------------
__global__ __launch_bounds__(256) void fc2_1x1(const float* __restrict__ w2,
                                               const float* __restrict__ b2) {
    __shared__ float sw2[144], sb2[12];
    int b = blockIdx.y, l = blockIdx.x * 256 + threadIdx.x;
    if (threadIdx.x < 144) sw2[threadIdx.x] = w2[threadIdx.x];
    if (threadIdx.x < 12) sb2[threadIdx.x] = b2[threadIdx.x];
    __syncthreads();
    float xv[12];
    #pragma unroll
    for (int c = 0; c < 12; c++) xv[c] = d_xc[(size_t)(b * 12 + c) * 1024 + l];
    #pragma unroll
    for (int o = 0; o < 12; o++) {
        float a = sb2[o];
        #pragma unroll
        for (int c = 0; c < 12; c++) a += sw2[o * 12 + c] * xv[c];
        d_x1[(size_t)(b * 12 + o) * 1024 + l] = a;
    }
}

// ---------------- conv1: 12 -> 48 ----------------
__global__ __launch_bounds__(128) void conv12_48(const float* __restrict__ w,
                                                 const float* __restrict__ bb) {
    __shared__ float sx[12][130];
    __shared__ float sw[48 * 12 * 3];
    __shared__ float sb[48];
    int b = blockIdx.y, l0 = blockIdx.x * 128, tid = threadIdx.x;
    for (int i = tid; i < 12 * 130; i += 128) {
        int c = i / 130, j = i % 130, l = l0 + j - 1;
        sx[c][j] = (l >= 0 && l < 1024) ? d_y[(size_t)(b * 12 + c) * 1024 + l] : 0.f;
    }
    for (int i = tid; i < 1728; i += 128) sw[i] = w[i];
    if (tid < 48) sb[tid] = bb[tid];
    __syncthreads();
    float acc[48];
    #pragma unroll
    for (int o = 0; o < 48; o++) acc[o] = sb[o];
    #pragma unroll
    for (int c = 0; c < 12; c++) {
        float x0 = sx[c][tid], x1 = sx[c][tid + 1], x2 = sx[c][tid + 2];
        #pragma unroll
        for (int o = 0; o < 48; o++) {
            const float* wp = &sw[(o * 12 + c) * 3];
            acc[o] += wp[0] * x0 + wp[1] * x1 + wp[2] * x2;
        }
    }
    int l = l0 + tid;
    #pragma unroll
    for (int o = 0; o < 48; o++) d_z48[(size_t)(b * 48 + o) * 1024 + l] = acc[o];
}

// ---------------- conv2: 48 -> 12; + skip -> out ----------------
__global__ __launch_bounds__(128) void conv48_12(const float* __restrict__ w,
                                                 const float* __restrict__ bb,
                                                 float* __restrict__ out) {
    __shared__ float sx[48][130];
    __shared__ float sw[12 * 48 * 3];
    __shared__ float sb[12];
    int b = blockIdx.y, l0 = blockIdx.x * 128, tid = threadIdx.x;
    for (int i = tid; i < 48 * 130; i += 128) {
        int c = i / 130, j = i % 130, l = l0 + j - 1;
        sx[c][j] = (l >= 0 && l < 1024) ? d_z48[(size_t)(b * 48 + c) * 1024 + l] : 0.f;
    }
    for (int i = tid; i < 1728; i += 128) sw[i] = w[i];
    if (tid < 12) sb[tid] = bb[tid];
    __syncthreads();
    float acc[12];
    #pragma unroll
    for (int o = 0; o < 12; o++) acc[o] = sb[o];
    #pragma unroll
    for (int c = 0; c < 48; c++) {
        float x0 = sx[c][tid], x1 = sx[c][tid + 1], x2 = sx[c][tid + 2];
        #pragma unroll
        for (int o = 0; o < 12; o++) {
            const float* wp = &sw[(o * 48 + c) * 3];
            acc[o] += wp[0] * x0 + wp[1] * x1 + wp[2] * x2;
        }
    }
    int l = l0 + tid;
    #pragma unroll
    for (int o = 0; o < 12; o++) {
        size_t idx = (size_t)(b * 12 + o) * 1024 + l;
        out[idx] = acc[o] + d_xn[idx];
    }
}

// ---------------- bf16 tensor-core GEMM: mma.m16n8k16, cp.async 2-stage ----------------
// MODE 0: C(fp32) = acc + bias
// MODE 2: C(fp32) = silu(aux0) * (acc + bias + aux1) + aux2
// MODE 3: interleaved pair GEMM (N even cols = left, odd = right):
//         C(bf16)[r][c/2] = gelu(accL + bias[c/2]) * (accR + aux1b[c/2])
template<int MODE>
__global__ __launch_bounds__(256) void gemm_bf16(int N, int K,
                                                 const __nv_bfloat16* __restrict__ A,
                                                 const uint32_t* __restrict__ Bp,
                                                 const float* __restrict__ bias,
                                                 const float* __restrict__ aux0,
                                                 const float* __restrict__ aux1,
                                                 const float* __restrict__ aux2,
                                                 void* __restrict__ Cout) {
    __shared__ uint32_t As[2][128 * 20];
    __shared__ uint32_t Bs[2][16 * 136];
    int tid = threadIdx.x;
    int warp = tid >> 5, lane = tid & 31;
    int g = lane >> 2, tg = lane & 3;
    int warpM = warp >> 2, warpN = warp & 3;
    int row0 = blockIdx.y * 128, col0 = blockIdx.x * 128;

    uint32_t asb = (uint32_t)__cvta_generic_to_shared(&As[0][0]);
    uint32_t bsb = (uint32_t)__cvta_generic_to_shared(&Bs[0][0]);

    float acc[4][4][4];
    #pragma unroll
    for (int m = 0; m < 4; m++)
        #pragma unroll
        for (int n = 0; n < 4; n++)
            #pragma unroll
            for (int q = 0; q < 4; q++) acc[m][n][q] = 0.f;

    const int nt = K >> 5;

    auto load_tile = [&](int it, int buf) {
        int k0 = it << 5;
        int kp0 = it << 4;
        #pragma unroll
        for (int i = 0; i < 2; i++) {
            int e = i * 256 + tid;
            int r = e >> 2, ch = e & 3;
            cp_async16(asb + (uint32_t)(buf * 128 * 20 + r * 20 + ch * 4) * 4,
                       A + (size_t)(row0 + r) * K + k0 + ch * 8);
        }
        #pragma unroll
        for (int i = 0; i < 2; i++) {
            int e = i * 256 + tid;
            int kp = e >> 5, c = (e & 31) * 4;
            cp_async16(bsb + (uint32_t)(buf * 16 * 136 + kp * 136 + c) * 4,
                       Bp + (size_t)(kp0 + kp) * N + col0 + c);
        }
        asm volatile("cp.async.commit_group;");
    };

    load_tile(0, 0);
    for (int it = 0; it < nt; it++) {
        int buf = it & 1;
        if (it + 1 < nt) {
            load_tile(it + 1, buf ^ 1);
            asm volatile("cp.async.wait_group 1;");
        } else {
            asm volatile("cp.async.wait_group 0;");
        }
        __syncthreads();
        const uint32_t* Ab = &As[buf][0];
        const uint32_t* Bb = &Bs[buf][0];
        #pragma unroll
        for (int s = 0; s < 2; s++) {
            uint32_t af[4][4];
            #pragma unroll
            for (int m = 0; m < 4; m++) {
                int r = warpM * 64 + m * 16;
                af[m][0] = Ab[(r + g)     * 20 + s * 8 + tg];
                af[m][1] = Ab[(r + 8 + g) * 20 + s * 8 + tg];
                af[m][2] = Ab[(r + g)     * 20 + s * 8 + tg + 4];
                af[m][3] = Ab[(r + 8 + g) * 20 + s * 8 + tg + 4];
            }
            uint32_t bf[4][2];
            #pragma unroll
            for (int n = 0; n < 4; n++) {
                int c = warpN * 32 + n * 8 + g;
                bf[n][0] = Bb[(s * 8 + tg)     * 136 + c];
                bf[n][1] = Bb[(s * 8 + tg + 4) * 136 + c];
            }
            #pragma unroll
            for (int m = 0; m < 4; m++)
                #pragma unroll
                for (int n = 0; n < 4; n++)
                    mma_bf16(acc[m][n], af[m][0], af[m][1], af[m][2], af[m][3],
                             bf[n][0], bf[n][1]);
        }
        __syncthreads();
    }

    #pragma unroll
    for (int m = 0; m < 4; m++) {
        int r = row0 + warpM * 64 + m * 16 + g;
        #pragma unroll
        for (int n = 0; n < 4; n++) {
            int c = col0 + warpN * 32 + n * 8 + 2 * tg;
            #pragma unroll
            for (int half = 0; half < 2; half++) {
                int rr = r + half * 8;
                float a0 = acc[m][n][half * 2 + 0];
                float a1 = acc[m][n][half * 2 + 1];
                if (MODE == 3) {
                    int j = c >> 1;
                    float l  = a0 + bias[j];
                    float rv = a1 + aux1[j];
                    ((__nv_bfloat16*)Cout)[(size_t)rr * (N >> 1) + j] =
                        __float2bfloat16_rn(gelu_exact(l) * rv);
                } else {
                    size_t i0 = (size_t)rr * N + c;
                    float v0 = a0 + bias[c];
                    float v1 = a1 + bias[c + 1];
                    if (MODE == 2) {
                        float x0 = aux0[i0], x1v = aux0[i0 + 1];
                        v0 = x0  * sigmoidf_(x0)  * (v0 + aux1[i0])     + aux2[i0];
                        v1 = x1v * sigmoidf_(x1v) * (v1 + aux1[i0 + 1]) + aux2[i0 + 1];
                    }
                    *reinterpret_cast<float2*>((float*)Cout + i0) = make_float2(v0, v1);
                }
            }
        }
    }
}

// ---------------- sLSTM recurrence v3: tensor-core rec GEMM, persistent B ----------------
// 128 blocks: head = bx>>4, batch tile of 32 = (bx&15)*32. 256 threads, 8 warps.
// smem: Bp [64][520] words (133120 B) + rec [32][516] fp32 (66048 B) + h [32][68] words (8704 B)
__global__ __launch_bounds__(256) void slstm_rec3() {
    extern __shared__ uint32_t smw[];
    uint32_t* sBp = smw;                                  // [64][520]
    float* s_rec = (float*)(smw + 64 * 520);              // [32][516]
    uint32_t* sh_w = (uint32_t*)(s_rec + 32 * 516);       // h words [32][68]
    __nv_bfloat16* sh_h = (__nv_bfloat16*)sh_w;           // halves stride 136

    int head = blockIdx.x >> 4;
    int b0 = (blockIdx.x & 15) << 5;
    int tid = threadIdx.x;
    int warp = tid >> 5, lane = tid & 31;
    int g = lane >> 2, tg = lane & 3;
    int wm = warp >> 2, wn = warp & 3;       // wm 0..1, wn 0..3

    // stage head's packed Rg into smem (persistent across 12 steps)
    uint32_t sb = (uint32_t)__cvta_generic_to_shared(sBp);
    const uint32_t* Bg = d_Rgp + (size_t)head * (64 * 512);
    #pragma unroll
    for (int i = 0; i < 32; i++) {
        int e = i * 256 + tid;               // 8192 vec4 loads
        int kp = e >> 7, c = (e & 127) * 4;
        cp_async16(sb + (uint32_t)(kp * 520 + c) * 4, Bg + (size_t)kp * 512 + c);
    }
    asm volatile("cp.async.commit_group;");
    for (int i = tid; i < 32 * 68; i += 256) sh_w[i] = 0;
    float cS[16], nS[16], mS[16];
    #pragma unroll
    for (int j = 0; j < 16; j++) { cS[j] = 0.f; nS[j] = 0.f; mS[j] = 0.f; }
    asm volatile("cp.async.wait_group 0;");
    __syncthreads();

    for (int t = 0; t < 12; t++) {
        // rec[32][512] = h[32][128] @ RgT ; warp tile M16 x N128
        float acc[16][4];
        #pragma unroll
        for (int j = 0; j < 16; j++)
            #pragma unroll
            for (int q = 0; q < 4; q++) acc[j][q] = 0.f;
        #pragma unroll
        for (int s = 0; s < 8; s++) {
            uint32_t a0 = sh_w[(wm * 16 + g)     * 68 + s * 8 + tg];
            uint32_t a1 = sh_w[(wm * 16 + 8 + g) * 68 + s * 8 + tg];
            uint32_t a2 = sh_w[(wm * 16 + g)     * 68 + s * 8 + tg + 4];
            uint32_t a3 = sh_w[(wm * 16 + 8 + g) * 68 + s * 8 + tg + 4];
            #pragma unroll
            for (int j = 0; j < 16; j++) {
                int c = wn * 128 + j * 8 + g;
                uint32_t b0v = sBp[(s * 8 + tg)     * 520 + c];
                uint32_t b1v = sBp[(s * 8 + tg + 4) * 520 + c];
                mma_bf16(acc[j], a0, a1, a2, a3, b0v, b1v);
            }
        }
        #pragma unroll
        for (int j = 0; j < 16; j++) {
            int c = wn * 128 + j * 8 + 2 * tg;
            int r = wm * 16 + g;
            s_rec[r * 516 + c]           = acc[j][0];
            s_rec[r * 516 + c + 1]       = acc[j][1];
            s_rec[(r + 8) * 516 + c]     = acc[j][2];
            s_rec[(r + 8) * 516 + c + 1] = acc[j][3];
        }
        __syncthreads();
        // gate update: thread owns 16 fixed (bb,hs) pairs; state in registers
        #pragma unroll
        for (int it = 0; it < 16; it++) {
            int idx = it * 256 + tid;
            int bb = idx >> 7, hs = idx & 127;
            int b = b0 + bb;
            const float* gxp = d_gx + (size_t)(b * 12 + t) * 4096 + head * 512;
            const float* rp = s_rec + bb * 516;
            float z_ = gxp[hs]       + rp[hs];
            float i_ = gxp[128 + hs] + rp[128 + hs];
            float f_ = gxp[256 + hs] + rp[256 + hs];
            float o_ = gxp[384 + hs] + rp[384 + hs];
            float z  = tanhf(z_);
            float o  = sigmoidf_(o_);
            float mo = mS[it];
            float mn = fmaxf(f_ + mo, i_);
            float iv = expf(i_ - mn);
            float fv = expf(f_ + mo - mn);
            float cv = fv * cS[it] + iv * z;
            float nv = fv * nS[it] + iv;
            float hv = o * (cv / nv);
            cS[it] = cv; nS[it] = nv; mS[it] = mn;
            sh_h[bb * 136 + hs] = __float2bfloat16_rn(hv);
            d_h[(size_t)((b * 12 + t) * 8 + head) * 128 + hs] = hv;
        }
        __syncthreads();
    }
}

// ---------------- launch ----------------
extern "C" void kernel_launch(void* const* d_in, const int* in_sizes, int n_in,
                              void* d_out, int out_size) {
    const float* x       = (const float*)d_in[0];
    const float* ln_g    = (const float*)d_in[1];
    const float* ln_b    = (const float*)d_in[2];
    const float* fc1_w   = (const float*)d_in[3];
    const float* fc1_b   = (const float*)d_in[4];
    const float* fc2_w   = (const float*)d_in[5];
    const float* fc2_b   = (const float*)d_in[6];
    const float* conv1_w = (const float*)d_in[7];
    const float* conv1_b = (const float*)d_in[8];
    const float* conv2_w = (const float*)d_in[9];
    const float* conv2_b = (const float*)d_in[10];
    const float* xlg     = (const float*)d_in[11];
    const float* xlb     = (const float*)d_in[12];
    const float* Wg      = (const float*)d_in[13];
    const float* bg      = (const float*)d_in[14];
    const float* Rg      = (const float*)d_in[15];
    const float* gng     = (const float*)d_in[16];
    const float* gnb     = (const float*)d_in[17];
    const float* uplw    = (const float*)d_in[18];
    const float* uplb    = (const float*)d_in[19];
    const float* uprw    = (const float*)d_in[20];
    const float* uprb    = (const float*)d_in[21];
    const float* downw   = (const float*)d_in[22];
    const float* downb   = (const float*)d_in[23];
    float* out = (float*)d_out;

    cudaFuncSetAttribute(slstm_rec3, cudaFuncAttributeMaxDynamicSharedMemorySize, 207872);

    float *p_xn, *p_xc, *p_x1, *p_gx, *p_y, *p_z48;
    __nv_bfloat16 *p_xn2h, *p_hnh, *p_uh;
    uint32_t *p_Wgp, *p_downp, *p_Wpair;
    cudaGetSymbolAddress((void**)&p_xn,    d_xn);
    cudaGetSymbolAddress((void**)&p_xc,    d_xc);
    cudaGetSymbolAddress((void**)&p_x1,    d_x1);
    cudaGetSymbolAddress((void**)&p_gx,    d_gx);
    cudaGetSymbolAddress((void**)&p_y,     d_y);
    cudaGetSymbolAddress((void**)&p_z48,   d_z48);
    cudaGetSymbolAddress((void**)&p_xn2h,  d_xn2h);
    cudaGetSymbolAddress((void**)&p_hnh,   d_hnh);
    cudaGetSymbolAddress((void**)&p_uh,    d_uh);
    cudaGetSymbolAddress((void**)&p_Wgp,   d_Wgp);
    cudaGetSymbolAddress((void**)&p_downp, d_downp);
    cudaGetSymbolAddress((void**)&p_Wpair, d_Wpair);

    // one-time per launch: packs
    pack_w<<<dim3(16, 512), 256>>>(Wg,    p_Wgp,   4096);
    pack_w<<<dim3(4, 512),  256>>>(downw, p_downp, 1024);
    pack_w_pair<<<dim3(4, 512), 256>>>(uplw, uprw, p_Wpair);
    pack_rg<<<dim3(8, 16), 256>>>(Rg);

    // xn = LN(x); skip = xn
    ln_rows<<<BT_, 256>>>(x, p_xn, ln_g, ln_b);
    // xc = conv1d(xn, fc1)
    fc1_conv<<<dim3(8, B_), 128>>>(fc1_w, fc1_b);
    // x1 = fc2(xc)
    fc2_1x1<<<dim3(4, B_), 256>>>(fc2_w, fc2_b);
    // xn2 = LN(x1) -> bf16
    ln_rows_bf16<<<BT_, 256>>>(p_x1, p_xn2h, xlg, xlb);
    // gx = xn2 @ Wg + bg
    gemm_bf16<0><<<dim3(32, 48), 256>>>(4096, 1024, p_xn2h, p_Wgp, bg,
                                        nullptr, nullptr, nullptr, p_gx);
    // sLSTM recurrence -> d_h  (tensor-core rec)
    slstm_rec3<<<128, 256, 207872>>>();
    // per-head GroupNorm -> bf16 hn
    groupnorm2<<<BT_, 256>>>(gng, gnb);
    // u = gelu(hn@upl + uplb) * (hn@upr + uprb)   [single interleaved GEMM]
    gemm_bf16<3><<<dim3(16, 48), 256>>>(2048, 1024, p_hnh, p_Wpair, uplb,
                                        nullptr, uprb, nullptr, p_uh);
    // y = silu(xc) * (u @ down + downb + x1) + xn
    gemm_bf16<2><<<dim3(8, 48), 256>>>(1024, 1024, p_uh, p_downp, downb,
                                       p_xc, p_x1, p_xn, p_y);
    // z48 = conv1d(y, 12->48)
    conv12_48<<<dim3(8, B_), 128>>>(conv1_w, conv1_b);
    // z48 = LN(gelu(z48))
    gelu_ln_rows<<<ROWS48_, 256>>>(p_z48, ln_g, ln_b);
    // out = conv1d(z48, 48->12) + skip
    conv48_12<<<dim3(8, B_), 128>>>(conv2_w, conv2_b, out);
}

// round 10
// speedup vs baseline: 3.6832x; 1.1161x over previous
#include <cuda_runtime.h>
#include <cuda_bf16.h>
#include <cmath>
#include <cstdint>

// ---------------- problem constants ----------------
static constexpr int B_   = 512;
static constexpr int T_   = 12;
static constexpr int E_   = 1024;
static constexpr int NH_  = 8;
static constexpr int HS_  = 128;
static constexpr int H_   = 1024;
static constexpr int G4_  = 4096;
static constexpr int BT_  = B_ * T_;        // 6144

// ---------------- scratch (device globals; no allocation) ----------------
__device__ float d_xn [BT_ * (size_t)E_];
__device__ float d_xc [BT_ * (size_t)E_];
__device__ float d_x1 [BT_ * (size_t)E_];
__device__ float d_gx [BT_ * (size_t)G4_];
__device__ float d_h  [BT_ * (size_t)H_];
__device__ float d_y  [BT_ * (size_t)E_];
// bf16 GEMM operands
__device__ __nv_bfloat16 d_xn2h[BT_ * (size_t)E_];
__device__ __nv_bfloat16 d_hnh [BT_ * (size_t)H_];
__device__ __nv_bfloat16 d_uh  [BT_ * (size_t)H_];
// pair-packed bf16 weights
__device__ uint32_t d_Wgp  [(size_t)512 * G4_];
__device__ uint32_t d_downp[(size_t)512 * E_];
__device__ uint32_t d_Wpair[(size_t)512 * 2048];
__device__ uint32_t d_Rgp  [(size_t)NH_ * 64 * 512];

// ---------------- helpers ----------------
__device__ __forceinline__ float gelu_exact(float x) {
    return 0.5f * x * (1.0f + erff(x * 0.70710678118654752440f));
}
__device__ __forceinline__ float sigmoidf_(float x) {
    return 1.0f / (1.0f + expf(-x));
}
__device__ __forceinline__ void cp_async16(uint32_t saddr, const void* g) {
    asm volatile("cp.async.cg.shared.global [%0], [%1], 16;" :: "r"(saddr), "l"(g));
}
__device__ __forceinline__ void mma_bf16(float* acc, uint32_t a0, uint32_t a1,
                                         uint32_t a2, uint32_t a3,
                                         uint32_t b0, uint32_t b1) {
    asm volatile(
        "mma.sync.aligned.m16n8k16.row.col.f32.bf16.bf16.f32 "
        "{%0,%1,%2,%3}, {%4,%5,%6,%7}, {%8,%9}, {%0,%1,%2,%3};"
        : "+f"(acc[0]), "+f"(acc[1]), "+f"(acc[2]), "+f"(acc[3])
        : "r"(a0), "r"(a1), "r"(a2), "r"(a3), "r"(b0), "r"(b1));
}
__device__ __forceinline__ void warp_reduce_2(float& s, float& ss) {
    #pragma unroll
    for (int o = 16; o; o >>= 1) {
        s  += __shfl_xor_sync(0xffffffffu, s,  o);
        ss += __shfl_xor_sync(0xffffffffu, ss, o);
    }
}

// ---------------- GroupNorm -> bf16 ----------------
__global__ __launch_bounds__(256) void groupnorm2(const float* __restrict__ gng,
                                                  const float* __restrict__ gnb) {
    size_t row = blockIdx.x;
    int head = threadIdx.x >> 5, lane = threadIdx.x & 31;
    const float* x = d_h + row * 1024 + head * 128;
    float s = 0.f, ss = 0.f;
    for (int j = lane; j < 128; j += 32) {
        float v = x[j];
        s += v; ss += v * v;
    }
    warp_reduce_2(s, ss);
    float mu  = s * (1.0f / 128.0f);
    float var = ss * (1.0f / 128.0f) - mu * mu;
    float rstd = rsqrtf(var + 1e-5f);
    for (int j = lane; j < 128; j += 32) {
        int ch = head * 128 + j;
        d_hnh[row * 1024 + ch] =
            __float2bfloat16_rn((x[j] - mu) * rstd * gng[ch] + gnb[ch]);
    }
}

// ---------------- weight packs ----------------
__global__ void pack_w(const float* __restrict__ w, uint32_t* __restrict__ out, int N) {
    int n = blockIdx.x * 256 + threadIdx.x;
    int kp = blockIdx.y;
    __nv_bfloat162 h = __floats2bfloat162_rn(w[(size_t)(2 * kp) * N + n],
                                             w[(size_t)(2 * kp + 1) * N + n]);
    out[(size_t)kp * N + n] = *reinterpret_cast<uint32_t*>(&h);
}
__global__ void pack_w_pair(const float* __restrict__ wl, const float* __restrict__ wr,
                            uint32_t* __restrict__ out) {
    int n = blockIdx.x * 256 + threadIdx.x;
    int kp = blockIdx.y;
    __nv_bfloat162 hl = __floats2bfloat162_rn(wl[(size_t)(2 * kp) * 1024 + n],
                                              wl[(size_t)(2 * kp + 1) * 1024 + n]);
    __nv_bfloat162 hr = __floats2bfloat162_rn(wr[(size_t)(2 * kp) * 1024 + n],
                                              wr[(size_t)(2 * kp + 1) * 1024 + n]);
    out[(size_t)kp * 2048 + 2 * n]     = *reinterpret_cast<uint32_t*>(&hl);
    out[(size_t)kp * 2048 + 2 * n + 1] = *reinterpret_cast<uint32_t*>(&hr);
}
__global__ __launch_bounds__(256) void pack_rg(const float* __restrict__ Rg) {
    __shared__ float tile[32][129];
    int head = blockIdx.x;
    int g0 = blockIdx.y * 32;
    int tid = threadIdx.x;
    #pragma unroll
    for (int i = 0; i < 16; i++) {
        int e = i * 256 + tid;
        int r = e >> 7, c = e & 127;
        tile[r][c] = Rg[((size_t)(head * 512 + g0 + r)) * 128 + c];
    }
    __syncthreads();
    #pragma unroll
    for (int i = 0; i < 8; i++) {
        int e = i * 256 + tid;
        int kp = e >> 5, gl = e & 31;
        __nv_bfloat162 h = __floats2bfloat162_rn(tile[gl][2 * kp], tile[gl][2 * kp + 1]);
        d_Rgp[((size_t)(head * 64 + kp)) * 512 + g0 + gl] =
            *reinterpret_cast<uint32_t*>(&h);
    }
}

// ---------------- fused front: LN(x) -> fc1 conv -> fc2 -> LN -> bf16 ----------------
// one block per batch b; 384 threads = 12 warps (one warp per channel row).
__global__ __launch_bounds__(384) void fused_front(
    const float* __restrict__ x,
    const float* __restrict__ ln_g, const float* __restrict__ ln_b,
    const float* __restrict__ w1g, const float* __restrict__ b1g,
    const float* __restrict__ w2g, const float* __restrict__ b2g,
    const float* __restrict__ xlg, const float* __restrict__ xlb) {
    extern __shared__ float sm[];
    float* sxn = sm;                    // [12][1032], data at +1, halo zeros
    float* sxc = sxn + 12 * 1032;       // [12][1024]
    float* sx1 = sxc + 12 * 1024;       // [12][1024]
    float* sw1 = sx1 + 12 * 1024;       // 432
    float* sw2 = sw1 + 432;             // 144
    float* sb1 = sw2 + 144;             // 12
    float* sb2 = sb1 + 12;              // 12
    int b = blockIdx.x, tid = threadIdx.x, w = tid >> 5, lane = tid & 31;

    for (int i = tid; i < 432; i += 384) sw1[i] = w1g[i];
    if (tid < 144) sw2[tid] = w2g[tid];
    if (tid < 12) { sb1[tid] = b1g[tid]; sb2[tid] = b2g[tid]; }
    if (lane == 0) { sxn[w * 1032] = 0.f; sxn[w * 1032 + 1025] = 0.f; }

    // LN1 of row (b, w)
    size_t rbase = ((size_t)b * 12 + w) * 1024;
    const float* xr = x + rbase;
    float4 vals[8];
    float s = 0.f, ss = 0.f;
    #pragma unroll
    for (int j = 0; j < 8; j++) {
        float4 v = *reinterpret_cast<const float4*>(xr + lane * 4 + j * 128);
        vals[j] = v;
        s  += v.x + v.y + v.z + v.w;
        ss += v.x*v.x + v.y*v.y + v.z*v.z + v.w*v.w;
    }
    warp_reduce_2(s, ss);
    float mu = s * (1.0f / 1024.0f);
    float rstd = rsqrtf(ss * (1.0f / 1024.0f) - mu * mu + 1e-5f);
    #pragma unroll
    for (int j = 0; j < 8; j++) {
        int idx = lane * 4 + j * 128;
        float4 g = *reinterpret_cast<const float4*>(ln_g + idx);
        float4 bb = *reinterpret_cast<const float4*>(ln_b + idx);
        float4 v = vals[j], o;
        o.x = (v.x - mu) * rstd * g.x + bb.x;
        o.y = (v.y - mu) * rstd * g.y + bb.y;
        o.z = (v.z - mu) * rstd * g.z + bb.z;
        o.w = (v.w - mu) * rstd * g.w + bb.w;
        sxn[w * 1032 + 1 + idx] = o.x; sxn[w * 1032 + 2 + idx] = o.y;
        sxn[w * 1032 + 3 + idx] = o.z; sxn[w * 1032 + 4 + idx] = o.w;
        *reinterpret_cast<float4*>(d_xn + rbase + idx) = o;
    }
    __syncthreads();

    // fc1 conv: warp w computes out channel o=w over all l
    {
        int o = w;
        float wl[36];
        #pragma unroll
        for (int i = 0; i < 36; i++) wl[i] = sw1[o * 36 + i];
        float bo = sb1[o];
        for (int j = 0; j < 32; j++) {
            int l = lane + j * 32;
            float a = bo;
            #pragma unroll
            for (int c = 0; c < 12; c++) {
                a += wl[c*3]   * sxn[c * 1032 + l]
                   + wl[c*3+1] * sxn[c * 1032 + l + 1]
                   + wl[c*3+2] * sxn[c * 1032 + l + 2];
            }
            sxc[o * 1024 + l] = a;
            d_xc[rbase + l] = a;   // rbase row == (b*12+o) since o==w
        }
    }
    __syncthreads();

    // fc2 1x1
    {
        int o = w;
        float wl[12];
        #pragma unroll
        for (int c = 0; c < 12; c++) wl[c] = sw2[o * 12 + c];
        float bo = sb2[o];
        for (int j = 0; j < 32; j++) {
            int l = lane + j * 32;
            float a = bo;
            #pragma unroll
            for (int c = 0; c < 12; c++) a += wl[c] * sxc[c * 1024 + l];
            sx1[o * 1024 + l] = a;
            d_x1[rbase + l] = a;
        }
    }
    __syncthreads();

    // LN2 (xl_ln) of row w -> bf16
    s = 0.f; ss = 0.f;
    #pragma unroll
    for (int j = 0; j < 8; j++) {
        float4 v = *reinterpret_cast<const float4*>(sx1 + w * 1024 + lane * 4 + j * 128);
        vals[j] = v;
        s  += v.x + v.y + v.z + v.w;
        ss += v.x*v.x + v.y*v.y + v.z*v.z + v.w*v.w;
    }
    warp_reduce_2(s, ss);
    mu = s * (1.0f / 1024.0f);
    rstd = rsqrtf(ss * (1.0f / 1024.0f) - mu * mu + 1e-5f);
    #pragma unroll
    for (int j = 0; j < 8; j++) {
        int idx = lane * 4 + j * 128;
        float4 g = *reinterpret_cast<const float4*>(xlg + idx);
        float4 bb = *reinterpret_cast<const float4*>(xlb + idx);
        float4 v = vals[j];
        __nv_bfloat162 h0 = __floats2bfloat162_rn((v.x - mu) * rstd * g.x + bb.x,
                                                  (v.y - mu) * rstd * g.y + bb.y);
        __nv_bfloat162 h1 = __floats2bfloat162_rn((v.z - mu) * rstd * g.z + bb.z,
                                                  (v.w - mu) * rstd * g.w + bb.w);
        uint2 pk = make_uint2(*reinterpret_cast<uint32_t*>(&h0),
                              *reinterpret_cast<uint32_t*>(&h1));
        *reinterpret_cast<uint2*>(d_xn2h + rbase + idx) = pk;
    }
}

// ---------------- fused tail: conv12->48 + gelu + LN + conv48->12 + skip ----------------
// one block per batch b; 512 threads = 16 warps.
__global__ __launch_bounds__(512) void fused_tail(
    const float* __restrict__ w1g, const float* __restrict__ b1g,
    const float* __restrict__ w2g, const float* __restrict__ b2g,
    const float* __restrict__ ln_g, const float* __restrict__ ln_b,
    float* __restrict__ out) {
    extern __shared__ float sm[];
    float* sy = sm;                                       // [12][1032], data at +1
    __nv_bfloat16* sz = (__nv_bfloat16*)(sy + 12 * 1032); // [48][1032], data at +1
    float* stats = (float*)(sz + 48 * 1032);              // [48][2] mu,rstd
    float* sw1 = stats + 96;                              // 1728 (o,c,k)
    float* sw2 = sw1 + 1728;                              // 1728 repacked (c,o,k)
    float* sb1 = sw2 + 1728;                              // 48
    float* sb2 = sb1 + 48;                                // 12
    int b = blockIdx.x, tid = threadIdx.x, w = tid >> 5, lane = tid & 31;

    // load y (12x1024) into sy with halo
    for (int i = tid; i < 12 * 256; i += 512) {
        int c = i >> 8, q = (i & 255) * 4;
        float4 v = *reinterpret_cast<const float4*>(d_y + ((size_t)b * 12 + c) * 1024 + q);
        sy[c * 1032 + 1 + q]     = v.x;
        sy[c * 1032 + 1 + q + 1] = v.y;
        sy[c * 1032 + 1 + q + 2] = v.z;
        sy[c * 1032 + 1 + q + 3] = v.w;
    }
    if (tid < 12) { sy[tid * 1032] = 0.f; sy[tid * 1032 + 1025] = 0.f; }
    if (tid < 48) {
        sz[tid * 1032] = __float2bfloat16_rn(0.f);
        sz[tid * 1032 + 1025] = __float2bfloat16_rn(0.f);
    }
    for (int i = tid; i < 1728; i += 512) {
        sw1[i] = w1g[i];
        // repack conv2 (12,48,3) -> [c][o][k]
        int o = i / 144, rem = i % 144;      // i = (o*48+c)*3+k
        int c = rem / 3, k = rem % 3;
        sw2[c * 36 + o * 3 + k] = w2g[i];
    }
    if (tid < 48) sb1[tid] = b1g[tid];
    if (tid < 12) sb2[tid] = b2g[tid];
    __syncthreads();

    // Phase A: conv12->48 + gelu, per-row stats (warp w owns rows 3w..3w+2)
    #pragma unroll
    for (int rr = 0; rr < 3; rr++) {
        int o = w * 3 + rr;
        float wl[36];
        #pragma unroll
        for (int i = 0; i < 36; i++) wl[i] = sw1[o * 36 + i];
        float bo = sb1[o];
        float s = 0.f, ss = 0.f;
        for (int j = 0; j < 32; j++) {
            int l = lane + j * 32;
            float a = bo;
            #pragma unroll
            for (int c = 0; c < 12; c++) {
                a += wl[c*3]   * sy[c * 1032 + l]
                   + wl[c*3+1] * sy[c * 1032 + l + 1]
                   + wl[c*3+2] * sy[c * 1032 + l + 2];
            }
            float v = gelu_exact(a);
            s += v; ss += v * v;
            sz[o * 1032 + 1 + l] = __float2bfloat16_rn(v);
        }
        warp_reduce_2(s, ss);
        if (lane == 0) {
            float mu = s * (1.0f / 1024.0f);
            stats[o * 2] = mu;
            stats[o * 2 + 1] = rsqrtf(ss * (1.0f / 1024.0f) - mu * mu + 1e-5f);
        }
    }
    __syncthreads();

    // Phase B1: in-place LN apply on sz
    for (int i = tid; i < 48 * 1024; i += 512) {
        int o = i >> 10, l = i & 1023;
        float v = __bfloat162float(sz[o * 1032 + 1 + l]);
        float hn = (v - stats[o * 2]) * stats[o * 2 + 1] * ln_g[l] + ln_b[l];
        sz[o * 1032 + 1 + l] = __float2bfloat16_rn(hn);
    }
    __syncthreads();

    // Phase B2: conv48->12 + skip; thread owns l2 = 2*tid, 2*tid+1
    {
        int l2 = tid * 2;
        float acc0[12], acc1[12];
        #pragma unroll
        for (int o = 0; o < 12; o++) { acc0[o] = 0.f; acc1[o] = 0.f; }
        for (int c = 0; c < 48; c++) {
            // halves at positions (l2-1 .. l2+2): smem index c*1032 + l2 .. +3
            uint32_t u0 = *reinterpret_cast<uint32_t*>(&sz[c * 1032 + l2]);
            uint32_t u1 = *reinterpret_cast<uint32_t*>(&sz[c * 1032 + l2 + 2]);
            __nv_bfloat162 p0 = *reinterpret_cast<__nv_bfloat162*>(&u0);
            __nv_bfloat162 p1 = *reinterpret_cast<__nv_bfloat162*>(&u1);
            float h0 = __bfloat162float(p0.x), h1 = __bfloat162float(p0.y);
            float h2 = __bfloat162float(p1.x), h3 = __bfloat162float(p1.y);
            const float4* wr = reinterpret_cast<const float4*>(sw2 + c * 36);
            #pragma unroll
            for (int q = 0; q < 9; q++) {
                float4 wv = wr[q];      // 4 weights spanning o*3+k
                int base = q * 4;
                #pragma unroll
                for (int e = 0; e < 4; e++) {
                    int idx = base + e;
                    int o = idx / 3, k = idx % 3;
                    float wk = (e == 0) ? wv.x : (e == 1) ? wv.y : (e == 2) ? wv.z : wv.w;
                    float i0 = (k == 0) ? h0 : (k == 1) ? h1 : h2;
                    float i1 = (k == 0) ? h1 : (k == 1) ? h2 : h3;
                    acc0[o] += wk * i0;
                    acc1[o] += wk * i1;
                }
            }
        }
        #pragma unroll
        for (int o = 0; o < 12; o++) {
            size_t idx = ((size_t)b * 12 + o) * 1024 + l2;
            float2 sk = *reinterpret_cast<const float2*>(d_xn + idx);
            float2 ov;
            ov.x = acc0[o] + sb2[o] + sk.x;
            ov.y = acc1[o] + sb2[o] + sk.y;
            *reinterpret_cast<float2*>(out + idx) = ov;
        }
    }
}

// ---------------- bf16 tensor-core GEMM (unchanged from R9) ----------------
template<int MODE>
__global__ __launch_bounds__(256) void gemm_bf16(int N, int K,
                                                 const __nv_bfloat16* __restrict__ A,
                                                 const uint32_t* __restrict__ Bp,
                                                 const float* __restrict__ bias,
                                                 const float* __restrict__ aux0,
                                                 const float* __restrict__ aux1,
                                                 const float* __restrict__ aux2,
                                                 void* __restrict__ Cout) {
    __shared__ uint32_t As[2][128 * 20];
    __shared__ uint32_t Bs[2][16 * 136];
    int tid = threadIdx.x;
    int warp = tid >> 5, lane = tid & 31;
    int g = lane >> 2, tg = lane & 3;
    int warpM = warp >> 2, warpN = warp & 3;
    int row0 = blockIdx.y * 128, col0 = blockIdx.x * 128;

    uint32_t asb = (uint32_t)__cvta_generic_to_shared(&As[0][0]);
    uint32_t bsb = (uint32_t)__cvta_generic_to_shared(&Bs[0][0]);

    float acc[4][4][4];
    #pragma unroll
    for (int m = 0; m < 4; m++)
        #pragma unroll
        for (int n = 0; n < 4; n++)
            #pragma unroll
            for (int q = 0; q < 4; q++) acc[m][n][q] = 0.f;

    const int nt = K >> 5;

    auto load_tile = [&](int it, int buf) {
        int k0 = it << 5;
        int kp0 = it << 4;
        #pragma unroll
        for (int i = 0; i < 2; i++) {
            int e = i * 256 + tid;
            int r = e >> 2, ch = e & 3;
            cp_async16(asb + (uint32_t)(buf * 128 * 20 + r * 20 + ch * 4) * 4,
                       A + (size_t)(row0 + r) * K + k0 + ch * 8);
        }
        #pragma unroll
        for (int i = 0; i < 2; i++) {
            int e = i * 256 + tid;
            int kp = e >> 5, c = (e & 31) * 4;
            cp_async16(bsb + (uint32_t)(buf * 16 * 136 + kp * 136 + c) * 4,
                       Bp + (size_t)(kp0 + kp) * N + col0 + c);
        }
        asm volatile("cp.async.commit_group;");
    };

    load_tile(0, 0);
    for (int it = 0; it < nt; it++) {
        int buf = it & 1;
        if (it + 1 < nt) {
            load_tile(it + 1, buf ^ 1);
            asm volatile("cp.async.wait_group 1;");
        } else {
            asm volatile("cp.async.wait_group 0;");
        }
        __syncthreads();
        const uint32_t* Ab = &As[buf][0];
        const uint32_t* Bb = &Bs[buf][0];
        #pragma unroll
        for (int s = 0; s < 2; s++) {
            uint32_t af[4][4];
            #pragma unroll
            for (int m = 0; m < 4; m++) {
                int r = warpM * 64 + m * 16;
                af[m][0] = Ab[(r + g)     * 20 + s * 8 + tg];
                af[m][1] = Ab[(r + 8 + g) * 20 + s * 8 + tg];
                af[m][2] = Ab[(r + g)     * 20 + s * 8 + tg + 4];
                af[m][3] = Ab[(r + 8 + g) * 20 + s * 8 + tg + 4];
            }
            uint32_t bf[4][2];
            #pragma unroll
            for (int n = 0; n < 4; n++) {
                int c = warpN * 32 + n * 8 + g;
                bf[n][0] = Bb[(s * 8 + tg)     * 136 + c];
                bf[n][1] = Bb[(s * 8 + tg + 4) * 136 + c];
            }
            #pragma unroll
            for (int m = 0; m < 4; m++)
                #pragma unroll
                for (int n = 0; n < 4; n++)
                    mma_bf16(acc[m][n], af[m][0], af[m][1], af[m][2], af[m][3],
                             bf[n][0], bf[n][1]);
        }
        __syncthreads();
    }

    #pragma unroll
    for (int m = 0; m < 4; m++) {
        int r = row0 + warpM * 64 + m * 16 + g;
        #pragma unroll
        for (int n = 0; n < 4; n++) {
            int c = col0 + warpN * 32 + n * 8 + 2 * tg;
            #pragma unroll
            for (int half = 0; half < 2; half++) {
                int rr = r + half * 8;
                float a0 = acc[m][n][half * 2 + 0];
                float a1 = acc[m][n][half * 2 + 1];
                if (MODE == 3) {
                    int j = c >> 1;
                    float l  = a0 + bias[j];
                    float rv = a1 + aux1[j];
                    ((__nv_bfloat16*)Cout)[(size_t)rr * (N >> 1) + j] =
                        __float2bfloat16_rn(gelu_exact(l) * rv);
                } else {
                    size_t i0 = (size_t)rr * N + c;
                    float v0 = a0 + bias[c];
                    float v1 = a1 + bias[c + 1];
                    if (MODE == 2) {
                        float x0 = aux0[i0], x1v = aux0[i0 + 1];
                        v0 = x0  * sigmoidf_(x0)  * (v0 + aux1[i0])     + aux2[i0];
                        v1 = x1v * sigmoidf_(x1v) * (v1 + aux1[i0 + 1]) + aux2[i0 + 1];
                    }
                    *reinterpret_cast<float2*>((float*)Cout + i0) = make_float2(v0, v1);
                }
            }
        }
    }
}

// ---------------- sLSTM recurrence v3 (unchanged from R9) ----------------
__global__ __launch_bounds__(256) void slstm_rec3() {
    extern __shared__ uint32_t smw[];
    uint32_t* sBp = smw;                                  // [64][520]
    float* s_rec = (float*)(smw + 64 * 520);              // [32][516]
    uint32_t* sh_w = (uint32_t*)(s_rec + 32 * 516);       // [32][68]
    __nv_bfloat16* sh_h = (__nv_bfloat16*)sh_w;

    int head = blockIdx.x >> 4;
    int b0 = (blockIdx.x & 15) << 5;
    int tid = threadIdx.x;
    int warp = tid >> 5, lane = tid & 31;
    int g = lane >> 2, tg = lane & 3;
    int wm = warp >> 2, wn = warp & 3;

    uint32_t sb = (uint32_t)__cvta_generic_to_shared(sBp);
    const uint32_t* Bg = d_Rgp + (size_t)head * (64 * 512);
    #pragma unroll
    for (int i = 0; i < 32; i++) {
        int e = i * 256 + tid;
        int kp = e >> 7, c = (e & 127) * 4;
        cp_async16(sb + (uint32_t)(kp * 520 + c) * 4, Bg + (size_t)kp * 512 + c);
    }
    asm volatile("cp.async.commit_group;");
    for (int i = tid; i < 32 * 68; i += 256) sh_w[i] = 0;
    float cS[16], nS[16], mS[16];
    #pragma unroll
    for (int j = 0; j < 16; j++) { cS[j] = 0.f; nS[j] = 0.f; mS[j] = 0.f; }
    asm volatile("cp.async.wait_group 0;");
    __syncthreads();

    for (int t = 0; t < 12; t++) {
        float acc[16][4];
        #pragma unroll
        for (int j = 0; j < 16; j++)
            #pragma unroll
            for (int q = 0; q < 4; q++) acc[j][q] = 0.f;
        #pragma unroll
        for (int s = 0; s < 8; s++) {
            uint32_t a0 = sh_w[(wm * 16 + g)     * 68 + s * 8 + tg];
            uint32_t a1 = sh_w[(wm * 16 + 8 + g) * 68 + s * 8 + tg];
            uint32_t a2 = sh_w[(wm * 16 + g)     * 68 + s * 8 + tg + 4];
            uint32_t a3 = sh_w[(wm * 16 + 8 + g) * 68 + s * 8 + tg + 4];
            #pragma unroll
            for (int j = 0; j < 16; j++) {
                int c = wn * 128 + j * 8 + g;
                uint32_t b0v = sBp[(s * 8 + tg)     * 520 + c];
                uint32_t b1v = sBp[(s * 8 + tg + 4) * 520 + c];
                mma_bf16(acc[j], a0, a1, a2, a3, b0v, b1v);
            }
        }
        #pragma unroll
        for (int j = 0; j < 16; j++) {
            int c = wn * 128 + j * 8 + 2 * tg;
            int r = wm * 16 + g;
            s_rec[r * 516 + c]           = acc[j][0];
            s_rec[r * 516 + c + 1]       = acc[j][1];
            s_rec[(r + 8) * 516 + c]     = acc[j][2];
            s_rec[(r + 8) * 516 + c + 1] = acc[j][3];
        }
        __syncthreads();
        #pragma unroll
        for (int it = 0; it < 16; it++) {
            int idx = it * 256 + tid;
            int bb = idx >> 7, hs = idx & 127;
            int b = b0 + bb;
            const float* gxp = d_gx + (size_t)(b * 12 + t) * 4096 + head * 512;
            const float* rp = s_rec + bb * 516;
            float z_ = gxp[hs]       + rp[hs];
            float i_ = gxp[128 + hs] + rp[128 + hs];
            float f_ = gxp[256 + hs] + rp[256 + hs];
            float o_ = gxp[384 + hs] + rp[384 + hs];
            float z  = tanhf(z_);
            float o  = sigmoidf_(o_);
            float mo = mS[it];
            float mn = fmaxf(f_ + mo, i_);
            float iv = expf(i_ - mn);
            float fv = expf(f_ + mo - mn);
            float cv = fv * cS[it] + iv * z;
            float nv = fv * nS[it] + iv;
            float hv = o * (cv / nv);
            cS[it] = cv; nS[it] = nv; mS[it] = mn;
            sh_h[bb * 136 + hs] = __float2bfloat16_rn(hv);
            d_h[(size_t)((b * 12 + t) * 8 + head) * 128 + hs] = hv;
        }
        __syncthreads();
    }
}

// ---------------- launch ----------------
extern "C" void kernel_launch(void* const* d_in, const int* in_sizes, int n_in,
                              void* d_out, int out_size) {
    const float* x       = (const float*)d_in[0];
    const float* ln_g    = (const float*)d_in[1];
    const float* ln_b    = (const float*)d_in[2];
    const float* fc1_w   = (const float*)d_in[3];
    const float* fc1_b   = (const float*)d_in[4];
    const float* fc2_w   = (const float*)d_in[5];
    const float* fc2_b   = (const float*)d_in[6];
    const float* conv1_w = (const float*)d_in[7];
    const float* conv1_b = (const float*)d_in[8];
    const float* conv2_w = (const float*)d_in[9];
    const float* conv2_b = (const float*)d_in[10];
    const float* xlg     = (const float*)d_in[11];
    const float* xlb     = (const float*)d_in[12];
    const float* Wg      = (const float*)d_in[13];
    const float* bg      = (const float*)d_in[14];
    const float* Rg      = (const float*)d_in[15];
    const float* gng     = (const float*)d_in[16];
    const float* gnb     = (const float*)d_in[17];
    const float* uplw    = (const float*)d_in[18];
    const float* uplb    = (const float*)d_in[19];
    const float* uprw    = (const float*)d_in[20];
    const float* uprb    = (const float*)d_in[21];
    const float* downw   = (const float*)d_in[22];
    const float* downb   = (const float*)d_in[23];
    float* out = (float*)d_out;

    cudaFuncSetAttribute(slstm_rec3,  cudaFuncAttributeMaxDynamicSharedMemorySize, 207872);
    cudaFuncSetAttribute(fused_front, cudaFuncAttributeMaxDynamicSharedMemorySize, 150240);
    cudaFuncSetAttribute(fused_tail,  cudaFuncAttributeMaxDynamicSharedMemorySize, 163056);

    float *p_xn, *p_xc, *p_x1, *p_gx, *p_y;
    __nv_bfloat16 *p_xn2h, *p_hnh, *p_uh;
    uint32_t *p_Wgp, *p_downp, *p_Wpair;
    cudaGetSymbolAddress((void**)&p_xn,    d_xn);
    cudaGetSymbolAddress((void**)&p_xc,    d_xc);
    cudaGetSymbolAddress((void**)&p_x1,    d_x1);
    cudaGetSymbolAddress((void**)&p_gx,    d_gx);
    cudaGetSymbolAddress((void**)&p_y,     d_y);
    cudaGetSymbolAddress((void**)&p_xn2h,  d_xn2h);
    cudaGetSymbolAddress((void**)&p_hnh,   d_hnh);
    cudaGetSymbolAddress((void**)&p_uh,    d_uh);
    cudaGetSymbolAddress((void**)&p_Wgp,   d_Wgp);
    cudaGetSymbolAddress((void**)&p_downp, d_downp);
    cudaGetSymbolAddress((void**)&p_Wpair, d_Wpair);

    pack_w<<<dim3(16, 512), 256>>>(Wg,    p_Wgp,   4096);
    pack_w<<<dim3(4, 512),  256>>>(downw, p_downp, 1024);
    pack_w_pair<<<dim3(4, 512), 256>>>(uplw, uprw, p_Wpair);
    pack_rg<<<dim3(8, 16), 256>>>(Rg);

    // LN(x) -> fc1 -> fc2 -> LN -> bf16   [fused per batch]
    fused_front<<<B_, 384, 150240>>>(x, ln_g, ln_b, fc1_w, fc1_b,
                                     fc2_w, fc2_b, xlg, xlb);
    // gx = xn2 @ Wg + bg
    gemm_bf16<0><<<dim3(32, 48), 256>>>(4096, 1024, p_xn2h, p_Wgp, bg,
                                        nullptr, nullptr, nullptr, p_gx);
    // sLSTM recurrence -> d_h
    slstm_rec3<<<128, 256, 207872>>>();
    // per-head GroupNorm -> bf16 hn
    groupnorm2<<<BT_, 256>>>(gng, gnb);
    // u = gelu(hn@upl + uplb) * (hn@upr + uprb)
    gemm_bf16<3><<<dim3(16, 48), 256>>>(2048, 1024, p_hnh, p_Wpair, uplb,
                                        nullptr, uprb, nullptr, p_uh);
    // y = silu(xc) * (u @ down + downb + x1) + xn
    gemm_bf16<2><<<dim3(8, 48), 256>>>(1024, 1024, p_uh, p_downp, downb,
                                       p_xc, p_x1, p_xn, p_y);
    // conv12->48 + gelu + LN + conv48->12 + skip   [fused per batch]
    fused_tail<<<B_, 512, 163056>>>(conv1_w, conv1_b, conv2_w, conv2_b,
                                    ln_g, ln_b, out);
}

// round 11
// speedup vs baseline: 3.7297x; 1.0126x over previous
#include <cuda_runtime.h>
#include <cuda_bf16.h>
#include <cmath>
#include <cstdint>

// ---------------- problem constants ----------------
static constexpr int B_   = 512;
static constexpr int T_   = 12;
static constexpr int E_   = 1024;
static constexpr int NH_  = 8;
static constexpr int HS_  = 128;
static constexpr int H_   = 1024;
static constexpr int G4_  = 4096;
static constexpr int BT_  = B_ * T_;        // 6144

// ---------------- scratch (device globals; no allocation) ----------------
__device__ float d_xn [BT_ * (size_t)E_];
__device__ float d_xc [BT_ * (size_t)E_];
__device__ float d_x1 [BT_ * (size_t)E_];
__device__ float d_h  [BT_ * (size_t)H_];
__device__ float d_y  [BT_ * (size_t)E_];
// bf16 operands
__device__ __nv_bfloat16 d_gxh [BT_ * (size_t)G4_];
__device__ __nv_bfloat16 d_xn2h[BT_ * (size_t)E_];
__device__ __nv_bfloat16 d_hnh [BT_ * (size_t)H_];
__device__ __nv_bfloat16 d_uh  [BT_ * (size_t)H_];
// pair-packed bf16 weights
__device__ uint32_t d_Wgp  [(size_t)512 * G4_];
__device__ uint32_t d_downp[(size_t)512 * E_];
__device__ uint32_t d_Wpair[(size_t)512 * 2048];
__device__ uint32_t d_Rgp  [(size_t)NH_ * 64 * 512];

// ---------------- helpers ----------------
__device__ __forceinline__ float gelu_exact(float x) {
    return 0.5f * x * (1.0f + erff(x * 0.70710678118654752440f));
}
__device__ __forceinline__ float sigmoidf_(float x) {
    return 1.0f / (1.0f + expf(-x));
}
__device__ __forceinline__ void cp_async16(uint32_t saddr, const void* g) {
    asm volatile("cp.async.cg.shared.global [%0], [%1], 16;" :: "r"(saddr), "l"(g));
}
__device__ __forceinline__ void mma_bf16(float* acc, uint32_t a0, uint32_t a1,
                                         uint32_t a2, uint32_t a3,
                                         uint32_t b0, uint32_t b1) {
    asm volatile(
        "mma.sync.aligned.m16n8k16.row.col.f32.bf16.bf16.f32 "
        "{%0,%1,%2,%3}, {%4,%5,%6,%7}, {%8,%9}, {%0,%1,%2,%3};"
        : "+f"(acc[0]), "+f"(acc[1]), "+f"(acc[2]), "+f"(acc[3])
        : "r"(a0), "r"(a1), "r"(a2), "r"(a3), "r"(b0), "r"(b1));
}
__device__ __forceinline__ void warp_reduce_2(float& s, float& ss) {
    #pragma unroll
    for (int o = 16; o; o >>= 1) {
        s  += __shfl_xor_sync(0xffffffffu, s,  o);
        ss += __shfl_xor_sync(0xffffffffu, ss, o);
    }
}

// ---------------- GroupNorm -> bf16 ----------------
__global__ __launch_bounds__(256) void groupnorm2(const float* __restrict__ gng,
                                                  const float* __restrict__ gnb) {
    size_t row = blockIdx.x;
    int head = threadIdx.x >> 5, lane = threadIdx.x & 31;
    const float* x = d_h + row * 1024 + head * 128;
    float s = 0.f, ss = 0.f;
    for (int j = lane; j < 128; j += 32) {
        float v = x[j];
        s += v; ss += v * v;
    }
    warp_reduce_2(s, ss);
    float mu  = s * (1.0f / 128.0f);
    float var = ss * (1.0f / 128.0f) - mu * mu;
    float rstd = rsqrtf(var + 1e-5f);
    for (int j = lane; j < 128; j += 32) {
        int ch = head * 128 + j;
        d_hnh[row * 1024 + ch] =
            __float2bfloat16_rn((x[j] - mu) * rstd * gng[ch] + gnb[ch]);
    }
}

// ---------------- weight packs ----------------
__global__ void pack_w(const float* __restrict__ w, uint32_t* __restrict__ out, int N) {
    int n = blockIdx.x * 256 + threadIdx.x;
    int kp = blockIdx.y;
    __nv_bfloat162 h = __floats2bfloat162_rn(w[(size_t)(2 * kp) * N + n],
                                             w[(size_t)(2 * kp + 1) * N + n]);
    out[(size_t)kp * N + n] = *reinterpret_cast<uint32_t*>(&h);
}
__global__ void pack_w_pair(const float* __restrict__ wl, const float* __restrict__ wr,
                            uint32_t* __restrict__ out) {
    int n = blockIdx.x * 256 + threadIdx.x;
    int kp = blockIdx.y;
    __nv_bfloat162 hl = __floats2bfloat162_rn(wl[(size_t)(2 * kp) * 1024 + n],
                                              wl[(size_t)(2 * kp + 1) * 1024 + n]);
    __nv_bfloat162 hr = __floats2bfloat162_rn(wr[(size_t)(2 * kp) * 1024 + n],
                                              wr[(size_t)(2 * kp + 1) * 1024 + n]);
    out[(size_t)kp * 2048 + 2 * n]     = *reinterpret_cast<uint32_t*>(&hl);
    out[(size_t)kp * 2048 + 2 * n + 1] = *reinterpret_cast<uint32_t*>(&hr);
}
__global__ __launch_bounds__(256) void pack_rg(const float* __restrict__ Rg) {
    __shared__ float tile[32][129];
    int head = blockIdx.x;
    int g0 = blockIdx.y * 32;
    int tid = threadIdx.x;
    #pragma unroll
    for (int i = 0; i < 16; i++) {
        int e = i * 256 + tid;
        int r = e >> 7, c = e & 127;
        tile[r][c] = Rg[((size_t)(head * 512 + g0 + r)) * 128 + c];
    }
    __syncthreads();
    #pragma unroll
    for (int i = 0; i < 8; i++) {
        int e = i * 256 + tid;
        int kp = e >> 5, gl = e & 31;
        __nv_bfloat162 h = __floats2bfloat162_rn(tile[gl][2 * kp], tile[gl][2 * kp + 1]);
        d_Rgp[((size_t)(head * 64 + kp)) * 512 + g0 + gl] =
            *reinterpret_cast<uint32_t*>(&h);
    }
}

// ---------------- fused front: LN(x) -> fc1 conv -> fc2 -> LN -> bf16 ----------------
__global__ __launch_bounds__(384) void fused_front(
    const float* __restrict__ x,
    const float* __restrict__ ln_g, const float* __restrict__ ln_b,
    const float* __restrict__ w1g, const float* __restrict__ b1g,
    const float* __restrict__ w2g, const float* __restrict__ b2g,
    const float* __restrict__ xlg, const float* __restrict__ xlb) {
    extern __shared__ float sm[];
    float* sxn = sm;                    // [12][1032], data at +1, halo zeros
    float* sxc = sxn + 12 * 1032;       // [12][1024]
    float* sx1 = sxc + 12 * 1024;       // [12][1024]
    float* sw1 = sx1 + 12 * 1024;       // 432
    float* sw2 = sw1 + 432;             // 144
    float* sb1 = sw2 + 144;             // 12
    float* sb2 = sb1 + 12;              // 12
    int b = blockIdx.x, tid = threadIdx.x, w = tid >> 5, lane = tid & 31;

    for (int i = tid; i < 432; i += 384) sw1[i] = w1g[i];
    if (tid < 144) sw2[tid] = w2g[tid];
    if (tid < 12) { sb1[tid] = b1g[tid]; sb2[tid] = b2g[tid]; }
    if (lane == 0) { sxn[w * 1032] = 0.f; sxn[w * 1032 + 1025] = 0.f; }

    size_t rbase = ((size_t)b * 12 + w) * 1024;
    const float* xr = x + rbase;
    float4 vals[8];
    float s = 0.f, ss = 0.f;
    #pragma unroll
    for (int j = 0; j < 8; j++) {
        float4 v = *reinterpret_cast<const float4*>(xr + lane * 4 + j * 128);
        vals[j] = v;
        s  += v.x + v.y + v.z + v.w;
        ss += v.x*v.x + v.y*v.y + v.z*v.z + v.w*v.w;
    }
    warp_reduce_2(s, ss);
    float mu = s * (1.0f / 1024.0f);
    float rstd = rsqrtf(ss * (1.0f / 1024.0f) - mu * mu + 1e-5f);
    #pragma unroll
    for (int j = 0; j < 8; j++) {
        int idx = lane * 4 + j * 128;
        float4 g = *reinterpret_cast<const float4*>(ln_g + idx);
        float4 bb = *reinterpret_cast<const float4*>(ln_b + idx);
        float4 v = vals[j], o;
        o.x = (v.x - mu) * rstd * g.x + bb.x;
        o.y = (v.y - mu) * rstd * g.y + bb.y;
        o.z = (v.z - mu) * rstd * g.z + bb.z;
        o.w = (v.w - mu) * rstd * g.w + bb.w;
        sxn[w * 1032 + 1 + idx] = o.x; sxn[w * 1032 + 2 + idx] = o.y;
        sxn[w * 1032 + 3 + idx] = o.z; sxn[w * 1032 + 4 + idx] = o.w;
        *reinterpret_cast<float4*>(d_xn + rbase + idx) = o;
    }
    __syncthreads();

    {   // fc1 conv: warp w -> channel w
        int o = w;
        float wl[36];
        #pragma unroll
        for (int i = 0; i < 36; i++) wl[i] = sw1[o * 36 + i];
        float bo = sb1[o];
        for (int j = 0; j < 32; j++) {
            int l = lane + j * 32;
            float a = bo;
            #pragma unroll
            for (int c = 0; c < 12; c++) {
                a += wl[c*3]   * sxn[c * 1032 + l]
                   + wl[c*3+1] * sxn[c * 1032 + l + 1]
                   + wl[c*3+2] * sxn[c * 1032 + l + 2];
            }
            sxc[o * 1024 + l] = a;
            d_xc[rbase + l] = a;
        }
    }
    __syncthreads();

    {   // fc2 1x1
        int o = w;
        float wl[12];
        #pragma unroll
        for (int c = 0; c < 12; c++) wl[c] = sw2[o * 12 + c];
        float bo = sb2[o];
        for (int j = 0; j < 32; j++) {
            int l = lane + j * 32;
            float a = bo;
            #pragma unroll
            for (int c = 0; c < 12; c++) a += wl[c] * sxc[c * 1024 + l];
            sx1[o * 1024 + l] = a;
            d_x1[rbase + l] = a;
        }
    }
    __syncthreads();

    // LN2 -> bf16
    s = 0.f; ss = 0.f;
    #pragma unroll
    for (int j = 0; j < 8; j++) {
        float4 v = *reinterpret_cast<const float4*>(sx1 + w * 1024 + lane * 4 + j * 128);
        vals[j] = v;
        s  += v.x + v.y + v.z + v.w;
        ss += v.x*v.x + v.y*v.y + v.z*v.z + v.w*v.w;
    }
    warp_reduce_2(s, ss);
    mu = s * (1.0f / 1024.0f);
    rstd = rsqrtf(ss * (1.0f / 1024.0f) - mu * mu + 1e-5f);
    #pragma unroll
    for (int j = 0; j < 8; j++) {
        int idx = lane * 4 + j * 128;
        float4 g = *reinterpret_cast<const float4*>(xlg + idx);
        float4 bb = *reinterpret_cast<const float4*>(xlb + idx);
        float4 v = vals[j];
        __nv_bfloat162 h0 = __floats2bfloat162_rn((v.x - mu) * rstd * g.x + bb.x,
                                                  (v.y - mu) * rstd * g.y + bb.y);
        __nv_bfloat162 h1 = __floats2bfloat162_rn((v.z - mu) * rstd * g.z + bb.z,
                                                  (v.w - mu) * rstd * g.w + bb.w);
        uint2 pk = make_uint2(*reinterpret_cast<uint32_t*>(&h0),
                              *reinterpret_cast<uint32_t*>(&h1));
        *reinterpret_cast<uint2*>(d_xn2h + rbase + idx) = pk;
    }
}

// ---------------- fused tail v2: all-fp32, 3 chunks of 16 z-rows ----------------
// one block per batch b; 512 threads = 16 warps; chunk buffer fp32.
__global__ __launch_bounds__(512) void fused_tail(
    const float* __restrict__ w1g, const float* __restrict__ b1g,
    const float* __restrict__ w2g, const float* __restrict__ b2g,
    const float* __restrict__ ln_g, const float* __restrict__ ln_b,
    float* __restrict__ out) {
    extern __shared__ float sm[];
    float* sy  = sm;                   // [12][1032], data at +1, halo zeros
    float* szf = sy + 12 * 1032;       // [16][1032] fp32 chunk, data at +1
    float* sw1 = szf + 16 * 1032;      // 1728 (o,c,k)
    float* sw2 = sw1 + 1728;           // 1728 repacked (c,o,k)
    float* sb1 = sw2 + 1728;           // 48
    float* sb2 = sb1 + 48;             // 12
    int b = blockIdx.x, tid = threadIdx.x, w = tid >> 5, lane = tid & 31;

    for (int i = tid; i < 12 * 256; i += 512) {
        int c = i >> 8, q = (i & 255) * 4;
        float4 v = *reinterpret_cast<const float4*>(d_y + ((size_t)b * 12 + c) * 1024 + q);
        sy[c * 1032 + 1 + q]     = v.x;
        sy[c * 1032 + 1 + q + 1] = v.y;
        sy[c * 1032 + 1 + q + 2] = v.z;
        sy[c * 1032 + 1 + q + 3] = v.w;
    }
    if (tid < 12) { sy[tid * 1032] = 0.f; sy[tid * 1032 + 1025] = 0.f; }
    if (tid < 16) { szf[tid * 1032] = 0.f; szf[tid * 1032 + 1025] = 0.f; }
    for (int i = tid; i < 1728; i += 512) {
        sw1[i] = w1g[i];
        int o = i / 144, rem = i % 144;
        int c = rem / 3, k = rem % 3;
        sw2[c * 36 + o * 3 + k] = w2g[i];
    }
    if (tid < 48) sb1[tid] = b1g[tid];
    if (tid < 12) sb2[tid] = b2g[tid];
    __syncthreads();

    int l2 = tid * 2;
    float acc0[12], acc1[12];
    #pragma unroll
    for (int o = 0; o < 12; o++) { acc0[o] = 0.f; acc1[o] = 0.f; }

    for (int cc = 0; cc < 3; cc++) {
        // Phase A: warp w computes z row o = cc*16+w: conv12->48, gelu (fp32 regs),
        // warp stats, LN apply, store fp32 normalized to szf.
        int o = cc * 16 + w;
        float wl[36];
        #pragma unroll
        for (int i = 0; i < 36; i++) wl[i] = sw1[o * 36 + i];
        float bo = sb1[o];
        float vbuf[32];
        float s = 0.f, ss = 0.f;
        #pragma unroll 4
        for (int j = 0; j < 32; j++) {
            int l = lane + j * 32;
            float a = bo;
            #pragma unroll
            for (int c = 0; c < 12; c++) {
                a += wl[c*3]   * sy[c * 1032 + l]
                   + wl[c*3+1] * sy[c * 1032 + l + 1]
                   + wl[c*3+2] * sy[c * 1032 + l + 2];
            }
            float v = gelu_exact(a);
            vbuf[j] = v;
            s += v; ss += v * v;
        }
        warp_reduce_2(s, ss);
        float mu = s * (1.0f / 1024.0f);
        float rstd = rsqrtf(ss * (1.0f / 1024.0f) - mu * mu + 1e-5f);
        #pragma unroll 4
        for (int j = 0; j < 32; j++) {
            int l = lane + j * 32;
            szf[w * 1032 + 1 + l] =
                (vbuf[j] - mu) * rstd * __ldg(ln_g + l) + __ldg(ln_b + l);
        }
        __syncthreads();

        // Phase B: conv48->12 partial accumulation over this chunk's 16 rows
        for (int c16 = 0; c16 < 16; c16++) {
            int c = cc * 16 + c16;
            const float* zr = szf + c16 * 1032 + l2;   // positions l2-1..l2+2
            float2 p0 = *reinterpret_cast<const float2*>(zr);
            float2 p1 = *reinterpret_cast<const float2*>(zr + 2);
            float h0 = p0.x, h1 = p0.y, h2 = p1.x, h3 = p1.y;
            const float* wr = sw2 + c * 36;
            #pragma unroll
            for (int o2 = 0; o2 < 12; o2++) {
                float w0 = wr[o2*3], w1 = wr[o2*3+1], w2v = wr[o2*3+2];
                acc0[o2] += w0 * h0 + w1 * h1 + w2v * h2;
                acc1[o2] += w0 * h1 + w1 * h2 + w2v * h3;
            }
        }
        __syncthreads();
    }

    #pragma unroll
    for (int o = 0; o < 12; o++) {
        size_t idx = ((size_t)b * 12 + o) * 1024 + l2;
        float2 sk = *reinterpret_cast<const float2*>(d_xn + idx);
        float2 ov;
        ov.x = acc0[o] + sb2[o] + sk.x;
        ov.y = acc1[o] + sb2[o] + sk.y;
        *reinterpret_cast<float2*>(out + idx) = ov;
    }
}

// ---------------- bf16 tensor-core GEMM ----------------
// MODE 2: C(fp32) = silu(aux0) * (acc + bias + aux1) + aux2
// MODE 3: interleaved pair: C(bf16)[r][c/2] = gelu(accL+bias) * (accR+aux1)
// MODE 4: C(bf16) = acc + bias
template<int MODE>
__global__ __launch_bounds__(256) void gemm_bf16(int N, int K,
                                                 const __nv_bfloat16* __restrict__ A,
                                                 const uint32_t* __restrict__ Bp,
                                                 const float* __restrict__ bias,
                                                 const float* __restrict__ aux0,
                                                 const float* __restrict__ aux1,
                                                 const float* __restrict__ aux2,
                                                 void* __restrict__ Cout) {
    __shared__ uint32_t As[2][128 * 20];
    __shared__ uint32_t Bs[2][16 * 136];
    int tid = threadIdx.x;
    int warp = tid >> 5, lane = tid & 31;
    int g = lane >> 2, tg = lane & 3;
    int warpM = warp >> 2, warpN = warp & 3;
    int row0 = blockIdx.y * 128, col0 = blockIdx.x * 128;

    uint32_t asb = (uint32_t)__cvta_generic_to_shared(&As[0][0]);
    uint32_t bsb = (uint32_t)__cvta_generic_to_shared(&Bs[0][0]);

    float acc[4][4][4];
    #pragma unroll
    for (int m = 0; m < 4; m++)
        #pragma unroll
        for (int n = 0; n < 4; n++)
            #pragma unroll
            for (int q = 0; q < 4; q++) acc[m][n][q] = 0.f;

    const int nt = K >> 5;

    auto load_tile = [&](int it, int buf) {
        int k0 = it << 5;
        int kp0 = it << 4;
        #pragma unroll
        for (int i = 0; i < 2; i++) {
            int e = i * 256 + tid;
            int r = e >> 2, ch = e & 3;
            cp_async16(asb + (uint32_t)(buf * 128 * 20 + r * 20 + ch * 4) * 4,
                       A + (size_t)(row0 + r) * K + k0 + ch * 8);
        }
        #pragma unroll
        for (int i = 0; i < 2; i++) {
            int e = i * 256 + tid;
            int kp = e >> 5, c = (e & 31) * 4;
            cp_async16(bsb + (uint32_t)(buf * 16 * 136 + kp * 136 + c) * 4,
                       Bp + (size_t)(kp0 + kp) * N + col0 + c);
        }
        asm volatile("cp.async.commit_group;");
    };

    load_tile(0, 0);
    for (int it = 0; it < nt; it++) {
        int buf = it & 1;
        if (it + 1 < nt) {
            load_tile(it + 1, buf ^ 1);
            asm volatile("cp.async.wait_group 1;");
        } else {
            asm volatile("cp.async.wait_group 0;");
        }
        __syncthreads();
        const uint32_t* Ab = &As[buf][0];
        const uint32_t* Bb = &Bs[buf][0];
        #pragma unroll
        for (int s = 0; s < 2; s++) {
            uint32_t af[4][4];
            #pragma unroll
            for (int m = 0; m < 4; m++) {
                int r = warpM * 64 + m * 16;
                af[m][0] = Ab[(r + g)     * 20 + s * 8 + tg];
                af[m][1] = Ab[(r + 8 + g) * 20 + s * 8 + tg];
                af[m][2] = Ab[(r + g)     * 20 + s * 8 + tg + 4];
                af[m][3] = Ab[(r + 8 + g) * 20 + s * 8 + tg + 4];
            }
            uint32_t bf[4][2];
            #pragma unroll
            for (int n = 0; n < 4; n++) {
                int c = warpN * 32 + n * 8 + g;
                bf[n][0] = Bb[(s * 8 + tg)     * 136 + c];
                bf[n][1] = Bb[(s * 8 + tg + 4) * 136 + c];
            }
            #pragma unroll
            for (int m = 0; m < 4; m++)
                #pragma unroll
                for (int n = 0; n < 4; n++)
                    mma_bf16(acc[m][n], af[m][0], af[m][1], af[m][2], af[m][3],
                             bf[n][0], bf[n][1]);
        }
        __syncthreads();
    }

    #pragma unroll
    for (int m = 0; m < 4; m++) {
        int r = row0 + warpM * 64 + m * 16 + g;
        #pragma unroll
        for (int n = 0; n < 4; n++) {
            int c = col0 + warpN * 32 + n * 8 + 2 * tg;
            #pragma unroll
            for (int half = 0; half < 2; half++) {
                int rr = r + half * 8;
                float a0 = acc[m][n][half * 2 + 0];
                float a1 = acc[m][n][half * 2 + 1];
                if (MODE == 3) {
                    int j = c >> 1;
                    float l  = a0 + bias[j];
                    float rv = a1 + aux1[j];
                    ((__nv_bfloat16*)Cout)[(size_t)rr * (N >> 1) + j] =
                        __float2bfloat16_rn(gelu_exact(l) * rv);
                } else if (MODE == 4) {
                    size_t i0 = (size_t)rr * N + c;
                    __nv_bfloat162 hh = __floats2bfloat162_rn(a0 + bias[c],
                                                              a1 + bias[c + 1]);
                    *reinterpret_cast<uint32_t*>((__nv_bfloat16*)Cout + i0) =
                        *reinterpret_cast<uint32_t*>(&hh);
                } else {
                    size_t i0 = (size_t)rr * N + c;
                    float v0 = a0 + bias[c];
                    float v1 = a1 + bias[c + 1];
                    if (MODE == 2) {
                        float x0 = aux0[i0], x1v = aux0[i0 + 1];
                        v0 = x0  * sigmoidf_(x0)  * (v0 + aux1[i0])     + aux2[i0];
                        v1 = x1v * sigmoidf_(x1v) * (v1 + aux1[i0 + 1]) + aux2[i0 + 1];
                    }
                    *reinterpret_cast<float2*>((float*)Cout + i0) = make_float2(v0, v1);
                }
            }
        }
    }
}

// ---------------- sLSTM recurrence v3 (gx now bf16) ----------------
__global__ __launch_bounds__(256) void slstm_rec3() {
    extern __shared__ uint32_t smw[];
    uint32_t* sBp = smw;                                  // [64][520]
    float* s_rec = (float*)(smw + 64 * 520);              // [32][516]
    uint32_t* sh_w = (uint32_t*)(s_rec + 32 * 516);       // [32][68]
    __nv_bfloat16* sh_h = (__nv_bfloat16*)sh_w;

    int head = blockIdx.x >> 4;
    int b0 = (blockIdx.x & 15) << 5;
    int tid = threadIdx.x;
    int warp = tid >> 5, lane = tid & 31;
    int g = lane >> 2, tg = lane & 3;
    int wm = warp >> 2, wn = warp & 3;

    uint32_t sb = (uint32_t)__cvta_generic_to_shared(sBp);
    const uint32_t* Bg = d_Rgp + (size_t)head * (64 * 512);
    #pragma unroll
    for (int i = 0; i < 32; i++) {
        int e = i * 256 + tid;
        int kp = e >> 7, c = (e & 127) * 4;
        cp_async16(sb + (uint32_t)(kp * 520 + c) * 4, Bg + (size_t)kp * 512 + c);
    }
    asm volatile("cp.async.commit_group;");
    for (int i = tid; i < 32 * 68; i += 256) sh_w[i] = 0;
    float cS[16], nS[16], mS[16];
    #pragma unroll
    for (int j = 0; j < 16; j++) { cS[j] = 0.f; nS[j] = 0.f; mS[j] = 0.f; }
    asm volatile("cp.async.wait_group 0;");
    __syncthreads();

    for (int t = 0; t < 12; t++) {
        float acc[16][4];
        #pragma unroll
        for (int j = 0; j < 16; j++)
            #pragma unroll
            for (int q = 0; q < 4; q++) acc[j][q] = 0.f;
        #pragma unroll
        for (int s = 0; s < 8; s++) {
            uint32_t a0 = sh_w[(wm * 16 + g)     * 68 + s * 8 + tg];
            uint32_t a1 = sh_w[(wm * 16 + 8 + g) * 68 + s * 8 + tg];
            uint32_t a2 = sh_w[(wm * 16 + g)     * 68 + s * 8 + tg + 4];
            uint32_t a3 = sh_w[(wm * 16 + 8 + g) * 68 + s * 8 + tg + 4];
            #pragma unroll
            for (int j = 0; j < 16; j++) {
                int c = wn * 128 + j * 8 + g;
                uint32_t b0v = sBp[(s * 8 + tg)     * 520 + c];
                uint32_t b1v = sBp[(s * 8 + tg + 4) * 520 + c];
                mma_bf16(acc[j], a0, a1, a2, a3, b0v, b1v);
            }
        }
        #pragma unroll
        for (int j = 0; j < 16; j++) {
            int c = wn * 128 + j * 8 + 2 * tg;
            int r = wm * 16 + g;
            s_rec[r * 516 + c]           = acc[j][0];
            s_rec[r * 516 + c + 1]       = acc[j][1];
            s_rec[(r + 8) * 516 + c]     = acc[j][2];
            s_rec[(r + 8) * 516 + c + 1] = acc[j][3];
        }
        __syncthreads();
        #pragma unroll
        for (int it = 0; it < 16; it++) {
            int idx = it * 256 + tid;
            int bb = idx >> 7, hs = idx & 127;
            int b = b0 + bb;
            const __nv_bfloat16* gxp =
                d_gxh + (size_t)(b * 12 + t) * 4096 + head * 512;
            const float* rp = s_rec + bb * 516;
            float z_ = __bfloat162float(gxp[hs])       + rp[hs];
            float i_ = __bfloat162float(gxp[128 + hs]) + rp[128 + hs];
            float f_ = __bfloat162float(gxp[256 + hs]) + rp[256 + hs];
            float o_ = __bfloat162float(gxp[384 + hs]) + rp[384 + hs];
            float z  = tanhf(z_);
            float o  = sigmoidf_(o_);
            float mo = mS[it];
            float mn = fmaxf(f_ + mo, i_);
            float iv = expf(i_ - mn);
            float fv = expf(f_ + mo - mn);
            float cv = fv * cS[it] + iv * z;
            float nv = fv * nS[it] + iv;
            float hv = o * (cv / nv);
            cS[it] = cv; nS[it] = nv; mS[it] = mn;
            sh_h[bb * 136 + hs] = __float2bfloat16_rn(hv);
            d_h[(size_t)((b * 12 + t) * 8 + head) * 128 + hs] = hv;
        }
        __syncthreads();
    }
}

// ---------------- launch ----------------
extern "C" void kernel_launch(void* const* d_in, const int* in_sizes, int n_in,
                              void* d_out, int out_size) {
    const float* x       = (const float*)d_in[0];
    const float* ln_g    = (const float*)d_in[1];
    const float* ln_b    = (const float*)d_in[2];
    const float* fc1_w   = (const float*)d_in[3];
    const float* fc1_b   = (const float*)d_in[4];
    const float* fc2_w   = (const float*)d_in[5];
    const float* fc2_b   = (const float*)d_in[6];
    const float* conv1_w = (const float*)d_in[7];
    const float* conv1_b = (const float*)d_in[8];
    const float* conv2_w = (const float*)d_in[9];
    const float* conv2_b = (const float*)d_in[10];
    const float* xlg     = (const float*)d_in[11];
    const float* xlb     = (const float*)d_in[12];
    const float* Wg      = (const float*)d_in[13];
    const float* bg      = (const float*)d_in[14];
    const float* Rg      = (const float*)d_in[15];
    const float* gng     = (const float*)d_in[16];
    const float* gnb     = (const float*)d_in[17];
    const float* uplw    = (const float*)d_in[18];
    const float* uplb    = (const float*)d_in[19];
    const float* uprw    = (const float*)d_in[20];
    const float* uprb    = (const float*)d_in[21];
    const float* downw   = (const float*)d_in[22];
    const float* downb   = (const float*)d_in[23];
    float* out = (float*)d_out;

    cudaFuncSetAttribute(slstm_rec3,  cudaFuncAttributeMaxDynamicSharedMemorySize, 207872);
    cudaFuncSetAttribute(fused_front, cudaFuncAttributeMaxDynamicSharedMemorySize, 150240);
    cudaFuncSetAttribute(fused_tail,  cudaFuncAttributeMaxDynamicSharedMemorySize, 129648);

    float *p_xn, *p_xc, *p_x1, *p_y;
    __nv_bfloat16 *p_gxh, *p_xn2h, *p_hnh, *p_uh;
    uint32_t *p_Wgp, *p_downp, *p_Wpair;
    cudaGetSymbolAddress((void**)&p_xn,    d_xn);
    cudaGetSymbolAddress((void**)&p_xc,    d_xc);
    cudaGetSymbolAddress((void**)&p_x1,    d_x1);
    cudaGetSymbolAddress((void**)&p_y,     d_y);
    cudaGetSymbolAddress((void**)&p_gxh,   d_gxh);
    cudaGetSymbolAddress((void**)&p_xn2h,  d_xn2h);
    cudaGetSymbolAddress((void**)&p_hnh,   d_hnh);
    cudaGetSymbolAddress((void**)&p_uh,    d_uh);
    cudaGetSymbolAddress((void**)&p_Wgp,   d_Wgp);
    cudaGetSymbolAddress((void**)&p_downp, d_downp);
    cudaGetSymbolAddress((void**)&p_Wpair, d_Wpair);

    pack_w<<<dim3(16, 512), 256>>>(Wg,    p_Wgp,   4096);
    pack_w<<<dim3(4, 512),  256>>>(downw, p_downp, 1024);
    pack_w_pair<<<dim3(4, 512), 256>>>(uplw, uprw, p_Wpair);
    pack_rg<<<dim3(8, 16), 256>>>(Rg);

    // LN(x) -> fc1 -> fc2 -> LN -> bf16   [fused per batch]
    fused_front<<<B_, 384, 150240>>>(x, ln_g, ln_b, fc1_w, fc1_b,
                                     fc2_w, fc2_b, xlg, xlb);
    // gx = xn2 @ Wg + bg  -> bf16
    gemm_bf16<4><<<dim3(32, 48), 256>>>(4096, 1024, p_xn2h, p_Wgp, bg,
                                        nullptr, nullptr, nullptr, p_gxh);
    // sLSTM recurrence -> d_h
    slstm_rec3<<<128, 256, 207872>>>();
    // per-head GroupNorm -> bf16 hn
    groupnorm2<<<BT_, 256>>>(gng, gnb);
    // u = gelu(hn@upl + uplb) * (hn@upr + uprb)
    gemm_bf16<3><<<dim3(16, 48), 256>>>(2048, 1024, p_hnh, p_Wpair, uplb,
                                        nullptr, uprb, nullptr, p_uh);
    // y = silu(xc) * (u @ down + downb + x1) + xn
    gemm_bf16<2><<<dim3(8, 48), 256>>>(1024, 1024, p_uh, p_downp, downb,
                                       p_xc, p_x1, p_xn, p_y);
    // conv12->48 + gelu + LN + conv48->12 + skip   [fused, fp32 throughout]
    fused_tail<<<B_, 512, 129648>>>(conv1_w, conv1_b, conv2_w, conv2_b,
                                    ln_g, ln_b, out);
}

// round 12
// speedup vs baseline: 3.8277x; 1.0263x over previous
#include <cuda_runtime.h>
#include <cuda_bf16.h>
#include <cmath>
#include <cstdint>

// ---------------- problem constants ----------------
static constexpr int B_   = 512;
static constexpr int T_   = 12;
static constexpr int E_   = 1024;
static constexpr int NH_  = 8;
static constexpr int HS_  = 128;
static constexpr int H_   = 1024;
static constexpr int G4_  = 4096;
static constexpr int BT_  = B_ * T_;        // 6144

// ---------------- scratch (device globals; no allocation) ----------------
__device__ float d_xn [BT_ * (size_t)E_];
__device__ float d_xc [BT_ * (size_t)E_];
__device__ float d_x1 [BT_ * (size_t)E_];
__device__ float d_y  [BT_ * (size_t)E_];
// bf16 operands
__device__ __nv_bfloat16 d_gxh [BT_ * (size_t)G4_];
__device__ __nv_bfloat16 d_xn2h[BT_ * (size_t)E_];
__device__ __nv_bfloat16 d_hnh [BT_ * (size_t)H_];
__device__ __nv_bfloat16 d_uh  [BT_ * (size_t)H_];
// pair-packed bf16 weights
__device__ uint32_t d_Wgp  [(size_t)512 * G4_];
__device__ uint32_t d_downp[(size_t)512 * E_];
__device__ uint32_t d_Wpair[(size_t)512 * 2048];
__device__ uint32_t d_Rgp  [(size_t)NH_ * 64 * 512];

// ---------------- helpers ----------------
__device__ __forceinline__ float gelu_exact(float x) {
    return 0.5f * x * (1.0f + erff(x * 0.70710678118654752440f));
}
__device__ __forceinline__ float sigmoidf_(float x) {
    return 1.0f / (1.0f + expf(-x));
}
__device__ __forceinline__ void cp_async16(uint32_t saddr, const void* g) {
    asm volatile("cp.async.cg.shared.global [%0], [%1], 16;" :: "r"(saddr), "l"(g));
}
__device__ __forceinline__ void mma_bf16(float* acc, uint32_t a0, uint32_t a1,
                                         uint32_t a2, uint32_t a3,
                                         uint32_t b0, uint32_t b1) {
    asm volatile(
        "mma.sync.aligned.m16n8k16.row.col.f32.bf16.bf16.f32 "
        "{%0,%1,%2,%3}, {%4,%5,%6,%7}, {%8,%9}, {%0,%1,%2,%3};"
        : "+f"(acc[0]), "+f"(acc[1]), "+f"(acc[2]), "+f"(acc[3])
        : "r"(a0), "r"(a1), "r"(a2), "r"(a3), "r"(b0), "r"(b1));
}
__device__ __forceinline__ void warp_reduce_2(float& s, float& ss) {
    #pragma unroll
    for (int o = 16; o; o >>= 1) {
        s  += __shfl_xor_sync(0xffffffffu, s,  o);
        ss += __shfl_xor_sync(0xffffffffu, ss, o);
    }
}

// ---------------- combined weight packs (one launch) ----------------
__global__ void pack_all(const float* __restrict__ Wg,
                         const float* __restrict__ downw,
                         const float* __restrict__ wl,
                         const float* __restrict__ wr) {
    int z = blockIdx.z;
    int kp = blockIdx.y;
    int n = blockIdx.x * 256 + threadIdx.x;
    if (z == 0) {                 // Wg: N=4096
        __nv_bfloat162 h = __floats2bfloat162_rn(Wg[(size_t)(2 * kp) * 4096 + n],
                                                 Wg[(size_t)(2 * kp + 1) * 4096 + n]);
        d_Wgp[(size_t)kp * 4096 + n] = *reinterpret_cast<uint32_t*>(&h);
    } else if (z == 1) {          // down: N=1024
        if (blockIdx.x >= 4) return;
        __nv_bfloat162 h = __floats2bfloat162_rn(downw[(size_t)(2 * kp) * 1024 + n],
                                                 downw[(size_t)(2 * kp + 1) * 1024 + n]);
        d_downp[(size_t)kp * 1024 + n] = *reinterpret_cast<uint32_t*>(&h);
    } else {                      // interleaved upl/upr
        if (blockIdx.x >= 4) return;
        __nv_bfloat162 hl = __floats2bfloat162_rn(wl[(size_t)(2 * kp) * 1024 + n],
                                                  wl[(size_t)(2 * kp + 1) * 1024 + n]);
        __nv_bfloat162 hr = __floats2bfloat162_rn(wr[(size_t)(2 * kp) * 1024 + n],
                                                  wr[(size_t)(2 * kp + 1) * 1024 + n]);
        d_Wpair[(size_t)kp * 2048 + 2 * n]     = *reinterpret_cast<uint32_t*>(&hl);
        d_Wpair[(size_t)kp * 2048 + 2 * n + 1] = *reinterpret_cast<uint32_t*>(&hr);
    }
}
__global__ __launch_bounds__(256) void pack_rg(const float* __restrict__ Rg) {
    __shared__ float tile[32][129];
    int head = blockIdx.x;
    int g0 = blockIdx.y * 32;
    int tid = threadIdx.x;
    #pragma unroll
    for (int i = 0; i < 16; i++) {
        int e = i * 256 + tid;
        int r = e >> 7, c = e & 127;
        tile[r][c] = Rg[((size_t)(head * 512 + g0 + r)) * 128 + c];
    }
    __syncthreads();
    #pragma unroll
    for (int i = 0; i < 8; i++) {
        int e = i * 256 + tid;
        int kp = e >> 5, gl = e & 31;
        __nv_bfloat162 h = __floats2bfloat162_rn(tile[gl][2 * kp], tile[gl][2 * kp + 1]);
        d_Rgp[((size_t)(head * 64 + kp)) * 512 + g0 + gl] =
            *reinterpret_cast<uint32_t*>(&h);
    }
}

// ---------------- fused front: LN(x) -> fc1 conv -> fc2 -> LN -> bf16 ----------------
__global__ __launch_bounds__(384) void fused_front(
    const float* __restrict__ x,
    const float* __restrict__ ln_g, const float* __restrict__ ln_b,
    const float* __restrict__ w1g, const float* __restrict__ b1g,
    const float* __restrict__ w2g, const float* __restrict__ b2g,
    const float* __restrict__ xlg, const float* __restrict__ xlb) {
    extern __shared__ float sm[];
    float* sxn = sm;                    // [12][1032], data at +1, halo zeros
    float* sxc = sxn + 12 * 1032;       // [12][1024]
    float* sx1 = sxc + 12 * 1024;       // [12][1024]
    float* sw1 = sx1 + 12 * 1024;       // 432
    float* sw2 = sw1 + 432;             // 144
    float* sb1 = sw2 + 144;             // 12
    float* sb2 = sb1 + 12;              // 12
    int b = blockIdx.x, tid = threadIdx.x, w = tid >> 5, lane = tid & 31;

    for (int i = tid; i < 432; i += 384) sw1[i] = w1g[i];
    if (tid < 144) sw2[tid] = w2g[tid];
    if (tid < 12) { sb1[tid] = b1g[tid]; sb2[tid] = b2g[tid]; }
    if (lane == 0) { sxn[w * 1032] = 0.f; sxn[w * 1032 + 1025] = 0.f; }

    size_t rbase = ((size_t)b * 12 + w) * 1024;
    const float* xr = x + rbase;
    float4 vals[8];
    float s = 0.f, ss = 0.f;
    #pragma unroll
    for (int j = 0; j < 8; j++) {
        float4 v = *reinterpret_cast<const float4*>(xr + lane * 4 + j * 128);
        vals[j] = v;
        s  += v.x + v.y + v.z + v.w;
        ss += v.x*v.x + v.y*v.y + v.z*v.z + v.w*v.w;
    }
    warp_reduce_2(s, ss);
    float mu = s * (1.0f / 1024.0f);
    float rstd = rsqrtf(ss * (1.0f / 1024.0f) - mu * mu + 1e-5f);
    #pragma unroll
    for (int j = 0; j < 8; j++) {
        int idx = lane * 4 + j * 128;
        float4 g = *reinterpret_cast<const float4*>(ln_g + idx);
        float4 bb = *reinterpret_cast<const float4*>(ln_b + idx);
        float4 v = vals[j], o;
        o.x = (v.x - mu) * rstd * g.x + bb.x;
        o.y = (v.y - mu) * rstd * g.y + bb.y;
        o.z = (v.z - mu) * rstd * g.z + bb.z;
        o.w = (v.w - mu) * rstd * g.w + bb.w;
        sxn[w * 1032 + 1 + idx] = o.x; sxn[w * 1032 + 2 + idx] = o.y;
        sxn[w * 1032 + 3 + idx] = o.z; sxn[w * 1032 + 4 + idx] = o.w;
        *reinterpret_cast<float4*>(d_xn + rbase + idx) = o;
    }
    __syncthreads();

    {   // fc1 conv: warp w -> channel w
        int o = w;
        float wl[36];
        #pragma unroll
        for (int i = 0; i < 36; i++) wl[i] = sw1[o * 36 + i];
        float bo = sb1[o];
        for (int j = 0; j < 32; j++) {
            int l = lane + j * 32;
            float a = bo;
            #pragma unroll
            for (int c = 0; c < 12; c++) {
                a += wl[c*3]   * sxn[c * 1032 + l]
                   + wl[c*3+1] * sxn[c * 1032 + l + 1]
                   + wl[c*3+2] * sxn[c * 1032 + l + 2];
            }
            sxc[o * 1024 + l] = a;
            d_xc[rbase + l] = a;
        }
    }
    __syncthreads();

    {   // fc2 1x1
        int o = w;
        float wl[12];
        #pragma unroll
        for (int c = 0; c < 12; c++) wl[c] = sw2[o * 12 + c];
        float bo = sb2[o];
        for (int j = 0; j < 32; j++) {
            int l = lane + j * 32;
            float a = bo;
            #pragma unroll
            for (int c = 0; c < 12; c++) a += wl[c] * sxc[c * 1024 + l];
            sx1[o * 1024 + l] = a;
            d_x1[rbase + l] = a;
        }
    }
    __syncthreads();

    // LN2 -> bf16
    s = 0.f; ss = 0.f;
    #pragma unroll
    for (int j = 0; j < 8; j++) {
        float4 v = *reinterpret_cast<const float4*>(sx1 + w * 1024 + lane * 4 + j * 128);
        vals[j] = v;
        s  += v.x + v.y + v.z + v.w;
        ss += v.x*v.x + v.y*v.y + v.z*v.z + v.w*v.w;
    }
    warp_reduce_2(s, ss);
    mu = s * (1.0f / 1024.0f);
    rstd = rsqrtf(ss * (1.0f / 1024.0f) - mu * mu + 1e-5f);
    #pragma unroll
    for (int j = 0; j < 8; j++) {
        int idx = lane * 4 + j * 128;
        float4 g = *reinterpret_cast<const float4*>(xlg + idx);
        float4 bb = *reinterpret_cast<const float4*>(xlb + idx);
        float4 v = vals[j];
        __nv_bfloat162 h0 = __floats2bfloat162_rn((v.x - mu) * rstd * g.x + bb.x,
                                                  (v.y - mu) * rstd * g.y + bb.y);
        __nv_bfloat162 h1 = __floats2bfloat162_rn((v.z - mu) * rstd * g.z + bb.z,
                                                  (v.w - mu) * rstd * g.w + bb.w);
        uint2 pk = make_uint2(*reinterpret_cast<uint32_t*>(&h0),
                              *reinterpret_cast<uint32_t*>(&h1));
        *reinterpret_cast<uint2*>(d_xn2h + rbase + idx) = pk;
    }
}

// ---------------- fused tail v2: all-fp32, 3 chunks of 16 z-rows ----------------
__global__ __launch_bounds__(512) void fused_tail(
    const float* __restrict__ w1g, const float* __restrict__ b1g,
    const float* __restrict__ w2g, const float* __restrict__ b2g,
    const float* __restrict__ ln_g, const float* __restrict__ ln_b,
    float* __restrict__ out) {
    extern __shared__ float sm[];
    float* sy  = sm;                   // [12][1032], data at +1, halo zeros
    float* szf = sy + 12 * 1032;       // [16][1032] fp32 chunk, data at +1
    float* sw1 = szf + 16 * 1032;      // 1728 (o,c,k)
    float* sw2 = sw1 + 1728;           // 1728 repacked (c,o,k)
    float* sb1 = sw2 + 1728;           // 48
    float* sb2 = sb1 + 48;             // 12
    int b = blockIdx.x, tid = threadIdx.x, w = tid >> 5, lane = tid & 31;

    for (int i = tid; i < 12 * 256; i += 512) {
        int c = i >> 8, q = (i & 255) * 4;
        float4 v = *reinterpret_cast<const float4*>(d_y + ((size_t)b * 12 + c) * 1024 + q);
        sy[c * 1032 + 1 + q]     = v.x;
        sy[c * 1032 + 1 + q + 1] = v.y;
        sy[c * 1032 + 1 + q + 2] = v.z;
        sy[c * 1032 + 1 + q + 3] = v.w;
    }
    if (tid < 12) { sy[tid * 1032] = 0.f; sy[tid * 1032 + 1025] = 0.f; }
    if (tid < 16) { szf[tid * 1032] = 0.f; szf[tid * 1032 + 1025] = 0.f; }
    for (int i = tid; i < 1728; i += 512) {
        sw1[i] = w1g[i];
        int o = i / 144, rem = i % 144;
        int c = rem / 3, k = rem % 3;
        sw2[c * 36 + o * 3 + k] = w2g[i];
    }
    if (tid < 48) sb1[tid] = b1g[tid];
    if (tid < 12) sb2[tid] = b2g[tid];
    __syncthreads();

    int l2 = tid * 2;
    float acc0[12], acc1[12];
    #pragma unroll
    for (int o = 0; o < 12; o++) { acc0[o] = 0.f; acc1[o] = 0.f; }

    for (int cc = 0; cc < 3; cc++) {
        int o = cc * 16 + w;
        float wl[36];
        #pragma unroll
        for (int i = 0; i < 36; i++) wl[i] = sw1[o * 36 + i];
        float bo = sb1[o];
        float vbuf[32];
        float s = 0.f, ss = 0.f;
        #pragma unroll 4
        for (int j = 0; j < 32; j++) {
            int l = lane + j * 32;
            float a = bo;
            #pragma unroll
            for (int c = 0; c < 12; c++) {
                a += wl[c*3]   * sy[c * 1032 + l]
                   + wl[c*3+1] * sy[c * 1032 + l + 1]
                   + wl[c*3+2] * sy[c * 1032 + l + 2];
            }
            float v = gelu_exact(a);
            vbuf[j] = v;
            s += v; ss += v * v;
        }
        warp_reduce_2(s, ss);
        float mu = s * (1.0f / 1024.0f);
        float rstd = rsqrtf(ss * (1.0f / 1024.0f) - mu * mu + 1e-5f);
        #pragma unroll 4
        for (int j = 0; j < 32; j++) {
            int l = lane + j * 32;
            szf[w * 1032 + 1 + l] =
                (vbuf[j] - mu) * rstd * __ldg(ln_g + l) + __ldg(ln_b + l);
        }
        __syncthreads();

        for (int c16 = 0; c16 < 16; c16++) {
            int c = cc * 16 + c16;
            const float* zr = szf + c16 * 1032 + l2;
            float2 p0 = *reinterpret_cast<const float2*>(zr);
            float2 p1 = *reinterpret_cast<const float2*>(zr + 2);
            float h0 = p0.x, h1 = p0.y, h2 = p1.x, h3 = p1.y;
            const float* wr = sw2 + c * 36;
            #pragma unroll
            for (int o2 = 0; o2 < 12; o2++) {
                float w0 = wr[o2*3], w1 = wr[o2*3+1], w2v = wr[o2*3+2];
                acc0[o2] += w0 * h0 + w1 * h1 + w2v * h2;
                acc1[o2] += w0 * h1 + w1 * h2 + w2v * h3;
            }
        }
        __syncthreads();
    }

    #pragma unroll
    for (int o = 0; o < 12; o++) {
        size_t idx = ((size_t)b * 12 + o) * 1024 + l2;
        float2 sk = *reinterpret_cast<const float2*>(d_xn + idx);
        float2 ov;
        ov.x = acc0[o] + sb2[o] + sk.x;
        ov.y = acc1[o] + sb2[o] + sk.y;
        *reinterpret_cast<float2*>(out + idx) = ov;
    }
}

// ---------------- bf16 tensor-core GEMM ----------------
// MODE 2: C(fp32) = silu(aux0) * (acc + bias + aux1) + aux2
// MODE 3: interleaved pair: C(bf16)[r][c/2] = gelu(accL+bias) * (accR+aux1)
// MODE 4: C(bf16) = acc + bias
template<int MODE>
__global__ __launch_bounds__(256) void gemm_bf16(int N, int K,
                                                 const __nv_bfloat16* __restrict__ A,
                                                 const uint32_t* __restrict__ Bp,
                                                 const float* __restrict__ bias,
                                                 const float* __restrict__ aux0,
                                                 const float* __restrict__ aux1,
                                                 const float* __restrict__ aux2,
                                                 void* __restrict__ Cout) {
    __shared__ uint32_t As[2][128 * 20];
    __shared__ uint32_t Bs[2][16 * 136];
    int tid = threadIdx.x;
    int warp = tid >> 5, lane = tid & 31;
    int g = lane >> 2, tg = lane & 3;
    int warpM = warp >> 2, warpN = warp & 3;
    int row0 = blockIdx.y * 128, col0 = blockIdx.x * 128;

    uint32_t asb = (uint32_t)__cvta_generic_to_shared(&As[0][0]);
    uint32_t bsb = (uint32_t)__cvta_generic_to_shared(&Bs[0][0]);

    float acc[4][4][4];
    #pragma unroll
    for (int m = 0; m < 4; m++)
        #pragma unroll
        for (int n = 0; n < 4; n++)
            #pragma unroll
            for (int q = 0; q < 4; q++) acc[m][n][q] = 0.f;

    const int nt = K >> 5;

    auto load_tile = [&](int it, int buf) {
        int k0 = it << 5;
        int kp0 = it << 4;
        #pragma unroll
        for (int i = 0; i < 2; i++) {
            int e = i * 256 + tid;
            int r = e >> 2, ch = e & 3;
            cp_async16(asb + (uint32_t)(buf * 128 * 20 + r * 20 + ch * 4) * 4,
                       A + (size_t)(row0 + r) * K + k0 + ch * 8);
        }
        #pragma unroll
        for (int i = 0; i < 2; i++) {
            int e = i * 256 + tid;
            int kp = e >> 5, c = (e & 31) * 4;
            cp_async16(bsb + (uint32_t)(buf * 16 * 136 + kp * 136 + c) * 4,
                       Bp + (size_t)(kp0 + kp) * N + col0 + c);
        }
        asm volatile("cp.async.commit_group;");
    };

    load_tile(0, 0);
    for (int it = 0; it < nt; it++) {
        int buf = it & 1;
        if (it + 1 < nt) {
            load_tile(it + 1, buf ^ 1);
            asm volatile("cp.async.wait_group 1;");
        } else {
            asm volatile("cp.async.wait_group 0;");
        }
        __syncthreads();
        const uint32_t* Ab = &As[buf][0];
        const uint32_t* Bb = &Bs[buf][0];
        #pragma unroll
        for (int s = 0; s < 2; s++) {
            uint32_t af[4][4];
            #pragma unroll
            for (int m = 0; m < 4; m++) {
                int r = warpM * 64 + m * 16;
                af[m][0] = Ab[(r + g)     * 20 + s * 8 + tg];
                af[m][1] = Ab[(r + 8 + g) * 20 + s * 8 + tg];
                af[m][2] = Ab[(r + g)     * 20 + s * 8 + tg + 4];
                af[m][3] = Ab[(r + 8 + g) * 20 + s * 8 + tg + 4];
            }
            uint32_t bf[4][2];
            #pragma unroll
            for (int n = 0; n < 4; n++) {
                int c = warpN * 32 + n * 8 + g;
                bf[n][0] = Bb[(s * 8 + tg)     * 136 + c];
                bf[n][1] = Bb[(s * 8 + tg + 4) * 136 + c];
            }
            #pragma unroll
            for (int m = 0; m < 4; m++)
                #pragma unroll
                for (int n = 0; n < 4; n++)
                    mma_bf16(acc[m][n], af[m][0], af[m][1], af[m][2], af[m][3],
                             bf[n][0], bf[n][1]);
        }
        __syncthreads();
    }

    #pragma unroll
    for (int m = 0; m < 4; m++) {
        int r = row0 + warpM * 64 + m * 16 + g;
        #pragma unroll
        for (int n = 0; n < 4; n++) {
            int c = col0 + warpN * 32 + n * 8 + 2 * tg;
            #pragma unroll
            for (int half = 0; half < 2; half++) {
                int rr = r + half * 8;
                float a0 = acc[m][n][half * 2 + 0];
                float a1 = acc[m][n][half * 2 + 1];
                if (MODE == 3) {
                    int j = c >> 1;
                    float l  = a0 + bias[j];
                    float rv = a1 + aux1[j];
                    ((__nv_bfloat16*)Cout)[(size_t)rr * (N >> 1) + j] =
                        __float2bfloat16_rn(gelu_exact(l) * rv);
                } else if (MODE == 4) {
                    size_t i0 = (size_t)rr * N + c;
                    __nv_bfloat162 hh = __floats2bfloat162_rn(a0 + bias[c],
                                                              a1 + bias[c + 1]);
                    *reinterpret_cast<uint32_t*>((__nv_bfloat16*)Cout + i0) =
                        *reinterpret_cast<uint32_t*>(&hh);
                } else {
                    size_t i0 = (size_t)rr * N + c;
                    float v0 = a0 + bias[c];
                    float v1 = a1 + bias[c + 1];
                    if (MODE == 2) {
                        float x0 = aux0[i0], x1v = aux0[i0 + 1];
                        v0 = x0  * sigmoidf_(x0)  * (v0 + aux1[i0])     + aux2[i0];
                        v1 = x1v * sigmoidf_(x1v) * (v1 + aux1[i0 + 1]) + aux2[i0 + 1];
                    }
                    *reinterpret_cast<float2*>((float*)Cout + i0) = make_float2(v0, v1);
                }
            }
        }
    }
}

// ---------------- sLSTM recurrence v4: fused GroupNorm -> d_hnh directly ----------------
// 128 blocks: head = bx>>4, batch tile of 32 = (bx&15)*32. 256 threads, 8 warps.
// For iteration it: threads 0..127 own (bb=2it, hs=tid), threads 128..255 own
// (bb=2it+1, hs=tid-128): each GN group (128 hs values) maps to 4 whole warps.
__global__ __launch_bounds__(256) void slstm_rec4(const float* __restrict__ gng,
                                                  const float* __restrict__ gnb) {
    extern __shared__ uint32_t smw[];
    uint32_t* sBp = smw;                                  // [64][520]
    float* s_rec = (float*)(smw + 64 * 520);              // [32][516]
    uint32_t* sh_w = (uint32_t*)(s_rec + 32 * 516);       // [32][68]
    float* gn_part = (float*)(sh_w + 32 * 68);            // [16][8][2]
    __nv_bfloat16* sh_h = (__nv_bfloat16*)sh_w;

    int head = blockIdx.x >> 4;
    int b0 = (blockIdx.x & 15) << 5;
    int tid = threadIdx.x;
    int warp = tid >> 5, lane = tid & 31;
    int g = lane >> 2, tg = lane & 3;
    int wm = warp >> 2, wn = warp & 3;

    uint32_t sb = (uint32_t)__cvta_generic_to_shared(sBp);
    const uint32_t* Bg = d_Rgp + (size_t)head * (64 * 512);
    #pragma unroll
    for (int i = 0; i < 32; i++) {
        int e = i * 256 + tid;
        int kp = e >> 7, c = (e & 127) * 4;
        cp_async16(sb + (uint32_t)(kp * 520 + c) * 4, Bg + (size_t)kp * 512 + c);
    }
    asm volatile("cp.async.commit_group;");
    for (int i = tid; i < 32 * 68; i += 256) sh_w[i] = 0;
    float cS[16], nS[16], mS[16];
    #pragma unroll
    for (int j = 0; j < 16; j++) { cS[j] = 0.f; nS[j] = 0.f; mS[j] = 0.f; }
    // per-thread GN constants: ch = head*128 + (tid&127)
    int hs_t = tid & 127;
    float gnw = __ldg(gng + head * 128 + hs_t);
    float gnbv = __ldg(gnb + head * 128 + hs_t);
    asm volatile("cp.async.wait_group 0;");
    __syncthreads();

    for (int t = 0; t < 12; t++) {
        // rec[32][512] = h[32][128] @ RgT
        float acc[16][4];
        #pragma unroll
        for (int j = 0; j < 16; j++)
            #pragma unroll
            for (int q = 0; q < 4; q++) acc[j][q] = 0.f;
        #pragma unroll
        for (int s = 0; s < 8; s++) {
            uint32_t a0 = sh_w[(wm * 16 + g)     * 68 + s * 8 + tg];
            uint32_t a1 = sh_w[(wm * 16 + 8 + g) * 68 + s * 8 + tg];
            uint32_t a2 = sh_w[(wm * 16 + g)     * 68 + s * 8 + tg + 4];
            uint32_t a3 = sh_w[(wm * 16 + 8 + g) * 68 + s * 8 + tg + 4];
            #pragma unroll
            for (int j = 0; j < 16; j++) {
                int c = wn * 128 + j * 8 + g;
                uint32_t b0v = sBp[(s * 8 + tg)     * 520 + c];
                uint32_t b1v = sBp[(s * 8 + tg + 4) * 520 + c];
                mma_bf16(acc[j], a0, a1, a2, a3, b0v, b1v);
            }
        }
        #pragma unroll
        for (int j = 0; j < 16; j++) {
            int c = wn * 128 + j * 8 + 2 * tg;
            int r = wm * 16 + g;
            s_rec[r * 516 + c]           = acc[j][0];
            s_rec[r * 516 + c + 1]       = acc[j][1];
            s_rec[(r + 8) * 516 + c]     = acc[j][2];
            s_rec[(r + 8) * 516 + c + 1] = acc[j][3];
        }
        __syncthreads();

        // gate update + warp GN partials
        float hv16[16];
        #pragma unroll
        for (int it = 0; it < 16; it++) {
            int idx = it * 256 + tid;
            int bb = idx >> 7, hs = idx & 127;
            int b = b0 + bb;
            const __nv_bfloat16* gxp =
                d_gxh + (size_t)(b * 12 + t) * 4096 + head * 512;
            const float* rp = s_rec + bb * 516;
            float z_ = __bfloat162float(gxp[hs])       + rp[hs];
            float i_ = __bfloat162float(gxp[128 + hs]) + rp[128 + hs];
            float f_ = __bfloat162float(gxp[256 + hs]) + rp[256 + hs];
            float o_ = __bfloat162float(gxp[384 + hs]) + rp[384 + hs];
            float z  = tanhf(z_);
            float o  = sigmoidf_(o_);
            float mo = mS[it];
            float mn = fmaxf(f_ + mo, i_);
            float iv = expf(i_ - mn);
            float fv = expf(f_ + mo - mn);
            float cv = fv * cS[it] + iv * z;
            float nv = fv * nS[it] + iv;
            float hv = o * (cv / nv);
            cS[it] = cv; nS[it] = nv; mS[it] = mn;
            sh_h[bb * 136 + hs] = __float2bfloat16_rn(hv);
            hv16[it] = hv;
            float s = hv, ss = hv * hv;
            warp_reduce_2(s, ss);
            if (lane == 0) {
                gn_part[(it * 8 + warp) * 2]     = s;
                gn_part[(it * 8 + warp) * 2 + 1] = ss;
            }
        }
        __syncthreads();

        // GN apply: combine 4 warp partials of this thread's group, write bf16 hn
        int wbase = (tid >> 7) * 4;       // 0 for bb=2it, 4 for bb=2it+1
        #pragma unroll
        for (int it = 0; it < 16; it++) {
            float s = 0.f, ss = 0.f;
            #pragma unroll
            for (int q = 0; q < 4; q++) {
                s  += gn_part[(it * 8 + wbase + q) * 2];
                ss += gn_part[(it * 8 + wbase + q) * 2 + 1];
            }
            float mu = s * (1.0f / 128.0f);
            float rstd = rsqrtf(ss * (1.0f / 128.0f) - mu * mu + 1e-5f);
            int bb = (it << 1) + (tid >> 7);
            int b = b0 + bb;
            d_hnh[(size_t)(b * 12 + t) * 1024 + head * 128 + hs_t] =
                __float2bfloat16_rn((hv16[it] - mu) * rstd * gnw + gnbv);
        }
        __syncthreads();
    }
}

// ---------------- launch ----------------
extern "C" void kernel_launch(void* const* d_in, const int* in_sizes, int n_in,
                              void* d_out, int out_size) {
    const float* x       = (const float*)d_in[0];
    const float* ln_g    = (const float*)d_in[1];
    const float* ln_b    = (const float*)d_in[2];
    const float* fc1_w   = (const float*)d_in[3];
    const float* fc1_b   = (const float*)d_in[4];
    const float* fc2_w   = (const float*)d_in[5];
    const float* fc2_b   = (const float*)d_in[6];
    const float* conv1_w = (const float*)d_in[7];
    const float* conv1_b = (const float*)d_in[8];
    const float* conv2_w = (const float*)d_in[9];
    const float* conv2_b = (const float*)d_in[10];
    const float* xlg     = (const float*)d_in[11];
    const float* xlb     = (const float*)d_in[12];
    const float* Wg      = (const float*)d_in[13];
    const float* bg      = (const float*)d_in[14];
    const float* Rg      = (const float*)d_in[15];
    const float* gng     = (const float*)d_in[16];
    const float* gnb     = (const float*)d_in[17];
    const float* uplw    = (const float*)d_in[18];
    const float* uplb    = (const float*)d_in[19];
    const float* uprw    = (const float*)d_in[20];
    const float* uprb    = (const float*)d_in[21];
    const float* downw   = (const float*)d_in[22];
    const float* downb   = (const float*)d_in[23];
    float* out = (float*)d_out;

    cudaFuncSetAttribute(slstm_rec4,  cudaFuncAttributeMaxDynamicSharedMemorySize, 208896);
    cudaFuncSetAttribute(fused_front, cudaFuncAttributeMaxDynamicSharedMemorySize, 150240);
    cudaFuncSetAttribute(fused_tail,  cudaFuncAttributeMaxDynamicSharedMemorySize, 129648);

    float *p_xn, *p_xc, *p_x1, *p_y;
    __nv_bfloat16 *p_gxh, *p_xn2h, *p_hnh, *p_uh;
    uint32_t *p_Wgp, *p_downp, *p_Wpair;
    cudaGetSymbolAddress((void**)&p_xn,    d_xn);
    cudaGetSymbolAddress((void**)&p_xc,    d_xc);
    cudaGetSymbolAddress((void**)&p_x1,    d_x1);
    cudaGetSymbolAddress((void**)&p_y,     d_y);
    cudaGetSymbolAddress((void**)&p_gxh,   d_gxh);
    cudaGetSymbolAddress((void**)&p_xn2h,  d_xn2h);
    cudaGetSymbolAddress((void**)&p_hnh,   d_hnh);
    cudaGetSymbolAddress((void**)&p_uh,    d_uh);
    cudaGetSymbolAddress((void**)&p_Wgp,   d_Wgp);
    cudaGetSymbolAddress((void**)&p_downp, d_downp);
    cudaGetSymbolAddress((void**)&p_Wpair, d_Wpair);

    // all weight packs in two launches
    pack_all<<<dim3(16, 512, 3), 256>>>(Wg, downw, uplw, uprw);
    pack_rg<<<dim3(8, 16), 256>>>(Rg);

    // LN(x) -> fc1 -> fc2 -> LN -> bf16   [fused per batch]
    fused_front<<<B_, 384, 150240>>>(x, ln_g, ln_b, fc1_w, fc1_b,
                                     fc2_w, fc2_b, xlg, xlb);
    // gx = xn2 @ Wg + bg  -> bf16
    gemm_bf16<4><<<dim3(32, 48), 256>>>(4096, 1024, p_xn2h, p_Wgp, bg,
                                        nullptr, nullptr, nullptr, p_gxh);
    // sLSTM recurrence + fused GroupNorm -> d_hnh (bf16)
    slstm_rec4<<<128, 256, 208896>>>(gng, gnb);
    // u = gelu(hn@upl + uplb) * (hn@upr + uprb)
    gemm_bf16<3><<<dim3(16, 48), 256>>>(2048, 1024, p_hnh, p_Wpair, uplb,
                                        nullptr, uprb, nullptr, p_uh);
    // y = silu(xc) * (u @ down + downb + x1) + xn
    gemm_bf16<2><<<dim3(8, 48), 256>>>(1024, 1024, p_uh, p_downp, downb,
                                       p_xc, p_x1, p_xn, p_y);
    // conv12->48 + gelu + LN + conv48->12 + skip   [fused, fp32 throughout]
    fused_tail<<<B_, 512, 129648>>>(conv1_w, conv1_b, conv2_w, conv2_b,
                                    ln_g, ln_b, out);
}

// round 13
// speedup vs baseline: 3.8772x; 1.0129x over previous
#include <cuda_runtime.h>
#include <cuda_bf16.h>
#include <cmath>
#include <cstdint>

// ---------------- problem constants ----------------
static constexpr int B_   = 512;
static constexpr int T_   = 12;
static constexpr int E_   = 1024;
static constexpr int NH_  = 8;
static constexpr int HS_  = 128;
static constexpr int H_   = 1024;
static constexpr int G4_  = 4096;
static constexpr int BT_  = B_ * T_;        // 6144

// ---------------- scratch (device globals; no allocation) ----------------
__device__ float d_xn [BT_ * (size_t)E_];
__device__ float d_xc [BT_ * (size_t)E_];
__device__ float d_x1 [BT_ * (size_t)E_];
__device__ float d_y  [BT_ * (size_t)E_];
// bf16 operands
__device__ __nv_bfloat16 d_gxh [BT_ * (size_t)G4_];
__device__ __nv_bfloat16 d_xn2h[BT_ * (size_t)E_];
__device__ __nv_bfloat16 d_hnh [BT_ * (size_t)H_];
__device__ __nv_bfloat16 d_uh  [BT_ * (size_t)H_];
// pair-packed bf16 weights
__device__ uint32_t d_Wgp  [(size_t)512 * G4_];
__device__ uint32_t d_downp[(size_t)512 * E_];
__device__ uint32_t d_Wpair[(size_t)512 * 2048];
__device__ uint32_t d_Rgp  [(size_t)NH_ * 64 * 512];

// ---------------- helpers ----------------
__device__ __forceinline__ float gelu_exact(float x) {
    return 0.5f * x * (1.0f + erff(x * 0.70710678118654752440f));
}
__device__ __forceinline__ float sigmoidf_(float x) {
    return 1.0f / (1.0f + expf(-x));
}
__device__ __forceinline__ void cp_async16(uint32_t saddr, const void* g) {
    asm volatile("cp.async.cg.shared.global [%0], [%1], 16;" :: "r"(saddr), "l"(g));
}
__device__ __forceinline__ void mma_bf16(float* acc, uint32_t a0, uint32_t a1,
                                         uint32_t a2, uint32_t a3,
                                         uint32_t b0, uint32_t b1) {
    asm volatile(
        "mma.sync.aligned.m16n8k16.row.col.f32.bf16.bf16.f32 "
        "{%0,%1,%2,%3}, {%4,%5,%6,%7}, {%8,%9}, {%0,%1,%2,%3};"
        : "+f"(acc[0]), "+f"(acc[1]), "+f"(acc[2]), "+f"(acc[3])
        : "r"(a0), "r"(a1), "r"(a2), "r"(a3), "r"(b0), "r"(b1));
}
__device__ __forceinline__ void warp_reduce_2(float& s, float& ss) {
    #pragma unroll
    for (int o = 16; o; o >>= 1) {
        s  += __shfl_xor_sync(0xffffffffu, s,  o);
        ss += __shfl_xor_sync(0xffffffffu, ss, o);
    }
}

// ---------------- combined weight packs (one launch) ----------------
__global__ void pack_all(const float* __restrict__ Wg,
                         const float* __restrict__ downw,
                         const float* __restrict__ wl,
                         const float* __restrict__ wr) {
    int z = blockIdx.z;
    int kp = blockIdx.y;
    int n = blockIdx.x * 256 + threadIdx.x;
    if (z == 0) {
        __nv_bfloat162 h = __floats2bfloat162_rn(Wg[(size_t)(2 * kp) * 4096 + n],
                                                 Wg[(size_t)(2 * kp + 1) * 4096 + n]);
        d_Wgp[(size_t)kp * 4096 + n] = *reinterpret_cast<uint32_t*>(&h);
    } else if (z == 1) {
        if (blockIdx.x >= 4) return;
        __nv_bfloat162 h = __floats2bfloat162_rn(downw[(size_t)(2 * kp) * 1024 + n],
                                                 downw[(size_t)(2 * kp + 1) * 1024 + n]);
        d_downp[(size_t)kp * 1024 + n] = *reinterpret_cast<uint32_t*>(&h);
    } else {
        if (blockIdx.x >= 4) return;
        __nv_bfloat162 hl = __floats2bfloat162_rn(wl[(size_t)(2 * kp) * 1024 + n],
                                                  wl[(size_t)(2 * kp + 1) * 1024 + n]);
        __nv_bfloat162 hr = __floats2bfloat162_rn(wr[(size_t)(2 * kp) * 1024 + n],
                                                  wr[(size_t)(2 * kp + 1) * 1024 + n]);
        d_Wpair[(size_t)kp * 2048 + 2 * n]     = *reinterpret_cast<uint32_t*>(&hl);
        d_Wpair[(size_t)kp * 2048 + 2 * n + 1] = *reinterpret_cast<uint32_t*>(&hr);
    }
}
__global__ __launch_bounds__(256) void pack_rg(const float* __restrict__ Rg) {
    __shared__ float tile[32][129];
    int head = blockIdx.x;
    int g0 = blockIdx.y * 32;
    int tid = threadIdx.x;
    #pragma unroll
    for (int i = 0; i < 16; i++) {
        int e = i * 256 + tid;
        int r = e >> 7, c = e & 127;
        tile[r][c] = Rg[((size_t)(head * 512 + g0 + r)) * 128 + c];
    }
    __syncthreads();
    #pragma unroll
    for (int i = 0; i < 8; i++) {
        int e = i * 256 + tid;
        int kp = e >> 5, gl = e & 31;
        __nv_bfloat162 h = __floats2bfloat162_rn(tile[gl][2 * kp], tile[gl][2 * kp + 1]);
        d_Rgp[((size_t)(head * 64 + kp)) * 512 + g0 + gl] =
            *reinterpret_cast<uint32_t*>(&h);
    }
}

// ---------------- fused front: LN(x) -> fc1 conv -> fc2 -> LN -> bf16 ----------------
__global__ __launch_bounds__(384) void fused_front(
    const float* __restrict__ x,
    const float* __restrict__ ln_g, const float* __restrict__ ln_b,
    const float* __restrict__ w1g, const float* __restrict__ b1g,
    const float* __restrict__ w2g, const float* __restrict__ b2g,
    const float* __restrict__ xlg, const float* __restrict__ xlb) {
    extern __shared__ float sm[];
    float* sxn = sm;                    // [12][1032], data at +1, halo zeros
    float* sxc = sxn + 12 * 1032;       // [12][1024]
    float* sx1 = sxc + 12 * 1024;       // [12][1024]
    float* sw1 = sx1 + 12 * 1024;       // 432
    float* sw2 = sw1 + 432;             // 144
    float* sb1 = sw2 + 144;             // 12
    float* sb2 = sb1 + 12;              // 12
    int b = blockIdx.x, tid = threadIdx.x, w = tid >> 5, lane = tid & 31;

    for (int i = tid; i < 432; i += 384) sw1[i] = w1g[i];
    if (tid < 144) sw2[tid] = w2g[tid];
    if (tid < 12) { sb1[tid] = b1g[tid]; sb2[tid] = b2g[tid]; }
    if (lane == 0) { sxn[w * 1032] = 0.f; sxn[w * 1032 + 1025] = 0.f; }

    size_t rbase = ((size_t)b * 12 + w) * 1024;
    const float* xr = x + rbase;
    float4 vals[8];
    float s = 0.f, ss = 0.f;
    #pragma unroll
    for (int j = 0; j < 8; j++) {
        float4 v = *reinterpret_cast<const float4*>(xr + lane * 4 + j * 128);
        vals[j] = v;
        s  += v.x + v.y + v.z + v.w;
        ss += v.x*v.x + v.y*v.y + v.z*v.z + v.w*v.w;
    }
    warp_reduce_2(s, ss);
    float mu = s * (1.0f / 1024.0f);
    float rstd = rsqrtf(ss * (1.0f / 1024.0f) - mu * mu + 1e-5f);
    #pragma unroll
    for (int j = 0; j < 8; j++) {
        int idx = lane * 4 + j * 128;
        float4 g = *reinterpret_cast<const float4*>(ln_g + idx);
        float4 bb = *reinterpret_cast<const float4*>(ln_b + idx);
        float4 v = vals[j], o;
        o.x = (v.x - mu) * rstd * g.x + bb.x;
        o.y = (v.y - mu) * rstd * g.y + bb.y;
        o.z = (v.z - mu) * rstd * g.z + bb.z;
        o.w = (v.w - mu) * rstd * g.w + bb.w;
        sxn[w * 1032 + 1 + idx] = o.x; sxn[w * 1032 + 2 + idx] = o.y;
        sxn[w * 1032 + 3 + idx] = o.z; sxn[w * 1032 + 4 + idx] = o.w;
        *reinterpret_cast<float4*>(d_xn + rbase + idx) = o;
    }
    __syncthreads();

    {   // fc1 conv: warp w -> channel w
        int o = w;
        float wl[36];
        #pragma unroll
        for (int i = 0; i < 36; i++) wl[i] = sw1[o * 36 + i];
        float bo = sb1[o];
        for (int j = 0; j < 32; j++) {
            int l = lane + j * 32;
            float a = bo;
            #pragma unroll
            for (int c = 0; c < 12; c++) {
                a += wl[c*3]   * sxn[c * 1032 + l]
                   + wl[c*3+1] * sxn[c * 1032 + l + 1]
                   + wl[c*3+2] * sxn[c * 1032 + l + 2];
            }
            sxc[o * 1024 + l] = a;
            d_xc[rbase + l] = a;
        }
    }
    __syncthreads();

    {   // fc2 1x1
        int o = w;
        float wl[12];
        #pragma unroll
        for (int c = 0; c < 12; c++) wl[c] = sw2[o * 12 + c];
        float bo = sb2[o];
        for (int j = 0; j < 32; j++) {
            int l = lane + j * 32;
            float a = bo;
            #pragma unroll
            for (int c = 0; c < 12; c++) a += wl[c] * sxc[c * 1024 + l];
            sx1[o * 1024 + l] = a;
            d_x1[rbase + l] = a;
        }
    }
    __syncthreads();

    // LN2 -> bf16
    s = 0.f; ss = 0.f;
    #pragma unroll
    for (int j = 0; j < 8; j++) {
        float4 v = *reinterpret_cast<const float4*>(sx1 + w * 1024 + lane * 4 + j * 128);
        vals[j] = v;
        s  += v.x + v.y + v.z + v.w;
        ss += v.x*v.x + v.y*v.y + v.z*v.z + v.w*v.w;
    }
    warp_reduce_2(s, ss);
    mu = s * (1.0f / 1024.0f);
    rstd = rsqrtf(ss * (1.0f / 1024.0f) - mu * mu + 1e-5f);
    #pragma unroll
    for (int j = 0; j < 8; j++) {
        int idx = lane * 4 + j * 128;
        float4 g = *reinterpret_cast<const float4*>(xlg + idx);
        float4 bb = *reinterpret_cast<const float4*>(xlb + idx);
        float4 v = vals[j];
        __nv_bfloat162 h0 = __floats2bfloat162_rn((v.x - mu) * rstd * g.x + bb.x,
                                                  (v.y - mu) * rstd * g.y + bb.y);
        __nv_bfloat162 h1 = __floats2bfloat162_rn((v.z - mu) * rstd * g.z + bb.z,
                                                  (v.w - mu) * rstd * g.w + bb.w);
        uint2 pk = make_uint2(*reinterpret_cast<uint32_t*>(&h0),
                              *reinterpret_cast<uint32_t*>(&h1));
        *reinterpret_cast<uint2*>(d_xn2h + rbase + idx) = pk;
    }
}

// ---------------- fused tail v2: all-fp32, 3 chunks of 16 z-rows ----------------
__global__ __launch_bounds__(512) void fused_tail(
    const float* __restrict__ w1g, const float* __restrict__ b1g,
    const float* __restrict__ w2g, const float* __restrict__ b2g,
    const float* __restrict__ ln_g, const float* __restrict__ ln_b,
    float* __restrict__ out) {
    extern __shared__ float sm[];
    float* sy  = sm;                   // [12][1032], data at +1, halo zeros
    float* szf = sy + 12 * 1032;       // [16][1032] fp32 chunk, data at +1
    float* sw1 = szf + 16 * 1032;      // 1728 (o,c,k)
    float* sw2 = sw1 + 1728;           // 1728 repacked (c,o,k)
    float* sb1 = sw2 + 1728;           // 48
    float* sb2 = sb1 + 48;             // 12
    int b = blockIdx.x, tid = threadIdx.x, w = tid >> 5, lane = tid & 31;

    for (int i = tid; i < 12 * 256; i += 512) {
        int c = i >> 8, q = (i & 255) * 4;
        float4 v = *reinterpret_cast<const float4*>(d_y + ((size_t)b * 12 + c) * 1024 + q);
        sy[c * 1032 + 1 + q]     = v.x;
        sy[c * 1032 + 1 + q + 1] = v.y;
        sy[c * 1032 + 1 + q + 2] = v.z;
        sy[c * 1032 + 1 + q + 3] = v.w;
    }
    if (tid < 12) { sy[tid * 1032] = 0.f; sy[tid * 1032 + 1025] = 0.f; }
    if (tid < 16) { szf[tid * 1032] = 0.f; szf[tid * 1032 + 1025] = 0.f; }
    for (int i = tid; i < 1728; i += 512) {
        sw1[i] = w1g[i];
        int o = i / 144, rem = i % 144;
        int c = rem / 3, k = rem % 3;
        sw2[c * 36 + o * 3 + k] = w2g[i];
    }
    if (tid < 48) sb1[tid] = b1g[tid];
    if (tid < 12) sb2[tid] = b2g[tid];
    __syncthreads();

    int l2 = tid * 2;
    float acc0[12], acc1[12];
    #pragma unroll
    for (int o = 0; o < 12; o++) { acc0[o] = 0.f; acc1[o] = 0.f; }

    for (int cc = 0; cc < 3; cc++) {
        int o = cc * 16 + w;
        float wl[36];
        #pragma unroll
        for (int i = 0; i < 36; i++) wl[i] = sw1[o * 36 + i];
        float bo = sb1[o];
        float vbuf[32];
        float s = 0.f, ss = 0.f;
        #pragma unroll 4
        for (int j = 0; j < 32; j++) {
            int l = lane + j * 32;
            float a = bo;
            #pragma unroll
            for (int c = 0; c < 12; c++) {
                a += wl[c*3]   * sy[c * 1032 + l]
                   + wl[c*3+1] * sy[c * 1032 + l + 1]
                   + wl[c*3+2] * sy[c * 1032 + l + 2];
            }
            float v = gelu_exact(a);
            vbuf[j] = v;
            s += v; ss += v * v;
        }
        warp_reduce_2(s, ss);
        float mu = s * (1.0f / 1024.0f);
        float rstd = rsqrtf(ss * (1.0f / 1024.0f) - mu * mu + 1e-5f);
        #pragma unroll 4
        for (int j = 0; j < 32; j++) {
            int l = lane + j * 32;
            szf[w * 1032 + 1 + l] =
                (vbuf[j] - mu) * rstd * __ldg(ln_g + l) + __ldg(ln_b + l);
        }
        __syncthreads();

        for (int c16 = 0; c16 < 16; c16++) {
            int c = cc * 16 + c16;
            const float* zr = szf + c16 * 1032 + l2;
            float2 p0 = *reinterpret_cast<const float2*>(zr);
            float2 p1 = *reinterpret_cast<const float2*>(zr + 2);
            float h0 = p0.x, h1 = p0.y, h2 = p1.x, h3 = p1.y;
            const float* wr = sw2 + c * 36;
            #pragma unroll
            for (int o2 = 0; o2 < 12; o2++) {
                float w0 = wr[o2*3], w1 = wr[o2*3+1], w2v = wr[o2*3+2];
                acc0[o2] += w0 * h0 + w1 * h1 + w2v * h2;
                acc1[o2] += w0 * h1 + w1 * h2 + w2v * h3;
            }
        }
        __syncthreads();
    }

    #pragma unroll
    for (int o = 0; o < 12; o++) {
        size_t idx = ((size_t)b * 12 + o) * 1024 + l2;
        float2 sk = *reinterpret_cast<const float2*>(d_xn + idx);
        float2 ov;
        ov.x = acc0[o] + sb2[o] + sk.x;
        ov.y = acc1[o] + sb2[o] + sk.y;
        *reinterpret_cast<float2*>(out + idx) = ov;
    }
}

// ---------------- bf16 tensor-core GEMM: 3-stage cp.async, single sync/iter ----------------
// MODE 2: C(fp32) = silu(aux0) * (acc + bias + aux1) + aux2
// MODE 3: interleaved pair: C(bf16)[r][c/2] = gelu(accL+bias) * (accR+aux1)
// MODE 4: C(bf16) = acc + bias
template<int MODE>
__global__ __launch_bounds__(256) void gemm_bf16(int N, int K,
                                                 const __nv_bfloat16* __restrict__ A,
                                                 const uint32_t* __restrict__ Bp,
                                                 const float* __restrict__ bias,
                                                 const float* __restrict__ aux0,
                                                 const float* __restrict__ aux1,
                                                 const float* __restrict__ aux2,
                                                 void* __restrict__ Cout) {
    __shared__ uint32_t As[3][128 * 20];
    __shared__ uint32_t Bs[3][16 * 136];
    int tid = threadIdx.x;
    int warp = tid >> 5, lane = tid & 31;
    int g = lane >> 2, tg = lane & 3;
    int warpM = warp >> 2, warpN = warp & 3;
    int row0 = blockIdx.y * 128, col0 = blockIdx.x * 128;

    uint32_t asb = (uint32_t)__cvta_generic_to_shared(&As[0][0]);
    uint32_t bsb = (uint32_t)__cvta_generic_to_shared(&Bs[0][0]);

    float acc[4][4][4];
    #pragma unroll
    for (int m = 0; m < 4; m++)
        #pragma unroll
        for (int n = 0; n < 4; n++)
            #pragma unroll
            for (int q = 0; q < 4; q++) acc[m][n][q] = 0.f;

    const int nt = K >> 5;

    auto load_tile = [&](int it, int buf) {
        int k0 = it << 5;
        int kp0 = it << 4;
        #pragma unroll
        for (int i = 0; i < 2; i++) {
            int e = i * 256 + tid;
            int r = e >> 2, ch = e & 3;
            cp_async16(asb + (uint32_t)(buf * 128 * 20 + r * 20 + ch * 4) * 4,
                       A + (size_t)(row0 + r) * K + k0 + ch * 8);
        }
        #pragma unroll
        for (int i = 0; i < 2; i++) {
            int e = i * 256 + tid;
            int kp = e >> 5, c = (e & 31) * 4;
            cp_async16(bsb + (uint32_t)(buf * 16 * 136 + kp * 136 + c) * 4,
                       Bp + (size_t)(kp0 + kp) * N + col0 + c);
        }
        asm volatile("cp.async.commit_group;");
    };

    // prime 2 stages
    load_tile(0, 0);
    load_tile(1, 1);

    // per-warp fragment base offsets (hoisted address math)
    int arow = warpM * 64;
    int bcol = warpN * 32 + g;

    for (int it = 0; it < nt; it++) {
        int buf = it - (it / 3) * 3;
        asm volatile("cp.async.wait_group 1;");
        __syncthreads();
        // prefetch stage it+2 into the buffer consumed at it-1 (safe post-sync)
        if (it + 2 < nt) {
            int buf2 = (it + 2) - ((it + 2) / 3) * 3;
            load_tile(it + 2, buf2);
        } else {
            asm volatile("cp.async.commit_group;");   // keep group count aligned
        }
        const uint32_t* Ab = &As[buf][0];
        const uint32_t* Bb = &Bs[buf][0];
        #pragma unroll
        for (int s = 0; s < 2; s++) {
            uint32_t af[4][4];
            #pragma unroll
            for (int m = 0; m < 4; m++) {
                int r = arow + m * 16;
                af[m][0] = Ab[(r + g)     * 20 + s * 8 + tg];
                af[m][1] = Ab[(r + 8 + g) * 20 + s * 8 + tg];
                af[m][2] = Ab[(r + g)     * 20 + s * 8 + tg + 4];
                af[m][3] = Ab[(r + 8 + g) * 20 + s * 8 + tg + 4];
            }
            uint32_t bf[4][2];
            #pragma unroll
            for (int n = 0; n < 4; n++) {
                int c = bcol + n * 8;
                bf[n][0] = Bb[(s * 8 + tg)     * 136 + c];
                bf[n][1] = Bb[(s * 8 + tg + 4) * 136 + c];
            }
            #pragma unroll
            for (int m = 0; m < 4; m++)
                #pragma unroll
                for (int n = 0; n < 4; n++)
                    mma_bf16(acc[m][n], af[m][0], af[m][1], af[m][2], af[m][3],
                             bf[n][0], bf[n][1]);
        }
    }

    __syncthreads();
    #pragma unroll
    for (int m = 0; m < 4; m++) {
        int r = row0 + warpM * 64 + m * 16 + g;
        #pragma unroll
        for (int n = 0; n < 4; n++) {
            int c = col0 + warpN * 32 + n * 8 + 2 * tg;
            #pragma unroll
            for (int half = 0; half < 2; half++) {
                int rr = r + half * 8;
                float a0 = acc[m][n][half * 2 + 0];
                float a1 = acc[m][n][half * 2 + 1];
                if (MODE == 3) {
                    int j = c >> 1;
                    float l  = a0 + bias[j];
                    float rv = a1 + aux1[j];
                    ((__nv_bfloat16*)Cout)[(size_t)rr * (N >> 1) + j] =
                        __float2bfloat16_rn(gelu_exact(l) * rv);
                } else if (MODE == 4) {
                    size_t i0 = (size_t)rr * N + c;
                    __nv_bfloat162 hh = __floats2bfloat162_rn(a0 + bias[c],
                                                              a1 + bias[c + 1]);
                    *reinterpret_cast<uint32_t*>((__nv_bfloat16*)Cout + i0) =
                        *reinterpret_cast<uint32_t*>(&hh);
                } else {
                    size_t i0 = (size_t)rr * N + c;
                    float v0 = a0 + bias[c];
                    float v1 = a1 + bias[c + 1];
                    if (MODE == 2) {
                        float x0 = aux0[i0], x1v = aux0[i0 + 1];
                        v0 = x0  * sigmoidf_(x0)  * (v0 + aux1[i0])     + aux2[i0];
                        v1 = x1v * sigmoidf_(x1v) * (v1 + aux1[i0 + 1]) + aux2[i0 + 1];
                    }
                    *reinterpret_cast<float2*>((float*)Cout + i0) = make_float2(v0, v1);
                }
            }
        }
    }
}

// ---------------- sLSTM recurrence v4: fused GroupNorm -> d_hnh directly ----------------
__global__ __launch_bounds__(256) void slstm_rec4(const float* __restrict__ gng,
                                                  const float* __restrict__ gnb) {
    extern __shared__ uint32_t smw[];
    uint32_t* sBp = smw;                                  // [64][520]
    float* s_rec = (float*)(smw + 64 * 520);              // [32][516]
    uint32_t* sh_w = (uint32_t*)(s_rec + 32 * 516);       // [32][68]
    float* gn_part = (float*)(sh_w + 32 * 68);            // [16][8][2]
    __nv_bfloat16* sh_h = (__nv_bfloat16*)sh_w;

    int head = blockIdx.x >> 4;
    int b0 = (blockIdx.x & 15) << 5;
    int tid = threadIdx.x;
    int warp = tid >> 5, lane = tid & 31;
    int g = lane >> 2, tg = lane & 3;
    int wm = warp >> 2, wn = warp & 3;

    uint32_t sb = (uint32_t)__cvta_generic_to_shared(sBp);
    const uint32_t* Bg = d_Rgp + (size_t)head * (64 * 512);
    #pragma unroll
    for (int i = 0; i < 32; i++) {
        int e = i * 256 + tid;
        int kp = e >> 7, c = (e & 127) * 4;
        cp_async16(sb + (uint32_t)(kp * 520 + c) * 4, Bg + (size_t)kp * 512 + c);
    }
    asm volatile("cp.async.commit_group;");
    for (int i = tid; i < 32 * 68; i += 256) sh_w[i] = 0;
    float cS[16], nS[16], mS[16];
    #pragma unroll
    for (int j = 0; j < 16; j++) { cS[j] = 0.f; nS[j] = 0.f; mS[j] = 0.f; }
    int hs_t = tid & 127;
    float gnw = __ldg(gng + head * 128 + hs_t);
    float gnbv = __ldg(gnb + head * 128 + hs_t);
    asm volatile("cp.async.wait_group 0;");
    __syncthreads();

    for (int t = 0; t < 12; t++) {
        float acc[16][4];
        #pragma unroll
        for (int j = 0; j < 16; j++)
            #pragma unroll
            for (int q = 0; q < 4; q++) acc[j][q] = 0.f;
        #pragma unroll
        for (int s = 0; s < 8; s++) {
            uint32_t a0 = sh_w[(wm * 16 + g)     * 68 + s * 8 + tg];
            uint32_t a1 = sh_w[(wm * 16 + 8 + g) * 68 + s * 8 + tg];
            uint32_t a2 = sh_w[(wm * 16 + g)     * 68 + s * 8 + tg + 4];
            uint32_t a3 = sh_w[(wm * 16 + 8 + g) * 68 + s * 8 + tg + 4];
            #pragma unroll
            for (int j = 0; j < 16; j++) {
                int c = wn * 128 + j * 8 + g;
                uint32_t b0v = sBp[(s * 8 + tg)     * 520 + c];
                uint32_t b1v = sBp[(s * 8 + tg + 4) * 520 + c];
                mma_bf16(acc[j], a0, a1, a2, a3, b0v, b1v);
            }
        }
        #pragma unroll
        for (int j = 0; j < 16; j++) {
            int c = wn * 128 + j * 8 + 2 * tg;
            int r = wm * 16 + g;
            s_rec[r * 516 + c]           = acc[j][0];
            s_rec[r * 516 + c + 1]       = acc[j][1];
            s_rec[(r + 8) * 516 + c]     = acc[j][2];
            s_rec[(r + 8) * 516 + c + 1] = acc[j][3];
        }
        __syncthreads();

        float hv16[16];
        #pragma unroll
        for (int it = 0; it < 16; it++) {
            int idx = it * 256 + tid;
            int bb = idx >> 7, hs = idx & 127;
            int b = b0 + bb;
            const __nv_bfloat16* gxp =
                d_gxh + (size_t)(b * 12 + t) * 4096 + head * 512;
            const float* rp = s_rec + bb * 516;
            float z_ = __bfloat162float(gxp[hs])       + rp[hs];
            float i_ = __bfloat162float(gxp[128 + hs]) + rp[128 + hs];
            float f_ = __bfloat162float(gxp[256 + hs]) + rp[256 + hs];
            float o_ = __bfloat162float(gxp[384 + hs]) + rp[384 + hs];
            float z  = tanhf(z_);
            float o  = sigmoidf_(o_);
            float mo = mS[it];
            float mn = fmaxf(f_ + mo, i_);
            float iv = expf(i_ - mn);
            float fv = expf(f_ + mo - mn);
            float cv = fv * cS[it] + iv * z;
            float nv = fv * nS[it] + iv;
            float hv = o * (cv / nv);
            cS[it] = cv; nS[it] = nv; mS[it] = mn;
            sh_h[bb * 136 + hs] = __float2bfloat16_rn(hv);
            hv16[it] = hv;
            float s = hv, ss = hv * hv;
            warp_reduce_2(s, ss);
            if (lane == 0) {
                gn_part[(it * 8 + warp) * 2]     = s;
                gn_part[(it * 8 + warp) * 2 + 1] = ss;
            }
        }
        __syncthreads();

        int wbase = (tid >> 7) * 4;
        #pragma unroll
        for (int it = 0; it < 16; it++) {
            float s = 0.f, ss = 0.f;
            #pragma unroll
            for (int q = 0; q < 4; q++) {
                s  += gn_part[(it * 8 + wbase + q) * 2];
                ss += gn_part[(it * 8 + wbase + q) * 2 + 1];
            }
            float mu = s * (1.0f / 128.0f);
            float rstd = rsqrtf(ss * (1.0f / 128.0f) - mu * mu + 1e-5f);
            int bb = (it << 1) + (tid >> 7);
            int b = b0 + bb;
            d_hnh[(size_t)(b * 12 + t) * 1024 + head * 128 + hs_t] =
                __float2bfloat16_rn((hv16[it] - mu) * rstd * gnw + gnbv);
        }
        __syncthreads();
    }
}

// ---------------- launch ----------------
extern "C" void kernel_launch(void* const* d_in, const int* in_sizes, int n_in,
                              void* d_out, int out_size) {
    const float* x       = (const float*)d_in[0];
    const float* ln_g    = (const float*)d_in[1];
    const float* ln_b    = (const float*)d_in[2];
    const float* fc1_w   = (const float*)d_in[3];
    const float* fc1_b   = (const float*)d_in[4];
    const float* fc2_w   = (const float*)d_in[5];
    const float* fc2_b   = (const float*)d_in[6];
    const float* conv1_w = (const float*)d_in[7];
    const float* conv1_b = (const float*)d_in[8];
    const float* conv2_w = (const float*)d_in[9];
    const float* conv2_b = (const float*)d_in[10];
    const float* xlg     = (const float*)d_in[11];
    const float* xlb     = (const float*)d_in[12];
    const float* Wg      = (const float*)d_in[13];
    const float* bg      = (const float*)d_in[14];
    const float* Rg      = (const float*)d_in[15];
    const float* gng     = (const float*)d_in[16];
    const float* gnb     = (const float*)d_in[17];
    const float* uplw    = (const float*)d_in[18];
    const float* uplb    = (const float*)d_in[19];
    const float* uprw    = (const float*)d_in[20];
    const float* uprb    = (const float*)d_in[21];
    const float* downw   = (const float*)d_in[22];
    const float* downb   = (const float*)d_in[23];
    float* out = (float*)d_out;

    cudaFuncSetAttribute(slstm_rec4,  cudaFuncAttributeMaxDynamicSharedMemorySize, 208896);
    cudaFuncSetAttribute(fused_front, cudaFuncAttributeMaxDynamicSharedMemorySize, 150240);
    cudaFuncSetAttribute(fused_tail,  cudaFuncAttributeMaxDynamicSharedMemorySize, 129648);

    float *p_xn, *p_xc, *p_x1, *p_y;
    __nv_bfloat16 *p_gxh, *p_xn2h, *p_hnh, *p_uh;
    uint32_t *p_Wgp, *p_downp, *p_Wpair;
    cudaGetSymbolAddress((void**)&p_xn,    d_xn);
    cudaGetSymbolAddress((void**)&p_xc,    d_xc);
    cudaGetSymbolAddress((void**)&p_x1,    d_x1);
    cudaGetSymbolAddress((void**)&p_y,     d_y);
    cudaGetSymbolAddress((void**)&p_gxh,   d_gxh);
    cudaGetSymbolAddress((void**)&p_xn2h,  d_xn2h);
    cudaGetSymbolAddress((void**)&p_hnh,   d_hnh);
    cudaGetSymbolAddress((void**)&p_uh,    d_uh);
    cudaGetSymbolAddress((void**)&p_Wgp,   d_Wgp);
    cudaGetSymbolAddress((void**)&p_downp, d_downp);
    cudaGetSymbolAddress((void**)&p_Wpair, d_Wpair);

    pack_all<<<dim3(16, 512, 3), 256>>>(Wg, downw, uplw, uprw);
    pack_rg<<<dim3(8, 16), 256>>>(Rg);

    // LN(x) -> fc1 -> fc2 -> LN -> bf16   [fused per batch]
    fused_front<<<B_, 384, 150240>>>(x, ln_g, ln_b, fc1_w, fc1_b,
                                     fc2_w, fc2_b, xlg, xlb);
    // gx = xn2 @ Wg + bg  -> bf16
    gemm_bf16<4><<<dim3(32, 48), 256>>>(4096, 1024, p_xn2h, p_Wgp, bg,
                                        nullptr, nullptr, nullptr, p_gxh);
    // sLSTM recurrence + fused GroupNorm -> d_hnh (bf16)
    slstm_rec4<<<128, 256, 208896>>>(gng, gnb);
    // u = gelu(hn@upl + uplb) * (hn@upr + uprb)
    gemm_bf16<3><<<dim3(16, 48), 256>>>(2048, 1024, p_hnh, p_Wpair, uplb,
                                        nullptr, uprb, nullptr, p_uh);
    // y = silu(xc) * (u @ down + downb + x1) + xn
    gemm_bf16<2><<<dim3(8, 48), 256>>>(1024, 1024, p_uh, p_downp, downb,
                                       p_xc, p_x1, p_xn, p_y);
    // conv12->48 + gelu + LN + conv48->12 + skip   [fused, fp32 throughout]
    fused_tail<<<B_, 512, 129648>>>(conv1_w, conv1_b, conv2_w, conv2_b,
                                    ln_g, ln_b, out);
}

// round 14
// speedup vs baseline: 3.9158x; 1.0100x over previous
#include <cuda_runtime.h>
#include <cuda_bf16.h>
#include <cmath>
#include <cstdint>

// ---------------- problem constants ----------------
static constexpr int B_   = 512;
static constexpr int T_   = 12;
static constexpr int E_   = 1024;
static constexpr int NH_  = 8;
static constexpr int HS_  = 128;
static constexpr int H_   = 1024;
static constexpr int G4_  = 4096;
static constexpr int BT_  = B_ * T_;        // 6144

// ---------------- scratch (device globals; no allocation) ----------------
__device__ float d_xn [BT_ * (size_t)E_];
__device__ float d_xc [BT_ * (size_t)E_];
__device__ float d_x1 [BT_ * (size_t)E_];
__device__ float d_y  [BT_ * (size_t)E_];
// bf16 operands
__device__ __nv_bfloat16 d_gxh [BT_ * (size_t)G4_];
__device__ __nv_bfloat16 d_xn2h[BT_ * (size_t)E_];
__device__ __nv_bfloat16 d_hnh [BT_ * (size_t)H_];
__device__ __nv_bfloat16 d_uh  [BT_ * (size_t)H_];
// pair-packed bf16 weights
__device__ uint32_t d_Wgp  [(size_t)512 * G4_];
__device__ uint32_t d_downp[(size_t)512 * E_];
__device__ uint32_t d_Wpair[(size_t)512 * 2048];
__device__ uint32_t d_Rgp  [(size_t)NH_ * 64 * 512];

// ---------------- helpers ----------------
__device__ __forceinline__ float gelu_exact(float x) {
    return 0.5f * x * (1.0f + erff(x * 0.70710678118654752440f));
}
__device__ __forceinline__ float sigmoidf_(float x) {
    return 1.0f / (1.0f + expf(-x));
}
__device__ __forceinline__ void cp_async16(uint32_t saddr, const void* g) {
    asm volatile("cp.async.cg.shared.global [%0], [%1], 16;" :: "r"(saddr), "l"(g));
}
__device__ __forceinline__ void mma_bf16(float* acc, uint32_t a0, uint32_t a1,
                                         uint32_t a2, uint32_t a3,
                                         uint32_t b0, uint32_t b1) {
    asm volatile(
        "mma.sync.aligned.m16n8k16.row.col.f32.bf16.bf16.f32 "
        "{%0,%1,%2,%3}, {%4,%5,%6,%7}, {%8,%9}, {%0,%1,%2,%3};"
        : "+f"(acc[0]), "+f"(acc[1]), "+f"(acc[2]), "+f"(acc[3])
        : "r"(a0), "r"(a1), "r"(a2), "r"(a3), "r"(b0), "r"(b1));
}
__device__ __forceinline__ void ldsm_x4(uint32_t* r, uint32_t saddr) {
    asm volatile("ldmatrix.sync.aligned.m8n8.x4.shared.b16 {%0,%1,%2,%3}, [%4];"
        : "=r"(r[0]), "=r"(r[1]), "=r"(r[2]), "=r"(r[3]) : "r"(saddr));
}
__device__ __forceinline__ void warp_reduce_2(float& s, float& ss) {
    #pragma unroll
    for (int o = 16; o; o >>= 1) {
        s  += __shfl_xor_sync(0xffffffffu, s,  o);
        ss += __shfl_xor_sync(0xffffffffu, ss, o);
    }
}

// ---------------- combined weight packs (one launch) ----------------
__global__ void pack_all(const float* __restrict__ Wg,
                         const float* __restrict__ downw,
                         const float* __restrict__ wl,
                         const float* __restrict__ wr) {
    int z = blockIdx.z;
    int kp = blockIdx.y;
    int n = blockIdx.x * 256 + threadIdx.x;
    if (z == 0) {
        __nv_bfloat162 h = __floats2bfloat162_rn(Wg[(size_t)(2 * kp) * 4096 + n],
                                                 Wg[(size_t)(2 * kp + 1) * 4096 + n]);
        d_Wgp[(size_t)kp * 4096 + n] = *reinterpret_cast<uint32_t*>(&h);
    } else if (z == 1) {
        if (blockIdx.x >= 4) return;
        __nv_bfloat162 h = __floats2bfloat162_rn(downw[(size_t)(2 * kp) * 1024 + n],
                                                 downw[(size_t)(2 * kp + 1) * 1024 + n]);
        d_downp[(size_t)kp * 1024 + n] = *reinterpret_cast<uint32_t*>(&h);
    } else {
        if (blockIdx.x >= 4) return;
        __nv_bfloat162 hl = __floats2bfloat162_rn(wl[(size_t)(2 * kp) * 1024 + n],
                                                  wl[(size_t)(2 * kp + 1) * 1024 + n]);
        __nv_bfloat162 hr = __floats2bfloat162_rn(wr[(size_t)(2 * kp) * 1024 + n],
                                                  wr[(size_t)(2 * kp + 1) * 1024 + n]);
        d_Wpair[(size_t)kp * 2048 + 2 * n]     = *reinterpret_cast<uint32_t*>(&hl);
        d_Wpair[(size_t)kp * 2048 + 2 * n + 1] = *reinterpret_cast<uint32_t*>(&hr);
    }
}
__global__ __launch_bounds__(256) void pack_rg(const float* __restrict__ Rg) {
    __shared__ float tile[32][129];
    int head = blockIdx.x;
    int g0 = blockIdx.y * 32;
    int tid = threadIdx.x;
    #pragma unroll
    for (int i = 0; i < 16; i++) {
        int e = i * 256 + tid;
        int r = e >> 7, c = e & 127;
        tile[r][c] = Rg[((size_t)(head * 512 + g0 + r)) * 128 + c];
    }
    __syncthreads();
    #pragma unroll
    for (int i = 0; i < 8; i++) {
        int e = i * 256 + tid;
        int kp = e >> 5, gl = e & 31;
        __nv_bfloat162 h = __floats2bfloat162_rn(tile[gl][2 * kp], tile[gl][2 * kp + 1]);
        d_Rgp[((size_t)(head * 64 + kp)) * 512 + g0 + gl] =
            *reinterpret_cast<uint32_t*>(&h);
    }
}

// ---------------- fused front: LN(x) -> fc1 conv -> fc2 -> LN -> bf16 ----------------
__global__ __launch_bounds__(384) void fused_front(
    const float* __restrict__ x,
    const float* __restrict__ ln_g, const float* __restrict__ ln_b,
    const float* __restrict__ w1g, const float* __restrict__ b1g,
    const float* __restrict__ w2g, const float* __restrict__ b2g,
    const float* __restrict__ xlg, const float* __restrict__ xlb) {
    extern __shared__ float sm[];
    float* sxn = sm;                    // [12][1032], data at +1, halo zeros
    float* sxc = sxn + 12 * 1032;       // [12][1024]
    float* sx1 = sxc + 12 * 1024;       // [12][1024]
    float* sw1 = sx1 + 12 * 1024;       // 432
    float* sw2 = sw1 + 432;             // 144
    float* sb1 = sw2 + 144;             // 12
    float* sb2 = sb1 + 12;              // 12
    int b = blockIdx.x, tid = threadIdx.x, w = tid >> 5, lane = tid & 31;

    for (int i = tid; i < 432; i += 384) sw1[i] = w1g[i];
    if (tid < 144) sw2[tid] = w2g[tid];
    if (tid < 12) { sb1[tid] = b1g[tid]; sb2[tid] = b2g[tid]; }
    if (lane == 0) { sxn[w * 1032] = 0.f; sxn[w * 1032 + 1025] = 0.f; }

    size_t rbase = ((size_t)b * 12 + w) * 1024;
    const float* xr = x + rbase;
    float4 vals[8];
    float s = 0.f, ss = 0.f;
    #pragma unroll
    for (int j = 0; j < 8; j++) {
        float4 v = *reinterpret_cast<const float4*>(xr + lane * 4 + j * 128);
        vals[j] = v;
        s  += v.x + v.y + v.z + v.w;
        ss += v.x*v.x + v.y*v.y + v.z*v.z + v.w*v.w;
    }
    warp_reduce_2(s, ss);
    float mu = s * (1.0f / 1024.0f);
    float rstd = rsqrtf(ss * (1.0f / 1024.0f) - mu * mu + 1e-5f);
    #pragma unroll
    for (int j = 0; j < 8; j++) {
        int idx = lane * 4 + j * 128;
        float4 g = *reinterpret_cast<const float4*>(ln_g + idx);
        float4 bb = *reinterpret_cast<const float4*>(ln_b + idx);
        float4 v = vals[j], o;
        o.x = (v.x - mu) * rstd * g.x + bb.x;
        o.y = (v.y - mu) * rstd * g.y + bb.y;
        o.z = (v.z - mu) * rstd * g.z + bb.z;
        o.w = (v.w - mu) * rstd * g.w + bb.w;
        sxn[w * 1032 + 1 + idx] = o.x; sxn[w * 1032 + 2 + idx] = o.y;
        sxn[w * 1032 + 3 + idx] = o.z; sxn[w * 1032 + 4 + idx] = o.w;
        *reinterpret_cast<float4*>(d_xn + rbase + idx) = o;
    }
    __syncthreads();

    {   // fc1 conv: warp w -> channel w
        int o = w;
        float wl[36];
        #pragma unroll
        for (int i = 0; i < 36; i++) wl[i] = sw1[o * 36 + i];
        float bo = sb1[o];
        for (int j = 0; j < 32; j++) {
            int l = lane + j * 32;
            float a = bo;
            #pragma unroll
            for (int c = 0; c < 12; c++) {
                a += wl[c*3]   * sxn[c * 1032 + l]
                   + wl[c*3+1] * sxn[c * 1032 + l + 1]
                   + wl[c*3+2] * sxn[c * 1032 + l + 2];
            }
            sxc[o * 1024 + l] = a;
            d_xc[rbase + l] = a;
        }
    }
    __syncthreads();

    {   // fc2 1x1
        int o = w;
        float wl[12];
        #pragma unroll
        for (int c = 0; c < 12; c++) wl[c] = sw2[o * 12 + c];
        float bo = sb2[o];
        for (int j = 0; j < 32; j++) {
            int l = lane + j * 32;
            float a = bo;
            #pragma unroll
            for (int c = 0; c < 12; c++) a += wl[c] * sxc[c * 1024 + l];
            sx1[o * 1024 + l] = a;
            d_x1[rbase + l] = a;
        }
    }
    __syncthreads();

    // LN2 -> bf16
    s = 0.f; ss = 0.f;
    #pragma unroll
    for (int j = 0; j < 8; j++) {
        float4 v = *reinterpret_cast<const float4*>(sx1 + w * 1024 + lane * 4 + j * 128);
        vals[j] = v;
        s  += v.x + v.y + v.z + v.w;
        ss += v.x*v.x + v.y*v.y + v.z*v.z + v.w*v.w;
    }
    warp_reduce_2(s, ss);
    mu = s * (1.0f / 1024.0f);
    rstd = rsqrtf(ss * (1.0f / 1024.0f) - mu * mu + 1e-5f);
    #pragma unroll
    for (int j = 0; j < 8; j++) {
        int idx = lane * 4 + j * 128;
        float4 g = *reinterpret_cast<const float4*>(xlg + idx);
        float4 bb = *reinterpret_cast<const float4*>(xlb + idx);
        float4 v = vals[j];
        __nv_bfloat162 h0 = __floats2bfloat162_rn((v.x - mu) * rstd * g.x + bb.x,
                                                  (v.y - mu) * rstd * g.y + bb.y);
        __nv_bfloat162 h1 = __floats2bfloat162_rn((v.z - mu) * rstd * g.z + bb.z,
                                                  (v.w - mu) * rstd * g.w + bb.w);
        uint2 pk = make_uint2(*reinterpret_cast<uint32_t*>(&h0),
                              *reinterpret_cast<uint32_t*>(&h1));
        *reinterpret_cast<uint2*>(d_xn2h + rbase + idx) = pk;
    }
}

// ---------------- fused tail v2: all-fp32, 3 chunks of 16 z-rows ----------------
__global__ __launch_bounds__(512) void fused_tail(
    const float* __restrict__ w1g, const float* __restrict__ b1g,
    const float* __restrict__ w2g, const float* __restrict__ b2g,
    const float* __restrict__ ln_g, const float* __restrict__ ln_b,
    float* __restrict__ out) {
    extern __shared__ float sm[];
    float* sy  = sm;                   // [12][1032], data at +1, halo zeros
    float* szf = sy + 12 * 1032;       // [16][1032] fp32 chunk, data at +1
    float* sw1 = szf + 16 * 1032;      // 1728 (o,c,k)
    float* sw2 = sw1 + 1728;           // 1728 repacked (c,o,k)
    float* sb1 = sw2 + 1728;           // 48
    float* sb2 = sb1 + 48;             // 12
    int b = blockIdx.x, tid = threadIdx.x, w = tid >> 5, lane = tid & 31;

    for (int i = tid; i < 12 * 256; i += 512) {
        int c = i >> 8, q = (i & 255) * 4;
        float4 v = *reinterpret_cast<const float4*>(d_y + ((size_t)b * 12 + c) * 1024 + q);
        sy[c * 1032 + 1 + q]     = v.x;
        sy[c * 1032 + 1 + q + 1] = v.y;
        sy[c * 1032 + 1 + q + 2] = v.z;
        sy[c * 1032 + 1 + q + 3] = v.w;
    }
    if (tid < 12) { sy[tid * 1032] = 0.f; sy[tid * 1032 + 1025] = 0.f; }
    if (tid < 16) { szf[tid * 1032] = 0.f; szf[tid * 1032 + 1025] = 0.f; }
    for (int i = tid; i < 1728; i += 512) {
        sw1[i] = w1g[i];
        int o = i / 144, rem = i % 144;
        int c = rem / 3, k = rem % 3;
        sw2[c * 36 + o * 3 + k] = w2g[i];
    }
    if (tid < 48) sb1[tid] = b1g[tid];
    if (tid < 12) sb2[tid] = b2g[tid];
    __syncthreads();

    int l2 = tid * 2;
    float acc0[12], acc1[12];
    #pragma unroll
    for (int o = 0; o < 12; o++) { acc0[o] = 0.f; acc1[o] = 0.f; }

    for (int cc = 0; cc < 3; cc++) {
        int o = cc * 16 + w;
        float wl[36];
        #pragma unroll
        for (int i = 0; i < 36; i++) wl[i] = sw1[o * 36 + i];
        float bo = sb1[o];
        float vbuf[32];
        float s = 0.f, ss = 0.f;
        #pragma unroll 4
        for (int j = 0; j < 32; j++) {
            int l = lane + j * 32;
            float a = bo;
            #pragma unroll
            for (int c = 0; c < 12; c++) {
                a += wl[c*3]   * sy[c * 1032 + l]
                   + wl[c*3+1] * sy[c * 1032 + l + 1]
                   + wl[c*3+2] * sy[c * 1032 + l + 2];
            }
            float v = gelu_exact(a);
            vbuf[j] = v;
            s += v; ss += v * v;
        }
        warp_reduce_2(s, ss);
        float mu = s * (1.0f / 1024.0f);
        float rstd = rsqrtf(ss * (1.0f / 1024.0f) - mu * mu + 1e-5f);
        #pragma unroll 4
        for (int j = 0; j < 32; j++) {
            int l = lane + j * 32;
            szf[w * 1032 + 1 + l] =
                (vbuf[j] - mu) * rstd * __ldg(ln_g + l) + __ldg(ln_b + l);
        }
        __syncthreads();

        for (int c16 = 0; c16 < 16; c16++) {
            int c = cc * 16 + c16;
            const float* zr = szf + c16 * 1032 + l2;
            float2 p0 = *reinterpret_cast<const float2*>(zr);
            float2 p1 = *reinterpret_cast<const float2*>(zr + 2);
            float h0 = p0.x, h1 = p0.y, h2 = p1.x, h3 = p1.y;
            const float* wr = sw2 + c * 36;
            #pragma unroll
            for (int o2 = 0; o2 < 12; o2++) {
                float w0 = wr[o2*3], w1 = wr[o2*3+1], w2v = wr[o2*3+2];
                acc0[o2] += w0 * h0 + w1 * h1 + w2v * h2;
                acc1[o2] += w0 * h1 + w1 * h2 + w2v * h3;
            }
        }
        __syncthreads();
    }

    #pragma unroll
    for (int o = 0; o < 12; o++) {
        size_t idx = ((size_t)b * 12 + o) * 1024 + l2;
        float2 sk = *reinterpret_cast<const float2*>(d_xn + idx);
        float2 ov;
        ov.x = acc0[o] + sb2[o] + sk.x;
        ov.y = acc1[o] + sb2[o] + sk.y;
        *reinterpret_cast<float2*>(out + idx) = ov;
    }
}

// ---------------- bf16 tensor-core GEMM: 3-stage cp.async + ldmatrix A ----------------
// MODE 2: C(fp32) = silu(aux0) * (acc + bias + aux1) + aux2
// MODE 3: interleaved pair: C(bf16)[r][c/2] = gelu(accL+bias) * (accR+aux1)
// MODE 4: C(bf16) = acc + bias
template<int MODE>
__global__ __launch_bounds__(256) void gemm_bf16(int N, int K,
                                                 const __nv_bfloat16* __restrict__ A,
                                                 const uint32_t* __restrict__ Bp,
                                                 const float* __restrict__ bias,
                                                 const float* __restrict__ aux0,
                                                 const float* __restrict__ aux1,
                                                 const float* __restrict__ aux2,
                                                 void* __restrict__ Cout) {
    __shared__ uint32_t As[3][128 * 20];
    __shared__ uint32_t Bs[3][16 * 136];
    int tid = threadIdx.x;
    int warp = tid >> 5, lane = tid & 31;
    int g = lane >> 2, tg = lane & 3;
    int warpM = warp >> 2, warpN = warp & 3;
    int row0 = blockIdx.y * 128, col0 = blockIdx.x * 128;

    uint32_t asb = (uint32_t)__cvta_generic_to_shared(&As[0][0]);
    uint32_t bsb = (uint32_t)__cvta_generic_to_shared(&Bs[0][0]);

    float acc[4][4][4];
    #pragma unroll
    for (int m = 0; m < 4; m++)
        #pragma unroll
        for (int n = 0; n < 4; n++)
            #pragma unroll
            for (int q = 0; q < 4; q++) acc[m][n][q] = 0.f;

    const int nt = K >> 5;

    auto load_tile = [&](int it, int buf) {
        int k0 = it << 5;
        int kp0 = it << 4;
        #pragma unroll
        for (int i = 0; i < 2; i++) {
            int e = i * 256 + tid;
            int r = e >> 2, ch = e & 3;
            cp_async16(asb + (uint32_t)(buf * 128 * 20 + r * 20 + ch * 4) * 4,
                       A + (size_t)(row0 + r) * K + k0 + ch * 8);
        }
        #pragma unroll
        for (int i = 0; i < 2; i++) {
            int e = i * 256 + tid;
            int kp = e >> 5, c = (e & 31) * 4;
            cp_async16(bsb + (uint32_t)(buf * 16 * 136 + kp * 136 + c) * 4,
                       Bp + (size_t)(kp0 + kp) * N + col0 + c);
        }
        asm volatile("cp.async.commit_group;");
    };

    // prime 2 stages
    load_tile(0, 0);
    load_tile(1, 1);

    // hoisted per-warp offsets
    int arow = warpM * 64;
    int bcol = warpN * 32 + g;
    // ldmatrix lane addressing: seg = lane>>3
    int lseg = lane >> 3;
    int a_row = (lseg & 1) * 8 + (lane & 7);   // row within 16-row tile
    int a_kw  = (lseg >> 1) * 4;               // word offset within k16 block (8 words)

    for (int it = 0; it < nt; it++) {
        int buf = it - (it / 3) * 3;
        asm volatile("cp.async.wait_group 1;");
        __syncthreads();
        if (it + 2 < nt) {
            int buf2 = (it + 2) - ((it + 2) / 3) * 3;
            load_tile(it + 2, buf2);
        } else {
            asm volatile("cp.async.commit_group;");
        }
        uint32_t a_base = asb + (uint32_t)(buf * 128 * 20) * 4;
        const uint32_t* Bb = &Bs[buf][0];
        #pragma unroll
        for (int s = 0; s < 2; s++) {
            uint32_t af[4][4];
            #pragma unroll
            for (int m = 0; m < 4; m++) {
                uint32_t sa = a_base +
                    (uint32_t)((arow + m * 16 + a_row) * 20 + s * 8 + a_kw) * 4;
                ldsm_x4(af[m], sa);
            }
            uint32_t bf[4][2];
            #pragma unroll
            for (int n = 0; n < 4; n++) {
                int c = bcol + n * 8;
                bf[n][0] = Bb[(s * 8 + tg)     * 136 + c];
                bf[n][1] = Bb[(s * 8 + tg + 4) * 136 + c];
            }
            #pragma unroll
            for (int m = 0; m < 4; m++)
                #pragma unroll
                for (int n = 0; n < 4; n++)
                    mma_bf16(acc[m][n], af[m][0], af[m][1], af[m][2], af[m][3],
                             bf[n][0], bf[n][1]);
        }
    }

    __syncthreads();
    #pragma unroll
    for (int m = 0; m < 4; m++) {
        int r = row0 + warpM * 64 + m * 16 + g;
        #pragma unroll
        for (int n = 0; n < 4; n++) {
            int c = col0 + warpN * 32 + n * 8 + 2 * tg;
            #pragma unroll
            for (int half = 0; half < 2; half++) {
                int rr = r + half * 8;
                float a0 = acc[m][n][half * 2 + 0];
                float a1 = acc[m][n][half * 2 + 1];
                if (MODE == 3) {
                    int j = c >> 1;
                    float l  = a0 + bias[j];
                    float rv = a1 + aux1[j];
                    ((__nv_bfloat16*)Cout)[(size_t)rr * (N >> 1) + j] =
                        __float2bfloat16_rn(gelu_exact(l) * rv);
                } else if (MODE == 4) {
                    size_t i0 = (size_t)rr * N + c;
                    __nv_bfloat162 hh = __floats2bfloat162_rn(a0 + bias[c],
                                                              a1 + bias[c + 1]);
                    *reinterpret_cast<uint32_t*>((__nv_bfloat16*)Cout + i0) =
                        *reinterpret_cast<uint32_t*>(&hh);
                } else {
                    size_t i0 = (size_t)rr * N + c;
                    float v0 = a0 + bias[c];
                    float v1 = a1 + bias[c + 1];
                    if (MODE == 2) {
                        float x0 = aux0[i0], x1v = aux0[i0 + 1];
                        v0 = x0  * sigmoidf_(x0)  * (v0 + aux1[i0])     + aux2[i0];
                        v1 = x1v * sigmoidf_(x1v) * (v1 + aux1[i0 + 1]) + aux2[i0 + 1];
                    }
                    *reinterpret_cast<float2*>((float*)Cout + i0) = make_float2(v0, v1);
                }
            }
        }
    }
}

// ---------------- sLSTM recurrence v4: fused GroupNorm -> d_hnh directly ----------------
__global__ __launch_bounds__(256) void slstm_rec4(const float* __restrict__ gng,
                                                  const float* __restrict__ gnb) {
    extern __shared__ uint32_t smw[];
    uint32_t* sBp = smw;                                  // [64][520]
    float* s_rec = (float*)(smw + 64 * 520);              // [32][516]
    uint32_t* sh_w = (uint32_t*)(s_rec + 32 * 516);       // [32][68]
    float* gn_part = (float*)(sh_w + 32 * 68);            // [16][8][2]
    __nv_bfloat16* sh_h = (__nv_bfloat16*)sh_w;

    int head = blockIdx.x >> 4;
    int b0 = (blockIdx.x & 15) << 5;
    int tid = threadIdx.x;
    int warp = tid >> 5, lane = tid & 31;
    int g = lane >> 2, tg = lane & 3;
    int wm = warp >> 2, wn = warp & 3;

    uint32_t sb = (uint32_t)__cvta_generic_to_shared(sBp);
    const uint32_t* Bg = d_Rgp + (size_t)head * (64 * 512);
    #pragma unroll
    for (int i = 0; i < 32; i++) {
        int e = i * 256 + tid;
        int kp = e >> 7, c = (e & 127) * 4;
        cp_async16(sb + (uint32_t)(kp * 520 + c) * 4, Bg + (size_t)kp * 512 + c);
    }
    asm volatile("cp.async.commit_group;");
    for (int i = tid; i < 32 * 68; i += 256) sh_w[i] = 0;
    float cS[16], nS[16], mS[16];
    #pragma unroll
    for (int j = 0; j < 16; j++) { cS[j] = 0.f; nS[j] = 0.f; mS[j] = 0.f; }
    int hs_t = tid & 127;
    float gnw = __ldg(gng + head * 128 + hs_t);
    float gnbv = __ldg(gnb + head * 128 + hs_t);
    asm volatile("cp.async.wait_group 0;");
    __syncthreads();

    for (int t = 0; t < 12; t++) {
        float acc[16][4];
        #pragma unroll
        for (int j = 0; j < 16; j++)
            #pragma unroll
            for (int q = 0; q < 4; q++) acc[j][q] = 0.f;
        #pragma unroll
        for (int s = 0; s < 8; s++) {
            uint32_t a0 = sh_w[(wm * 16 + g)     * 68 + s * 8 + tg];
            uint32_t a1 = sh_w[(wm * 16 + 8 + g) * 68 + s * 8 + tg];
            uint32_t a2 = sh_w[(wm * 16 + g)     * 68 + s * 8 + tg + 4];
            uint32_t a3 = sh_w[(wm * 16 + 8 + g) * 68 + s * 8 + tg + 4];
            #pragma unroll
            for (int j = 0; j < 16; j++) {
                int c = wn * 128 + j * 8 + g;
                uint32_t b0v = sBp[(s * 8 + tg)     * 520 + c];
                uint32_t b1v = sBp[(s * 8 + tg + 4) * 520 + c];
                mma_bf16(acc[j], a0, a1, a2, a3, b0v, b1v);
            }
        }
        #pragma unroll
        for (int j = 0; j < 16; j++) {
            int c = wn * 128 + j * 8 + 2 * tg;
            int r = wm * 16 + g;
            s_rec[r * 516 + c]           = acc[j][0];
            s_rec[r * 516 + c + 1]       = acc[j][1];
            s_rec[(r + 8) * 516 + c]     = acc[j][2];
            s_rec[(r + 8) * 516 + c + 1] = acc[j][3];
        }
        __syncthreads();

        float hv16[16];
        #pragma unroll
        for (int it = 0; it < 16; it++) {
            int idx = it * 256 + tid;
            int bb = idx >> 7, hs = idx & 127;
            int b = b0 + bb;
            const __nv_bfloat16* gxp =
                d_gxh + (size_t)(b * 12 + t) * 4096 + head * 512;
            const float* rp = s_rec + bb * 516;
            float z_ = __bfloat162float(gxp[hs])       + rp[hs];
            float i_ = __bfloat162float(gxp[128 + hs]) + rp[128 + hs];
            float f_ = __bfloat162float(gxp[256 + hs]) + rp[256 + hs];
            float o_ = __bfloat162float(gxp[384 + hs]) + rp[384 + hs];
            float z  = tanhf(z_);
            float o  = sigmoidf_(o_);
            float mo = mS[it];
            float mn = fmaxf(f_ + mo, i_);
            float iv = expf(i_ - mn);
            float fv = expf(f_ + mo - mn);
            float cv = fv * cS[it] + iv * z;
            float nv = fv * nS[it] + iv;
            float hv = o * (cv / nv);
            cS[it] = cv; nS[it] = nv; mS[it] = mn;
            sh_h[bb * 136 + hs] = __float2bfloat16_rn(hv);
            hv16[it] = hv;
            float s = hv, ss = hv * hv;
            warp_reduce_2(s, ss);
            if (lane == 0) {
                gn_part[(it * 8 + warp) * 2]     = s;
                gn_part[(it * 8 + warp) * 2 + 1] = ss;
            }
        }
        __syncthreads();

        int wbase = (tid >> 7) * 4;
        #pragma unroll
        for (int it = 0; it < 16; it++) {
            float s = 0.f, ss = 0.f;
            #pragma unroll
            for (int q = 0; q < 4; q++) {
                s  += gn_part[(it * 8 + wbase + q) * 2];
                ss += gn_part[(it * 8 + wbase + q) * 2 + 1];
            }
            float mu = s * (1.0f / 128.0f);
            float rstd = rsqrtf(ss * (1.0f / 128.0f) - mu * mu + 1e-5f);
            int bb = (it << 1) + (tid >> 7);
            int b = b0 + bb;
            d_hnh[(size_t)(b * 12 + t) * 1024 + head * 128 + hs_t] =
                __float2bfloat16_rn((hv16[it] - mu) * rstd * gnw + gnbv);
        }
        __syncthreads();
    }
}

// ---------------- launch ----------------
extern "C" void kernel_launch(void* const* d_in, const int* in_sizes, int n_in,
                              void* d_out, int out_size) {
    const float* x       = (const float*)d_in[0];
    const float* ln_g    = (const float*)d_in[1];
    const float* ln_b    = (const float*)d_in[2];
    const float* fc1_w   = (const float*)d_in[3];
    const float* fc1_b   = (const float*)d_in[4];
    const float* fc2_w   = (const float*)d_in[5];
    const float* fc2_b   = (const float*)d_in[6];
    const float* conv1_w = (const float*)d_in[7];
    const float* conv1_b = (const float*)d_in[8];
    const float* conv2_w = (const float*)d_in[9];
    const float* conv2_b = (const float*)d_in[10];
    const float* xlg     = (const float*)d_in[11];
    const float* xlb     = (const float*)d_in[12];
    const float* Wg      = (const float*)d_in[13];
    const float* bg      = (const float*)d_in[14];
    const float* Rg      = (const float*)d_in[15];
    const float* gng     = (const float*)d_in[16];
    const float* gnb     = (const float*)d_in[17];
    const float* uplw    = (const float*)d_in[18];
    const float* uplb    = (const float*)d_in[19];
    const float* uprw    = (const float*)d_in[20];
    const float* uprb    = (const float*)d_in[21];
    const float* downw   = (const float*)d_in[22];
    const float* downb   = (const float*)d_in[23];
    float* out = (float*)d_out;

    cudaFuncSetAttribute(slstm_rec4,  cudaFuncAttributeMaxDynamicSharedMemorySize, 208896);
    cudaFuncSetAttribute(fused_front, cudaFuncAttributeMaxDynamicSharedMemorySize, 150240);
    cudaFuncSetAttribute(fused_tail,  cudaFuncAttributeMaxDynamicSharedMemorySize, 129648);

    float *p_xn, *p_xc, *p_x1, *p_y;
    __nv_bfloat16 *p_gxh, *p_xn2h, *p_hnh, *p_uh;
    uint32_t *p_Wgp, *p_downp, *p_Wpair;
    cudaGetSymbolAddress((void**)&p_xn,    d_xn);
    cudaGetSymbolAddress((void**)&p_xc,    d_xc);
    cudaGetSymbolAddress((void**)&p_x1,    d_x1);
    cudaGetSymbolAddress((void**)&p_y,     d_y);
    cudaGetSymbolAddress((void**)&p_gxh,   d_gxh);
    cudaGetSymbolAddress((void**)&p_xn2h,  d_xn2h);
    cudaGetSymbolAddress((void**)&p_hnh,   d_hnh);
    cudaGetSymbolAddress((void**)&p_uh,    d_uh);
    cudaGetSymbolAddress((void**)&p_Wgp,   d_Wgp);
    cudaGetSymbolAddress((void**)&p_downp, d_downp);
    cudaGetSymbolAddress((void**)&p_Wpair, d_Wpair);

    pack_all<<<dim3(16, 512, 3), 256>>>(Wg, downw, uplw, uprw);
    pack_rg<<<dim3(8, 16), 256>>>(Rg);

    // LN(x) -> fc1 -> fc2 -> LN -> bf16   [fused per batch]
    fused_front<<<B_, 384, 150240>>>(x, ln_g, ln_b, fc1_w, fc1_b,
                                     fc2_w, fc2_b, xlg, xlb);
    // gx = xn2 @ Wg + bg  -> bf16
    gemm_bf16<4><<<dim3(32, 48), 256>>>(4096, 1024, p_xn2h, p_Wgp, bg,
                                        nullptr, nullptr, nullptr, p_gxh);
    // sLSTM recurrence + fused GroupNorm -> d_hnh (bf16)
    slstm_rec4<<<128, 256, 208896>>>(gng, gnb);
    // u = gelu(hn@upl + uplb) * (hn@upr + uprb)
    gemm_bf16<3><<<dim3(16, 48), 256>>>(2048, 1024, p_hnh, p_Wpair, uplb,
                                        nullptr, uprb, nullptr, p_uh);
    // y = silu(xc) * (u @ down + downb + x1) + xn
    gemm_bf16<2><<<dim3(8, 48), 256>>>(1024, 1024, p_uh, p_downp, downb,
                                       p_xc, p_x1, p_xn, p_y);
    // conv12->48 + gelu + LN + conv48->12 + skip   [fused, fp32 throughout]
    fused_tail<<<B_, 512, 129648>>>(conv1_w, conv1_b, conv2_w, conv2_b,
                                    ln_g, ln_b, out);
}